// round 2
// baseline (speedup 1.0000x reference)
#include <cuda_runtime.h>
#include <math.h>

#define Nn 30000
#define Ee 480000
#define Bb 4096
#define EPSF 1e-8f

// ------------- device scratch -------------
__device__ float g_XW[Nn*128];
__device__ float g_H[Nn*128];
__device__ float g_emb[Nn*64];
__device__ float g_S16[Nn*16];
__device__ float g_C16[Nn*16];
__device__ float g_dr[Nn], g_dc[Nn], g_w1[Nn], g_w2[Nn], g_b1[Nn], g_b2[Nn];
__device__ int   g_cnt[Nn], g_cntb[Nn], g_cur[Nn];
__device__ int   g_rp1d[Nn+1], g_rp2d[Nn+1], g_rp1s[Nn+1], g_rp2s[Nn+1];
__device__ int   g_col1d[Ee];   __device__ float g_val1d[Ee];
__device__ int   g_col2d[Ee];   __device__ float g_val2d[Ee];
__device__ int   g_col1s[2*Ee]; __device__ float g_val1s[2*Ee];
__device__ int   g_col2s[2*Ee]; __device__ float g_val2s[2*Ee];
__device__ float g_Zb[Bb*128], g_Tb[Bb*128], g_EV[Bb*128], g_E1[Bb*128], g_E2[Bb*128];
__device__ float g_NV[Bb], g_N1[Bb], g_N2[Bb];
__device__ float g_RS[Bb], g_CS[Bb], g_DG[Bb];

// ------------- small utils -------------
__global__ void k_zero_i(int* p, int n){ int i=blockIdx.x*blockDim.x+threadIdx.x; if(i<n) p[i]=0; }
__global__ void k_zero_f(float* p, int n){ int i=blockIdx.x*blockDim.x+threadIdx.x; if(i<n) p[i]=0.f; }
__global__ void k_copy_i(const int* __restrict__ a, int* __restrict__ b, int n){
    int i=blockIdx.x*blockDim.x+threadIdx.x; if(i<n) b[i]=a[i]; }

__global__ void k_count(const int* __restrict__ ind, int* cd, int* cs){
    int e=blockIdx.x*blockDim.x+threadIdx.x; if(e>=Ee) return;
    int r=ind[e], c=ind[Ee+e];
    atomicAdd(&cd[r],1); atomicAdd(&cs[r],1); atomicAdd(&cs[c],1);
}

__global__ void k_scan(const int* __restrict__ cnt, int* __restrict__ rp, int n){
    __shared__ int sh[1024]; __shared__ int soff;
    int tid=threadIdx.x;
    if(tid==0) soff=0;
    __syncthreads();
    for(int base=0;base<n;base+=1024){
        int v=(base+tid<n)?cnt[base+tid]:0;
        sh[tid]=v; __syncthreads();
        for(int d=1;d<1024;d<<=1){
            int t=(tid>=d)?sh[tid-d]:0; __syncthreads();
            sh[tid]+=t; __syncthreads();
        }
        if(base+tid<n) rp[base+tid]=soff+sh[tid]-v;
        int tot=sh[1023]; __syncthreads();
        if(tid==0) soff+=tot;
        __syncthreads();
    }
    if(tid==0) rp[n]=soff;
}

__global__ void k_scatter_dir(const int* __restrict__ ind, const float* __restrict__ vals,
                              int* cur, int* __restrict__ col, float* __restrict__ val){
    int e=blockIdx.x*blockDim.x+threadIdx.x; if(e>=Ee) return;
    int r=ind[e], c=ind[Ee+e];
    int p=atomicAdd(&cur[r],1);
    col[p]=c; val[p]=vals[e];
}

__global__ void k_scatter_sym(const int* __restrict__ rpd, const int* __restrict__ cold,
                              const float* __restrict__ vald, int* cur,
                              int* __restrict__ cols, float* __restrict__ vals){
    int r=blockIdx.x*blockDim.x+threadIdx.x; if(r>=Nn) return;
    for(int i=rpd[r];i<rpd[r+1];i++){
        int c=cold[i]; float v=vald[i];
        int p=atomicAdd(&cur[r],1); cols[p]=c; vals[p]=v;
        int q=atomicAdd(&cur[c],1); cols[q]=r; vals[q]=v;
    }
}

// ------------- dense GEMM: C[n,M]=A[n,K]@W[K,M] (+bias, act 0=none 1=elu) -------------
__global__ void k_gemm(const float* __restrict__ A, const float* __restrict__ W,
                       const float* __restrict__ bias, float* __restrict__ C,
                       int n, int K, int M, int act){
    __shared__ float sA[16][64];
    __shared__ float sW[16][64];
    int tid=threadIdx.x, tx=tid&15, ty=tid>>4;
    int br=blockIdx.y*64, bc=blockIdx.x*64;
    float acc[4][4];
#pragma unroll
    for(int i=0;i<4;i++)
#pragma unroll
        for(int j=0;j<4;j++) acc[i][j]=0.f;
    int ra=tid>>2, fa=(tid&3)<<2, cw=tid&63, kb=tid>>6;
    for(int k0=0;k0<K;k0+=16){
        {
            int gr=br+ra;
            float4 v=make_float4(0.f,0.f,0.f,0.f);
            if(gr<n) v=*(const float4*)(A+(long)gr*K+k0+fa);
            sA[fa][ra]=v.x; sA[fa+1][ra]=v.y; sA[fa+2][ra]=v.z; sA[fa+3][ra]=v.w;
        }
        {
            int gc=bc+cw;
#pragma unroll
            for(int i=0;i<4;i++){
                int kk=kb+i*4;
                sW[kk][cw]=(gc<M)?W[(long)(k0+kk)*M+gc]:0.f;
            }
        }
        __syncthreads();
#pragma unroll
        for(int kk=0;kk<16;kk++){
            float4 a=*(const float4*)&sA[kk][ty*4];
            float4 b=*(const float4*)&sW[kk][tx*4];
            acc[0][0]+=a.x*b.x; acc[0][1]+=a.x*b.y; acc[0][2]+=a.x*b.z; acc[0][3]+=a.x*b.w;
            acc[1][0]+=a.y*b.x; acc[1][1]+=a.y*b.y; acc[1][2]+=a.y*b.z; acc[1][3]+=a.y*b.w;
            acc[2][0]+=a.z*b.x; acc[2][1]+=a.z*b.y; acc[2][2]+=a.z*b.z; acc[2][3]+=a.z*b.w;
            acc[3][0]+=a.w*b.x; acc[3][1]+=a.w*b.y; acc[3][2]+=a.w*b.z; acc[3][3]+=a.w*b.w;
        }
        __syncthreads();
    }
#pragma unroll
    for(int i=0;i<4;i++){
        int gr=br+ty*4+i; if(gr>=n) continue;
#pragma unroll
        for(int j=0;j<4;j++){
            int gc=bc+tx*4+j; if(gc>=M) continue;
            float v=acc[i][j];
            if(bias) v+=bias[gc];
            if(act==1) v=(v>0.f)?v:expm1f(v);
            C[(long)gr*M+gc]=v;
        }
    }
}

// ------------- SpMM (warp per row) -------------
__global__ void k_spmm64(const int* __restrict__ rp, const int* __restrict__ col,
                         const float* __restrict__ val, const float* __restrict__ X,
                         float* __restrict__ Y, int relu){
    int w=(blockIdx.x*blockDim.x+threadIdx.x)>>5; if(w>=Nn) return;
    int lane=threadIdx.x&31;
    const float2* X2=(const float2*)X;
    float2 acc=make_float2(0.f,0.f);
    for(int i=rp[w];i<rp[w+1];i++){
        int c=col[i]; float v=val[i];
        float2 x=X2[(long)c*32+lane];
        acc.x+=v*x.x; acc.y+=v*x.y;
    }
    if(relu){acc.x=fmaxf(acc.x,0.f); acc.y=fmaxf(acc.y,0.f);}
    ((float2*)Y)[(long)w*32+lane]=acc;
}

__global__ void k_spmm128(const int* __restrict__ rp, const int* __restrict__ col,
                          const float* __restrict__ val, const float* __restrict__ X,
                          float* __restrict__ Y, int relu){
    int w=(blockIdx.x*blockDim.x+threadIdx.x)>>5; if(w>=Nn) return;
    int lane=threadIdx.x&31;
    const float4* X4=(const float4*)X;
    float4 acc=make_float4(0.f,0.f,0.f,0.f);
    for(int i=rp[w];i<rp[w+1];i++){
        int c=col[i]; float v=val[i];
        float4 x=X4[(long)c*32+lane];
        acc.x+=v*x.x; acc.y+=v*x.y; acc.z+=v*x.z; acc.w+=v*x.w;
    }
    if(relu){acc.x=fmaxf(acc.x,0.f);acc.y=fmaxf(acc.y,0.f);acc.z=fmaxf(acc.z,0.f);acc.w=fmaxf(acc.w,0.f);}
    ((float4*)Y)[(long)w*32+lane]=acc;
}

__global__ void k_spmm128f(const int* __restrict__ rp1, const int* __restrict__ col1,
                           const float* __restrict__ val1,
                           const int* __restrict__ rp2, const int* __restrict__ col2,
                           const float* __restrict__ val2,
                           const float* __restrict__ b1, const float* __restrict__ b2,
                           const float* __restrict__ X, float* __restrict__ Y, int relu){
    int w=(blockIdx.x*blockDim.x+threadIdx.x)>>5; if(w>=Nn) return;
    int lane=threadIdx.x&31;
    const float4* X4=(const float4*)X;
    float4 a1=make_float4(0.f,0.f,0.f,0.f), a2=a1;
    for(int i=rp1[w];i<rp1[w+1];i++){
        int c=col1[i]; float v=val1[i];
        float4 x=X4[(long)c*32+lane];
        a1.x+=v*x.x; a1.y+=v*x.y; a1.z+=v*x.z; a1.w+=v*x.w;
    }
    for(int i=rp2[w];i<rp2[w+1];i++){
        int c=col2[i]; float v=val2[i];
        float4 x=X4[(long)c*32+lane];
        a2.x+=v*x.x; a2.y+=v*x.y; a2.z+=v*x.z; a2.w+=v*x.w;
    }
    float f1=b1[w], f2=b2[w];
    float4 r;
    r.x=f1*a1.x+f2*a2.x; r.y=f1*a1.y+f2*a2.y; r.z=f1*a1.z+f2*a2.z; r.w=f1*a1.w+f2*a2.w;
    if(relu){r.x=fmaxf(r.x,0.f);r.y=fmaxf(r.y,0.f);r.z=fmaxf(r.z,0.f);r.w=fmaxf(r.w,0.f);}
    ((float4*)Y)[(long)w*32+lane]=r;
}

__global__ void k_spmm16(const int* __restrict__ rp, const int* __restrict__ col,
                         const float* __restrict__ val, const float* __restrict__ X,
                         float* __restrict__ Y){
    int row=blockIdx.x*16+threadIdx.y; int j=threadIdx.x;
    if(row>=Nn) return;
    float acc=0.f;
    for(int i=rp[row];i<rp[row+1];i++) acc+=val[i]*X[(long)col[i]*16+j];
    Y[(long)row*16+j]=acc;
}

__global__ void k_spmm16f(const int* __restrict__ rp1, const int* __restrict__ col1,
                          const float* __restrict__ val1,
                          const int* __restrict__ rp2, const int* __restrict__ col2,
                          const float* __restrict__ val2,
                          const float* __restrict__ b1, const float* __restrict__ b2,
                          const float* __restrict__ X, float* __restrict__ Y){
    int row=blockIdx.x*16+threadIdx.y; int j=threadIdx.x;
    if(row>=Nn) return;
    float a1=0.f, a2=0.f;
    for(int i=rp1[row];i<rp1[row+1];i++) a1+=val1[i]*X[(long)col1[i]*16+j];
    for(int i=rp2[row];i<rp2[row+1];i++) a2+=val2[i]*X[(long)col2[i]*16+j];
    Y[(long)row*16+j]=b1[row]*a1+b2[row]*a2;
}

// ------------- gen_view helpers -------------
__global__ void k_nodedot(const float* __restrict__ emb, const float* __restrict__ Wm,
                          float* __restrict__ dr, float* __restrict__ dc){
    int node=(blockIdx.x*blockDim.x+threadIdx.x)>>5; if(node>=Nn) return;
    int lane=threadIdx.x&31;
    float2 e=((const float2*)(emb+(long)node*64))[lane];
    float2 wr=((const float2*)Wm)[lane];
    float2 wc=((const float2*)Wm)[lane+32];
    float a=e.x*wr.x+e.y*wr.y;
    float b=e.x*wc.x+e.y*wc.y;
#pragma unroll
    for(int o=16;o;o>>=1){
        a+=__shfl_xor_sync(0xffffffffu,a,o);
        b+=__shfl_xor_sync(0xffffffffu,b,o);
    }
    if(lane==0){dr[node]=a; dc[node]=b;}
}

__global__ void k_gensoftmax(const int* __restrict__ rp, const int* __restrict__ col,
                             float* __restrict__ val, const float* __restrict__ dr,
                             const float* __restrict__ dc, const float* __restrict__ bm,
                             float com){
    int row=(blockIdx.x*blockDim.x+threadIdx.x)>>5; if(row>=Nn) return;
    int lane=threadIdx.x&31;
    int s=rp[row], e=rp[row+1];
    if(s==e) return;
    float base=dr[row]+bm[0];
    float m=-3.4e38f;
    for(int i=s+lane;i<e;i+=32) m=fmaxf(m, base+dc[col[i]]);
#pragma unroll
    for(int o=16;o;o>>=1) m=fmaxf(m,__shfl_xor_sync(0xffffffffu,m,o));
    float ss=0.f;
    for(int i=s+lane;i<e;i+=32) ss+=__expf(base+dc[col[i]]-m);
#pragma unroll
    for(int o=16;o;o>>=1) ss+=__shfl_xor_sync(0xffffffffu,ss,o);
    float inv=com/ss;
    for(int i=s+lane;i<e;i+=32) val[i]+=__expf(base+dc[col[i]]-m)*inv;
}

// ------------- 16-class softmax + logits + top2 weight -------------
__global__ void k_softmax_w(const float* __restrict__ C, float* __restrict__ lg,
                            float* __restrict__ w){
    int node=blockIdx.x*blockDim.x+threadIdx.x; if(node>=Nn) return;
    float x[16];
    const float4* p=(const float4*)(C+(long)node*16);
#pragma unroll
    for(int q=0;q<4;q++){float4 t=p[q]; x[4*q]=t.x; x[4*q+1]=t.y; x[4*q+2]=t.z; x[4*q+3]=t.w;}
    float m=x[0];
#pragma unroll
    for(int j=1;j<16;j++) m=fmaxf(m,x[j]);
    float s=0.f;
#pragma unroll
    for(int j=0;j<16;j++){x[j]=__expf(x[j]-m); s+=x[j];}
    float inv=1.f/s;
    float fir=0.f, sec=0.f;
#pragma unroll
    for(int j=0;j<16;j++){
        float pr=x[j]*inv;
        lg[(long)node*16+j]=logf(pr+EPSF);
        if(pr>fir){sec=fir; fir=pr;} else if(pr>sec) sec=pr;
    }
    if(w) w[node]=sqrtf((fir+EPSF)*(fir-sec+EPSF));
}

__global__ void k_bal(const float* __restrict__ w1, const float* __restrict__ w2,
                      float* __restrict__ b1, float* __restrict__ b2){
    int i=blockIdx.x*blockDim.x+threadIdx.x; if(i>=Nn) return;
    float a=w1[i], b=w2[i], inv=1.f/(a+b);
    b1[i]=a*inv; b2[i]=b*inv;
}

__global__ void k_gather(const int* __restrict__ idx, const float* __restrict__ H,
                         float* __restrict__ Z){
    int t=blockIdx.x*blockDim.x+threadIdx.x; if(t>=Bb*128) return;
    int i=t>>7, j=t&127;
    Z[t]=H[(long)idx[i]*128+j];
}

__global__ void k_rownorm(const float* __restrict__ Z, float* __restrict__ nrm){
    int row=(blockIdx.x*blockDim.x+threadIdx.x)>>5; if(row>=Bb) return;
    int lane=threadIdx.x&31;
    float4 v=((const float4*)(Z+(long)row*128))[lane];
    float s=v.x*v.x+v.y*v.y+v.z*v.z+v.w*v.w;
#pragma unroll
    for(int o=16;o;o>>=1) s+=__shfl_xor_sync(0xffffffffu,s,o);
    if(lane==0) nrm[row]=sqrtf(s);
}

// ------------- contrast: rowsum/colsum/diag of exp(2*cos) -------------
__global__ void k_contrast(const float* __restrict__ z1, const float* __restrict__ z2,
                           const float* __restrict__ n1, const float* __restrict__ n2,
                           float* RS, float* CS, float* DG){
    __shared__ float sA[16][64];
    __shared__ float sB[16][64];
    __shared__ float sRS[64], sCS[64];
    int tid=threadIdx.x, tx=tid&15, ty=tid>>4;
    int br=blockIdx.y*64, bc=blockIdx.x*64;
    float acc[4][4];
#pragma unroll
    for(int i=0;i<4;i++)
#pragma unroll
        for(int j=0;j<4;j++) acc[i][j]=0.f;
    int ra=tid>>2, fa=(tid&3)<<2;
    for(int k0=0;k0<128;k0+=16){
        {float4 v=*(const float4*)(z1+(long)(br+ra)*128+k0+fa);
         sA[fa][ra]=v.x; sA[fa+1][ra]=v.y; sA[fa+2][ra]=v.z; sA[fa+3][ra]=v.w;}
        {float4 v=*(const float4*)(z2+(long)(bc+ra)*128+k0+fa);
         sB[fa][ra]=v.x; sB[fa+1][ra]=v.y; sB[fa+2][ra]=v.z; sB[fa+3][ra]=v.w;}
        __syncthreads();
#pragma unroll
        for(int kk=0;kk<16;kk++){
            float4 a=*(const float4*)&sA[kk][ty*4];
            float4 b=*(const float4*)&sB[kk][tx*4];
            acc[0][0]+=a.x*b.x; acc[0][1]+=a.x*b.y; acc[0][2]+=a.x*b.z; acc[0][3]+=a.x*b.w;
            acc[1][0]+=a.y*b.x; acc[1][1]+=a.y*b.y; acc[1][2]+=a.y*b.z; acc[1][3]+=a.y*b.w;
            acc[2][0]+=a.z*b.x; acc[2][1]+=a.z*b.y; acc[2][2]+=a.z*b.z; acc[2][3]+=a.z*b.w;
            acc[3][0]+=a.w*b.x; acc[3][1]+=a.w*b.y; acc[3][2]+=a.w*b.z; acc[3][3]+=a.w*b.w;
        }
        __syncthreads();
    }
    if(tid<64){sRS[tid]=0.f; sCS[tid]=0.f;}
    __syncthreads();
    float rn[4], cn[4];
#pragma unroll
    for(int i=0;i<4;i++) rn[i]=1.f/n1[br+ty*4+i];
#pragma unroll
    for(int j=0;j<4;j++) cn[j]=1.f/n2[bc+tx*4+j];
    float rsum[4]={0.f,0.f,0.f,0.f}, csum[4]={0.f,0.f,0.f,0.f};
#pragma unroll
    for(int i=0;i<4;i++)
#pragma unroll
        for(int j=0;j<4;j++){
            float e=__expf(acc[i][j]*rn[i]*cn[j]*2.0f);
            rsum[i]+=e; csum[j]+=e;
            if(br+ty*4+i==bc+tx*4+j) DG[br+ty*4+i]=e;
        }
#pragma unroll
    for(int i=0;i<4;i++) atomicAdd(&sRS[ty*4+i], rsum[i]);
#pragma unroll
    for(int j=0;j<4;j++) atomicAdd(&sCS[tx*4+j], csum[j]);
    __syncthreads();
    if(tid<64){atomicAdd(&RS[br+tid], sRS[tid]); atomicAdd(&CS[bc+tid], sCS[tid]);}
}

__global__ void k_creduce(const float* __restrict__ RS, const float* __restrict__ CS,
                          const float* __restrict__ DG, float* out){
    __shared__ float sh[1024];
    int tid=threadIdx.x;
    float a=0.f;
    for(int i=tid;i<Bb;i+=1024){
        a+=-logf(DG[i]/(RS[i]+EPSF)+EPSF);
        a+=-logf(DG[i]/(CS[i]+EPSF)+EPSF);
    }
    sh[tid]=a; __syncthreads();
    for(int d=512;d;d>>=1){ if(tid<d) sh[tid]+=sh[tid+d]; __syncthreads(); }
    if(tid==0) out[0]=0.5f*sh[0]/(float)Bb;
}

// ------------- host -------------
#define GSA(var) ([]{ void* _p; cudaGetSymbolAddress(&_p, var); return _p; }())

extern "C" void kernel_launch(void* const* d_in, const int* in_sizes, int n_in,
                              void* d_out, int out_size){
    const float* feat  =(const float*)d_in[0];
    const int*   i1    =(const int*)  d_in[1];
    const float* v1    =(const float*)d_in[2];
    const int*   i2    =(const int*)  d_in[3];
    const float* v2    =(const float*)d_in[4];
    const int*   bidx  =(const int*)  d_in[5];
    const float* Wgen1 =(const float*)d_in[6];
    const float* Wm1   =(const float*)d_in[7];
    const float* bm1   =(const float*)d_in[8];
    const float* Wgen2 =(const float*)d_in[9];
    const float* Wm2   =(const float*)d_in[10];
    const float* bm2   =(const float*)d_in[11];
    const float* W1v1  =(const float*)d_in[12];
    const float* W2v1  =(const float*)d_in[13];
    const float* W1v2  =(const float*)d_in[14];
    const float* W2v2  =(const float*)d_in[15];
    const float* W1v   =(const float*)d_in[16];
    const float* W2v   =(const float*)d_in[17];
    const float* Wg    =(const float*)d_in[18];
    const float* Wg1   =(const float*)d_in[19];
    const float* Wg2   =(const float*)d_in[20];
    const float* Wp1   =(const float*)d_in[21];
    const float* bp1   =(const float*)d_in[22];
    const float* Wp2   =(const float*)d_in[23];
    const float* bp2   =(const float*)d_in[24];
    float* out=(float*)d_out;

    float* XW  =(float*)GSA(g_XW);   float* H   =(float*)GSA(g_H);
    float* emb =(float*)GSA(g_emb);  float* S16 =(float*)GSA(g_S16);
    float* C16 =(float*)GSA(g_C16);
    float* dr=(float*)GSA(g_dr), *dc=(float*)GSA(g_dc);
    float* w1=(float*)GSA(g_w1), *w2=(float*)GSA(g_w2);
    float* b1=(float*)GSA(g_b1), *b2=(float*)GSA(g_b2);
    int* cnt=(int*)GSA(g_cnt), *cntb=(int*)GSA(g_cntb), *cur=(int*)GSA(g_cur);
    int* rp1d=(int*)GSA(g_rp1d), *rp2d=(int*)GSA(g_rp2d);
    int* rp1s=(int*)GSA(g_rp1s), *rp2s=(int*)GSA(g_rp2s);
    int* col1d=(int*)GSA(g_col1d);   float* val1d=(float*)GSA(g_val1d);
    int* col2d=(int*)GSA(g_col2d);   float* val2d=(float*)GSA(g_val2d);
    int* col1s=(int*)GSA(g_col1s);   float* val1s=(float*)GSA(g_val1s);
    int* col2s=(int*)GSA(g_col2s);   float* val2s=(float*)GSA(g_val2s);
    float* Zb=(float*)GSA(g_Zb), *Tb=(float*)GSA(g_Tb);
    float* EV=(float*)GSA(g_EV), *E1=(float*)GSA(g_E1), *E2=(float*)GSA(g_E2);
    float* NV=(float*)GSA(g_NV), *N1=(float*)GSA(g_N1), *N2=(float*)GSA(g_N2);
    float* RS=(float*)GSA(g_RS), *CS=(float*)GSA(g_CS), *DG=(float*)GSA(g_DG);

    const int TB=256;
    int gN  =(Nn+TB-1)/TB;
    int gE  =(Ee+TB-1)/TB;
    int gW  =(Nn*32+TB-1)/TB;      // warp-per-node kernels
    int gWB =(Bb*32+TB-1)/TB;
    dim3 b16(16,16); int g16=(Nn+15)/16;

    auto gemm=[&](const float* A,const float* W,const float* bias,float* C,
                  int n,int K,int M,int act){
        dim3 grid((M+63)/64,(n+63)/64);
        k_gemm<<<grid,256>>>(A,W,bias,C,n,K,M,act);
    };

    // ---- CSR build ----
    k_zero_i<<<gN,TB>>>(cnt,Nn); k_zero_i<<<gN,TB>>>(cntb,Nn);
    k_count<<<gE,TB>>>(i1,cnt,cntb);
    k_scan<<<1,1024>>>(cnt,rp1d,Nn);
    k_scan<<<1,1024>>>(cntb,rp1s,Nn);
    k_zero_i<<<gN,TB>>>(cnt,Nn); k_zero_i<<<gN,TB>>>(cntb,Nn);
    k_count<<<gE,TB>>>(i2,cnt,cntb);
    k_scan<<<1,1024>>>(cnt,rp2d,Nn);
    k_scan<<<1,1024>>>(cntb,rp2s,Nn);
    k_copy_i<<<gN,TB>>>(rp1d,cur,Nn);
    k_scatter_dir<<<gE,TB>>>(i1,v1,cur,col1d,val1d);
    k_copy_i<<<gN,TB>>>(rp2d,cur,Nn);
    k_scatter_dir<<<gE,TB>>>(i2,v2,cur,col2d,val2d);

    // ---- gen_view v1 ----
    gemm(feat,Wgen1,nullptr,XW,Nn,256,64,0);
    k_spmm64<<<gW,TB>>>(rp1d,col1d,val1d,XW,emb,1);
    k_nodedot<<<gW,TB>>>(emb,Wm1,dr,dc);
    k_gensoftmax<<<gW,TB>>>(rp1d,col1d,val1d,dr,dc,bm1,0.5f);
    // ---- gen_view v2 ----
    gemm(feat,Wgen2,nullptr,XW,Nn,256,64,0);
    k_spmm64<<<gW,TB>>>(rp2d,col2d,val2d,XW,emb,1);
    k_nodedot<<<gW,TB>>>(emb,Wm2,dr,dc);
    k_gensoftmax<<<gW,TB>>>(rp2d,col2d,val2d,dr,dc,bm2,0.5f);

    // ---- symmetrize ----
    k_copy_i<<<gN,TB>>>(rp1s,cur,Nn);
    k_scatter_sym<<<gN,TB>>>(rp1d,col1d,val1d,cur,col1s,val1s);
    k_copy_i<<<gN,TB>>>(rp2s,cur,Nn);
    k_scatter_sym<<<gN,TB>>>(rp2d,col2d,val2d,cur,col2s,val2s);

    // ---- classifier v1 ----
    gemm(feat,W1v1,nullptr,XW,Nn,256,128,0);
    k_spmm128<<<gW,TB>>>(rp1s,col1s,val1s,XW,H,1);
    gemm(H,W2v1,nullptr,S16,Nn,128,16,0);
    k_spmm16<<<g16,b16>>>(rp1s,col1s,val1s,S16,C16);
    k_softmax_w<<<gN,TB>>>(C16,out+(long)16*Nn,w1);
    // ---- classifier v2 ----
    gemm(feat,W1v2,nullptr,XW,Nn,256,128,0);
    k_spmm128<<<gW,TB>>>(rp2s,col2s,val2s,XW,H,1);
    gemm(H,W2v2,nullptr,S16,Nn,128,16,0);
    k_spmm16<<<g16,b16>>>(rp2s,col2s,val2s,S16,C16);
    k_softmax_w<<<gN,TB>>>(C16,out+(long)32*Nn,w2);

    k_bal<<<gN,TB>>>(w1,w2,b1,b2);

    // ---- fused classifier ----
    gemm(feat,W1v,nullptr,XW,Nn,256,128,0);
    k_spmm128f<<<gW,TB>>>(rp1s,col1s,val1s,rp2s,col2s,val2s,b1,b2,XW,H,1);
    gemm(H,W2v,nullptr,S16,Nn,128,16,0);
    k_spmm16f<<<g16,b16>>>(rp1s,col1s,val1s,rp2s,col2s,val2s,b1,b2,S16,C16);
    k_softmax_w<<<gN,TB>>>(C16,out,nullptr);

    // ---- MI embeddings ----
    // fused graph
    gemm(feat,Wg,nullptr,XW,Nn,256,128,0);
    k_spmm128f<<<gW,TB>>>(rp1s,col1s,val1s,rp2s,col2s,val2s,b1,b2,XW,H,1);
    k_gather<<<(Bb*128+TB-1)/TB,TB>>>(bidx,H,Zb);
    gemm(Zb,Wp1,bp1,Tb,Bb,128,128,1);
    gemm(Tb,Wp2,bp2,EV,Bb,128,128,0);
    k_rownorm<<<gWB,TB>>>(EV,NV);
    // view1
    gemm(feat,Wg1,nullptr,XW,Nn,256,128,0);
    k_spmm128<<<gW,TB>>>(rp1s,col1s,val1s,XW,H,1);
    k_gather<<<(Bb*128+TB-1)/TB,TB>>>(bidx,H,Zb);
    gemm(Zb,Wp1,bp1,Tb,Bb,128,128,1);
    gemm(Tb,Wp2,bp2,E1,Bb,128,128,0);
    k_rownorm<<<gWB,TB>>>(E1,N1);
    // view2
    gemm(feat,Wg2,nullptr,XW,Nn,256,128,0);
    k_spmm128<<<gW,TB>>>(rp2s,col2s,val2s,XW,H,1);
    k_gather<<<(Bb*128+TB-1)/TB,TB>>>(bidx,H,Zb);
    gemm(Zb,Wp1,bp1,Tb,Bb,128,128,1);
    gemm(Tb,Wp2,bp2,E2,Bb,128,128,0);
    k_rownorm<<<gWB,TB>>>(E2,N2);

    // ---- contrasts ----
    dim3 cg(64,64);
    int gB=(Bb+TB-1)/TB;
    // vv1 = contrast(EV, E1)
    k_zero_f<<<gB,TB>>>(RS,Bb); k_zero_f<<<gB,TB>>>(CS,Bb);
    k_contrast<<<cg,256>>>(EV,E1,NV,N1,RS,CS,DG);
    k_creduce<<<1,1024>>>(RS,CS,DG,out+(long)48*Nn+0);
    // vv2 = contrast(EV, E2)
    k_zero_f<<<gB,TB>>>(RS,Bb); k_zero_f<<<gB,TB>>>(CS,Bb);
    k_contrast<<<cg,256>>>(EV,E2,NV,N2,RS,CS,DG);
    k_creduce<<<1,1024>>>(RS,CS,DG,out+(long)48*Nn+1);
    // v1v2 = contrast(E1, E2)
    k_zero_f<<<gB,TB>>>(RS,Bb); k_zero_f<<<gB,TB>>>(CS,Bb);
    k_contrast<<<cg,256>>>(E1,E2,N1,N2,RS,CS,DG);
    k_creduce<<<1,1024>>>(RS,CS,DG,out+(long)48*Nn+2);
}

// round 3
// speedup vs baseline: 1.1001x; 1.1001x over previous
#include <cuda_runtime.h>
#include <math.h>

#define Nn 30000
#define Ee 480000
#define Bb 4096
#define EPSF 1e-8f

typedef unsigned long long u64;
__device__ __forceinline__ u64 pk2(float x,float y){u64 r;asm("mov.b64 %0,{%1,%2};":"=l"(r):"f"(x),"f"(y));return r;}
__device__ __forceinline__ float2 up2(u64 v){float2 r;asm("mov.b64 {%0,%1},%2;":"=f"(r.x),"=f"(r.y):"l"(v));return r;}
__device__ __forceinline__ void fma2(u64&d,u64 a,u64 b){asm("fma.rn.f32x2 %0,%1,%2,%0;":"+l"(d):"l"(a),"l"(b));}

// ------------- device scratch -------------
__device__ float g_XW[Nn*128];
__device__ float g_H[Nn*128];
__device__ float g_emb[Nn*64];
__device__ float g_S16[Nn*16];
__device__ float g_C16[Nn*16];
__device__ float g_dr[Nn], g_dc[Nn], g_w1[Nn], g_w2[Nn], g_b1[Nn], g_b2[Nn];
__device__ int   g_cnt1[Nn], g_cnt1b[Nn], g_cnt2[Nn], g_cnt2b[Nn], g_cur[Nn];
__device__ int   g_rp1d[Nn+1], g_rp2d[Nn+1], g_rp1s[Nn+1], g_rp2s[Nn+1];
__device__ int   g_col1d[Ee];   __device__ float g_val1d[Ee];
__device__ int   g_col2d[Ee];   __device__ float g_val2d[Ee];
__device__ int   g_col1s[2*Ee]; __device__ float g_val1s[2*Ee];
__device__ int   g_col2s[2*Ee]; __device__ float g_val2s[2*Ee];
__device__ float g_Zb[Bb*128], g_Tb[Bb*128], g_EV[Bb*128], g_E1[Bb*128], g_E2[Bb*128];
__device__ float g_NV[Bb], g_N1[Bb], g_N2[Bb];
__device__ float g_RS[Bb], g_CS[Bb], g_DG[Bb];

// ------------- small utils -------------
__global__ void k_zero_i(int* p, int n){ int i=blockIdx.x*blockDim.x+threadIdx.x; if(i<n) p[i]=0; }
__global__ void k_zero_f(float* p, int n){ int i=blockIdx.x*blockDim.x+threadIdx.x; if(i<n) p[i]=0.f; }
__global__ void k_copy_i(const int* __restrict__ a, int* __restrict__ b, int n){
    int i=blockIdx.x*blockDim.x+threadIdx.x; if(i<n) b[i]=a[i]; }

__global__ void k_count2(const int* __restrict__ ind1, const int* __restrict__ ind2,
                         int* cd1, int* cs1, int* cd2, int* cs2){
    int e=blockIdx.x*blockDim.x+threadIdx.x; if(e>=Ee) return;
    int r1=ind1[e], c1=ind1[Ee+e];
    atomicAdd(&cd1[r1],1); atomicAdd(&cs1[r1],1); atomicAdd(&cs1[c1],1);
    int r2=ind2[e], c2=ind2[Ee+e];
    atomicAdd(&cd2[r2],1); atomicAdd(&cs2[r2],1); atomicAdd(&cs2[c2],1);
}

// 4 independent scans, one block each: chunk-per-thread + shuffle block scan
__global__ void k_scan4(const int* c0,int* r0,const int* c1,int* r1,
                        const int* c2,int* r2,const int* c3,int* r3,int n){
    const int* cnt; int* rp;
    switch(blockIdx.x){
        case 0: cnt=c0; rp=r0; break;
        case 1: cnt=c1; rp=r1; break;
        case 2: cnt=c2; rp=r2; break;
        default:cnt=c3; rp=r3; break;
    }
    const int T=1024;
    int tid=threadIdx.x;
    int chunk=(n+T-1)/T;
    int s=tid*chunk; if(s>n) s=n;
    int e=s+chunk;   if(e>n) e=n;
    int sum=0;
    for(int i=s;i<e;i++) sum+=cnt[i];
    __shared__ int wsum[32];
    int lane=tid&31, wid=tid>>5;
    int v=sum;
#pragma unroll
    for(int o=1;o<32;o<<=1){int t=__shfl_up_sync(0xffffffffu,v,o); if(lane>=o) v+=t;}
    if(lane==31) wsum[wid]=v;
    __syncthreads();
    if(wid==0){
        int w=wsum[lane];
#pragma unroll
        for(int o=1;o<32;o<<=1){int t=__shfl_up_sync(0xffffffffu,w,o); if(lane>=o) w+=t;}
        wsum[lane]=w;
    }
    __syncthreads();
    int excl=v-sum+(wid?wsum[wid-1]:0);
    int run=excl;
    for(int i=s;i<e;i++){ rp[i]=run; run+=cnt[i]; }
    if(tid==T-1) rp[n]=run;
}

__global__ void k_scatter_dir(const int* __restrict__ ind, const float* __restrict__ vals,
                              int* cur, int* __restrict__ col, float* __restrict__ val){
    int e=blockIdx.x*blockDim.x+threadIdx.x; if(e>=Ee) return;
    int r=ind[e], c=ind[Ee+e];
    int p=atomicAdd(&cur[r],1);
    col[p]=c; val[p]=vals[e];
}

__global__ void k_scatter_sym(const int* __restrict__ rpd, const int* __restrict__ cold,
                              const float* __restrict__ vald, int* cur,
                              int* __restrict__ cols, float* __restrict__ vals){
    int r=blockIdx.x*blockDim.x+threadIdx.x; if(r>=Nn) return;
    for(int i=rpd[r];i<rpd[r+1];i++){
        int c=cold[i]; float v=vald[i];
        int p=atomicAdd(&cur[r],1); cols[p]=c; vals[p]=v;
        int q=atomicAdd(&cur[c],1); cols[q]=r; vals[q]=v;
    }
}

// ------------- dense GEMM, f32x2 packed FMA -------------
// C[n,M]=A[n,K]@W[K,M] (+bias, act 0=none 1=elu). 64x64 tile, 256 thr, 4x4/thread.
__global__ void k_gemm(const float* __restrict__ A, const float* __restrict__ W,
                       const float* __restrict__ bias, float* __restrict__ C,
                       int n, int K, int M, int act){
    __shared__ __align__(16) float sA[16][64];
    __shared__ __align__(16) float sW[16][64];
    int tid=threadIdx.x, tx=tid&15, ty=tid>>4;
    int br=blockIdx.y*64, bc=blockIdx.x*64;
    u64 acc[4][2];
#pragma unroll
    for(int i=0;i<4;i++){acc[i][0]=0ULL; acc[i][1]=0ULL;}
    int ra=tid>>2, fa=(tid&3)<<2, cw=tid&63, kb=tid>>6;
    for(int k0=0;k0<K;k0+=16){
        {
            int gr=br+ra;
            float4 v=make_float4(0.f,0.f,0.f,0.f);
            if(gr<n) v=*(const float4*)(A+(long)gr*K+k0+fa);
            sA[fa][ra]=v.x; sA[fa+1][ra]=v.y; sA[fa+2][ra]=v.z; sA[fa+3][ra]=v.w;
        }
        {
            int gc=bc+cw;
#pragma unroll
            for(int i=0;i<4;i++){
                int kk=kb+i*4;
                sW[kk][cw]=(gc<M)?W[(long)(k0+kk)*M+gc]:0.f;
            }
        }
        __syncthreads();
#pragma unroll
        for(int kk=0;kk<16;kk++){
            float4 a=*(const float4*)&sA[kk][ty*4];
            const u64* bp=(const u64*)&sW[kk][tx*4];
            u64 b01=bp[0], b23=bp[1];
            u64 a0=pk2(a.x,a.x), a1=pk2(a.y,a.y), a2=pk2(a.z,a.z), a3=pk2(a.w,a.w);
            fma2(acc[0][0],a0,b01); fma2(acc[0][1],a0,b23);
            fma2(acc[1][0],a1,b01); fma2(acc[1][1],a1,b23);
            fma2(acc[2][0],a2,b01); fma2(acc[2][1],a2,b23);
            fma2(acc[3][0],a3,b01); fma2(acc[3][1],a3,b23);
        }
        __syncthreads();
    }
#pragma unroll
    for(int i=0;i<4;i++){
        int gr=br+ty*4+i; if(gr>=n) continue;
        float2 p0=up2(acc[i][0]), p1=up2(acc[i][1]);
        float vv[4]={p0.x,p0.y,p1.x,p1.y};
#pragma unroll
        for(int j=0;j<4;j++){
            int gc=bc+tx*4+j; if(gc>=M) continue;
            float v=vv[j];
            if(bias) v+=bias[gc];
            if(act==1) v=(v>0.f)?v:expm1f(v);
            C[(long)gr*M+gc]=v;
        }
    }
}

// ------------- SpMM (warp per row) -------------
__global__ void k_spmm64(const int* __restrict__ rp, const int* __restrict__ col,
                         const float* __restrict__ val, const float* __restrict__ X,
                         float* __restrict__ Y, int relu){
    int w=(blockIdx.x*blockDim.x+threadIdx.x)>>5; if(w>=Nn) return;
    int lane=threadIdx.x&31;
    const float2* X2=(const float2*)X;
    float2 acc=make_float2(0.f,0.f);
    for(int i=rp[w];i<rp[w+1];i++){
        int c=col[i]; float v=val[i];
        float2 x=X2[(long)c*32+lane];
        acc.x+=v*x.x; acc.y+=v*x.y;
    }
    if(relu){acc.x=fmaxf(acc.x,0.f); acc.y=fmaxf(acc.y,0.f);}
    ((float2*)Y)[(long)w*32+lane]=acc;
}

__global__ void k_spmm128(const int* __restrict__ rp, const int* __restrict__ col,
                          const float* __restrict__ val, const float* __restrict__ X,
                          float* __restrict__ Y, int relu){
    int w=(blockIdx.x*blockDim.x+threadIdx.x)>>5; if(w>=Nn) return;
    int lane=threadIdx.x&31;
    const float4* X4=(const float4*)X;
    float4 acc=make_float4(0.f,0.f,0.f,0.f);
    for(int i=rp[w];i<rp[w+1];i++){
        int c=col[i]; float v=val[i];
        float4 x=X4[(long)c*32+lane];
        acc.x+=v*x.x; acc.y+=v*x.y; acc.z+=v*x.z; acc.w+=v*x.w;
    }
    if(relu){acc.x=fmaxf(acc.x,0.f);acc.y=fmaxf(acc.y,0.f);acc.z=fmaxf(acc.z,0.f);acc.w=fmaxf(acc.w,0.f);}
    ((float4*)Y)[(long)w*32+lane]=acc;
}

__global__ void k_spmm128f(const int* __restrict__ rp1, const int* __restrict__ col1,
                           const float* __restrict__ val1,
                           const int* __restrict__ rp2, const int* __restrict__ col2,
                           const float* __restrict__ val2,
                           const float* __restrict__ b1, const float* __restrict__ b2,
                           const float* __restrict__ X, float* __restrict__ Y, int relu){
    int w=(blockIdx.x*blockDim.x+threadIdx.x)>>5; if(w>=Nn) return;
    int lane=threadIdx.x&31;
    const float4* X4=(const float4*)X;
    float4 a1=make_float4(0.f,0.f,0.f,0.f), a2=a1;
    for(int i=rp1[w];i<rp1[w+1];i++){
        int c=col1[i]; float v=val1[i];
        float4 x=X4[(long)c*32+lane];
        a1.x+=v*x.x; a1.y+=v*x.y; a1.z+=v*x.z; a1.w+=v*x.w;
    }
    for(int i=rp2[w];i<rp2[w+1];i++){
        int c=col2[i]; float v=val2[i];
        float4 x=X4[(long)c*32+lane];
        a2.x+=v*x.x; a2.y+=v*x.y; a2.z+=v*x.z; a2.w+=v*x.w;
    }
    float f1=b1[w], f2=b2[w];
    float4 r;
    r.x=f1*a1.x+f2*a2.x; r.y=f1*a1.y+f2*a2.y; r.z=f1*a1.z+f2*a2.z; r.w=f1*a1.w+f2*a2.w;
    if(relu){r.x=fmaxf(r.x,0.f);r.y=fmaxf(r.y,0.f);r.z=fmaxf(r.z,0.f);r.w=fmaxf(r.w,0.f);}
    ((float4*)Y)[(long)w*32+lane]=r;
}

__global__ void k_spmm16(const int* __restrict__ rp, const int* __restrict__ col,
                         const float* __restrict__ val, const float* __restrict__ X,
                         float* __restrict__ Y){
    int row=blockIdx.x*16+threadIdx.y; int j=threadIdx.x;
    if(row>=Nn) return;
    float acc=0.f;
    for(int i=rp[row];i<rp[row+1];i++) acc+=val[i]*X[(long)col[i]*16+j];
    Y[(long)row*16+j]=acc;
}

__global__ void k_spmm16f(const int* __restrict__ rp1, const int* __restrict__ col1,
                          const float* __restrict__ val1,
                          const int* __restrict__ rp2, const int* __restrict__ col2,
                          const float* __restrict__ val2,
                          const float* __restrict__ b1, const float* __restrict__ b2,
                          const float* __restrict__ X, float* __restrict__ Y){
    int row=blockIdx.x*16+threadIdx.y; int j=threadIdx.x;
    if(row>=Nn) return;
    float a1=0.f, a2=0.f;
    for(int i=rp1[row];i<rp1[row+1];i++) a1+=val1[i]*X[(long)col1[i]*16+j];
    for(int i=rp2[row];i<rp2[row+1];i++) a2+=val2[i]*X[(long)col2[i]*16+j];
    Y[(long)row*16+j]=b1[row]*a1+b2[row]*a2;
}

// ------------- gen_view helpers -------------
__global__ void k_nodedot(const float* __restrict__ emb, const float* __restrict__ Wm,
                          float* __restrict__ dr, float* __restrict__ dc){
    int node=(blockIdx.x*blockDim.x+threadIdx.x)>>5; if(node>=Nn) return;
    int lane=threadIdx.x&31;
    float2 e=((const float2*)(emb+(long)node*64))[lane];
    float2 wr=((const float2*)Wm)[lane];
    float2 wc=((const float2*)Wm)[lane+32];
    float a=e.x*wr.x+e.y*wr.y;
    float b=e.x*wc.x+e.y*wc.y;
#pragma unroll
    for(int o=16;o;o>>=1){
        a+=__shfl_xor_sync(0xffffffffu,a,o);
        b+=__shfl_xor_sync(0xffffffffu,b,o);
    }
    if(lane==0){dr[node]=a; dc[node]=b;}
}

__global__ void k_gensoftmax(const int* __restrict__ rp, const int* __restrict__ col,
                             float* __restrict__ val, const float* __restrict__ dr,
                             const float* __restrict__ dc, const float* __restrict__ bm,
                             float com){
    int row=(blockIdx.x*blockDim.x+threadIdx.x)>>5; if(row>=Nn) return;
    int lane=threadIdx.x&31;
    int s=rp[row], e=rp[row+1];
    if(s==e) return;
    float base=dr[row]+bm[0];
    float m=-3.4e38f;
    for(int i=s+lane;i<e;i+=32) m=fmaxf(m, base+dc[col[i]]);
#pragma unroll
    for(int o=16;o;o>>=1) m=fmaxf(m,__shfl_xor_sync(0xffffffffu,m,o));
    float ss=0.f;
    for(int i=s+lane;i<e;i+=32) ss+=__expf(base+dc[col[i]]-m);
#pragma unroll
    for(int o=16;o;o>>=1) ss+=__shfl_xor_sync(0xffffffffu,ss,o);
    float inv=com/ss;
    for(int i=s+lane;i<e;i+=32) val[i]+=__expf(base+dc[col[i]]-m)*inv;
}

// ------------- 16-class softmax + logits + top2 weight -------------
__global__ void k_softmax_w(const float* __restrict__ C, float* __restrict__ lg,
                            float* __restrict__ w){
    int node=blockIdx.x*blockDim.x+threadIdx.x; if(node>=Nn) return;
    float x[16];
    const float4* p=(const float4*)(C+(long)node*16);
#pragma unroll
    for(int q=0;q<4;q++){float4 t=p[q]; x[4*q]=t.x; x[4*q+1]=t.y; x[4*q+2]=t.z; x[4*q+3]=t.w;}
    float m=x[0];
#pragma unroll
    for(int j=1;j<16;j++) m=fmaxf(m,x[j]);
    float s=0.f;
#pragma unroll
    for(int j=0;j<16;j++){x[j]=__expf(x[j]-m); s+=x[j];}
    float inv=1.f/s;
    float fir=0.f, sec=0.f;
#pragma unroll
    for(int j=0;j<16;j++){
        float pr=x[j]*inv;
        lg[(long)node*16+j]=logf(pr+EPSF);
        if(pr>fir){sec=fir; fir=pr;} else if(pr>sec) sec=pr;
    }
    if(w) w[node]=sqrtf((fir+EPSF)*(fir-sec+EPSF));
}

__global__ void k_bal(const float* __restrict__ w1, const float* __restrict__ w2,
                      float* __restrict__ b1, float* __restrict__ b2){
    int i=blockIdx.x*blockDim.x+threadIdx.x; if(i>=Nn) return;
    float a=w1[i], b=w2[i], inv=1.f/(a+b);
    b1[i]=a*inv; b2[i]=b*inv;
}

__global__ void k_gather(const int* __restrict__ idx, const float* __restrict__ H,
                         float* __restrict__ Z){
    int t=blockIdx.x*blockDim.x+threadIdx.x; if(t>=Bb*128) return;
    int i=t>>7, j=t&127;
    Z[t]=H[(long)idx[i]*128+j];
}

__global__ void k_rownorm(const float* __restrict__ Z, float* __restrict__ nrm){
    int row=(blockIdx.x*blockDim.x+threadIdx.x)>>5; if(row>=Bb) return;
    int lane=threadIdx.x&31;
    float4 v=((const float4*)(Z+(long)row*128))[lane];
    float s=v.x*v.x+v.y*v.y+v.z*v.z+v.w*v.w;
#pragma unroll
    for(int o=16;o;o>>=1) s+=__shfl_xor_sync(0xffffffffu,s,o);
    if(lane==0) nrm[row]=sqrtf(s);
}

// ------------- contrast: rowsum/colsum/diag of exp(2*cos), f32x2 core -------------
__global__ void k_contrast(const float* __restrict__ z1, const float* __restrict__ z2,
                           const float* __restrict__ n1, const float* __restrict__ n2,
                           float* RS, float* CS, float* DG){
    __shared__ __align__(16) float sA[16][64];
    __shared__ __align__(16) float sB[16][64];
    __shared__ float sRS[64], sCS[64];
    int tid=threadIdx.x, tx=tid&15, ty=tid>>4;
    int br=blockIdx.y*64, bc=blockIdx.x*64;
    u64 acc[4][2];
#pragma unroll
    for(int i=0;i<4;i++){acc[i][0]=0ULL; acc[i][1]=0ULL;}
    int ra=tid>>2, fa=(tid&3)<<2;
    for(int k0=0;k0<128;k0+=16){
        {float4 v=*(const float4*)(z1+(long)(br+ra)*128+k0+fa);
         sA[fa][ra]=v.x; sA[fa+1][ra]=v.y; sA[fa+2][ra]=v.z; sA[fa+3][ra]=v.w;}
        {float4 v=*(const float4*)(z2+(long)(bc+ra)*128+k0+fa);
         sB[fa][ra]=v.x; sB[fa+1][ra]=v.y; sB[fa+2][ra]=v.z; sB[fa+3][ra]=v.w;}
        __syncthreads();
#pragma unroll
        for(int kk=0;kk<16;kk++){
            float4 a=*(const float4*)&sA[kk][ty*4];
            const u64* bp=(const u64*)&sB[kk][tx*4];
            u64 b01=bp[0], b23=bp[1];
            u64 a0=pk2(a.x,a.x), a1=pk2(a.y,a.y), a2=pk2(a.z,a.z), a3=pk2(a.w,a.w);
            fma2(acc[0][0],a0,b01); fma2(acc[0][1],a0,b23);
            fma2(acc[1][0],a1,b01); fma2(acc[1][1],a1,b23);
            fma2(acc[2][0],a2,b01); fma2(acc[2][1],a2,b23);
            fma2(acc[3][0],a3,b01); fma2(acc[3][1],a3,b23);
        }
        __syncthreads();
    }
    if(tid<64){sRS[tid]=0.f; sCS[tid]=0.f;}
    __syncthreads();
    float rn[4], cn[4];
#pragma unroll
    for(int i=0;i<4;i++) rn[i]=1.f/n1[br+ty*4+i];
#pragma unroll
    for(int j=0;j<4;j++) cn[j]=1.f/n2[bc+tx*4+j];
    float rsum[4]={0.f,0.f,0.f,0.f}, csum[4]={0.f,0.f,0.f,0.f};
#pragma unroll
    for(int i=0;i<4;i++){
        float2 p0=up2(acc[i][0]), p1=up2(acc[i][1]);
        float vv[4]={p0.x,p0.y,p1.x,p1.y};
#pragma unroll
        for(int j=0;j<4;j++){
            float e=__expf(vv[j]*rn[i]*cn[j]*2.0f);
            rsum[i]+=e; csum[j]+=e;
            if(br+ty*4+i==bc+tx*4+j) DG[br+ty*4+i]=e;
        }
    }
#pragma unroll
    for(int i=0;i<4;i++) atomicAdd(&sRS[ty*4+i], rsum[i]);
#pragma unroll
    for(int j=0;j<4;j++) atomicAdd(&sCS[tx*4+j], csum[j]);
    __syncthreads();
    if(tid<64){atomicAdd(&RS[br+tid], sRS[tid]); atomicAdd(&CS[bc+tid], sCS[tid]);}
}

__global__ void k_creduce(const float* __restrict__ RS, const float* __restrict__ CS,
                          const float* __restrict__ DG, float* out){
    __shared__ float sh[1024];
    int tid=threadIdx.x;
    float a=0.f;
    for(int i=tid;i<Bb;i+=1024){
        a+=-logf(DG[i]/(RS[i]+EPSF)+EPSF);
        a+=-logf(DG[i]/(CS[i]+EPSF)+EPSF);
    }
    sh[tid]=a; __syncthreads();
    for(int d=512;d;d>>=1){ if(tid<d) sh[tid]+=sh[tid+d]; __syncthreads(); }
    if(tid==0) out[0]=0.5f*sh[0]/(float)Bb;
}

// ------------- host -------------
#define GSA(var) ([]{ void* _p; cudaGetSymbolAddress(&_p, var); return _p; }())

extern "C" void kernel_launch(void* const* d_in, const int* in_sizes, int n_in,
                              void* d_out, int out_size){
    const float* feat  =(const float*)d_in[0];
    const int*   i1    =(const int*)  d_in[1];
    const float* v1    =(const float*)d_in[2];
    const int*   i2    =(const int*)  d_in[3];
    const float* v2    =(const float*)d_in[4];
    const int*   bidx  =(const int*)  d_in[5];
    const float* Wgen1 =(const float*)d_in[6];
    const float* Wm1   =(const float*)d_in[7];
    const float* bm1   =(const float*)d_in[8];
    const float* Wgen2 =(const float*)d_in[9];
    const float* Wm2   =(const float*)d_in[10];
    const float* bm2   =(const float*)d_in[11];
    const float* W1v1  =(const float*)d_in[12];
    const float* W2v1  =(const float*)d_in[13];
    const float* W1v2  =(const float*)d_in[14];
    const float* W2v2  =(const float*)d_in[15];
    const float* W1v   =(const float*)d_in[16];
    const float* W2v   =(const float*)d_in[17];
    const float* Wg    =(const float*)d_in[18];
    const float* Wg1   =(const float*)d_in[19];
    const float* Wg2   =(const float*)d_in[20];
    const float* Wp1   =(const float*)d_in[21];
    const float* bp1   =(const float*)d_in[22];
    const float* Wp2   =(const float*)d_in[23];
    const float* bp2   =(const float*)d_in[24];
    float* out=(float*)d_out;

    float* XW  =(float*)GSA(g_XW);   float* H   =(float*)GSA(g_H);
    float* emb =(float*)GSA(g_emb);  float* S16 =(float*)GSA(g_S16);
    float* C16 =(float*)GSA(g_C16);
    float* dr=(float*)GSA(g_dr), *dc=(float*)GSA(g_dc);
    float* w1=(float*)GSA(g_w1), *w2=(float*)GSA(g_w2);
    float* b1=(float*)GSA(g_b1), *b2=(float*)GSA(g_b2);
    int* cnt1=(int*)GSA(g_cnt1), *cnt1b=(int*)GSA(g_cnt1b);
    int* cnt2=(int*)GSA(g_cnt2), *cnt2b=(int*)GSA(g_cnt2b);
    int* cur=(int*)GSA(g_cur);
    int* rp1d=(int*)GSA(g_rp1d), *rp2d=(int*)GSA(g_rp2d);
    int* rp1s=(int*)GSA(g_rp1s), *rp2s=(int*)GSA(g_rp2s);
    int* col1d=(int*)GSA(g_col1d);   float* val1d=(float*)GSA(g_val1d);
    int* col2d=(int*)GSA(g_col2d);   float* val2d=(float*)GSA(g_val2d);
    int* col1s=(int*)GSA(g_col1s);   float* val1s=(float*)GSA(g_val1s);
    int* col2s=(int*)GSA(g_col2s);   float* val2s=(float*)GSA(g_val2s);
    float* Zb=(float*)GSA(g_Zb), *Tb=(float*)GSA(g_Tb);
    float* EV=(float*)GSA(g_EV), *E1=(float*)GSA(g_E1), *E2=(float*)GSA(g_E2);
    float* NV=(float*)GSA(g_NV), *N1=(float*)GSA(g_N1), *N2=(float*)GSA(g_N2);
    float* RS=(float*)GSA(g_RS), *CS=(float*)GSA(g_CS), *DG=(float*)GSA(g_DG);

    const int TB=256;
    int gN  =(Nn+TB-1)/TB;
    int gE  =(Ee+TB-1)/TB;
    int gW  =(Nn*32+TB-1)/TB;
    int gWB =(Bb*32+TB-1)/TB;
    dim3 b16(16,16); int g16=(Nn+15)/16;

    auto gemm=[&](const float* A,const float* W,const float* bias,float* C,
                  int n,int K,int M,int act){
        dim3 grid((M+63)/64,(n+63)/64);
        k_gemm<<<grid,256>>>(A,W,bias,C,n,K,M,act);
    };

    // ---- CSR build ----
    k_zero_i<<<gN,TB>>>(cnt1,Nn); k_zero_i<<<gN,TB>>>(cnt1b,Nn);
    k_zero_i<<<gN,TB>>>(cnt2,Nn); k_zero_i<<<gN,TB>>>(cnt2b,Nn);
    k_count2<<<gE,TB>>>(i1,i2,cnt1,cnt1b,cnt2,cnt2b);
    k_scan4<<<4,1024>>>(cnt1,rp1d,cnt1b,rp1s,cnt2,rp2d,cnt2b,rp2s,Nn);
    k_copy_i<<<gN,TB>>>(rp1d,cur,Nn);
    k_scatter_dir<<<gE,TB>>>(i1,v1,cur,col1d,val1d);
    k_copy_i<<<gN,TB>>>(rp2d,cur,Nn);
    k_scatter_dir<<<gE,TB>>>(i2,v2,cur,col2d,val2d);

    // ---- gen_view v1 ----
    gemm(feat,Wgen1,nullptr,XW,Nn,256,64,0);
    k_spmm64<<<gW,TB>>>(rp1d,col1d,val1d,XW,emb,1);
    k_nodedot<<<gW,TB>>>(emb,Wm1,dr,dc);
    k_gensoftmax<<<gW,TB>>>(rp1d,col1d,val1d,dr,dc,bm1,0.5f);
    // ---- gen_view v2 ----
    gemm(feat,Wgen2,nullptr,XW,Nn,256,64,0);
    k_spmm64<<<gW,TB>>>(rp2d,col2d,val2d,XW,emb,1);
    k_nodedot<<<gW,TB>>>(emb,Wm2,dr,dc);
    k_gensoftmax<<<gW,TB>>>(rp2d,col2d,val2d,dr,dc,bm2,0.5f);

    // ---- symmetrize ----
    k_copy_i<<<gN,TB>>>(rp1s,cur,Nn);
    k_scatter_sym<<<gN,TB>>>(rp1d,col1d,val1d,cur,col1s,val1s);
    k_copy_i<<<gN,TB>>>(rp2s,cur,Nn);
    k_scatter_sym<<<gN,TB>>>(rp2d,col2d,val2d,cur,col2s,val2s);

    // ---- classifier v1 ----
    gemm(feat,W1v1,nullptr,XW,Nn,256,128,0);
    k_spmm128<<<gW,TB>>>(rp1s,col1s,val1s,XW,H,1);
    gemm(H,W2v1,nullptr,S16,Nn,128,16,0);
    k_spmm16<<<g16,b16>>>(rp1s,col1s,val1s,S16,C16);
    k_softmax_w<<<gN,TB>>>(C16,out+(long)16*Nn,w1);
    // ---- classifier v2 ----
    gemm(feat,W1v2,nullptr,XW,Nn,256,128,0);
    k_spmm128<<<gW,TB>>>(rp2s,col2s,val2s,XW,H,1);
    gemm(H,W2v2,nullptr,S16,Nn,128,16,0);
    k_spmm16<<<g16,b16>>>(rp2s,col2s,val2s,S16,C16);
    k_softmax_w<<<gN,TB>>>(C16,out+(long)32*Nn,w2);

    k_bal<<<gN,TB>>>(w1,w2,b1,b2);

    // ---- fused classifier ----
    gemm(feat,W1v,nullptr,XW,Nn,256,128,0);
    k_spmm128f<<<gW,TB>>>(rp1s,col1s,val1s,rp2s,col2s,val2s,b1,b2,XW,H,1);
    gemm(H,W2v,nullptr,S16,Nn,128,16,0);
    k_spmm16f<<<g16,b16>>>(rp1s,col1s,val1s,rp2s,col2s,val2s,b1,b2,S16,C16);
    k_softmax_w<<<gN,TB>>>(C16,out,nullptr);

    // ---- MI embeddings ----
    gemm(feat,Wg,nullptr,XW,Nn,256,128,0);
    k_spmm128f<<<gW,TB>>>(rp1s,col1s,val1s,rp2s,col2s,val2s,b1,b2,XW,H,1);
    k_gather<<<(Bb*128+TB-1)/TB,TB>>>(bidx,H,Zb);
    gemm(Zb,Wp1,bp1,Tb,Bb,128,128,1);
    gemm(Tb,Wp2,bp2,EV,Bb,128,128,0);
    k_rownorm<<<gWB,TB>>>(EV,NV);

    gemm(feat,Wg1,nullptr,XW,Nn,256,128,0);
    k_spmm128<<<gW,TB>>>(rp1s,col1s,val1s,XW,H,1);
    k_gather<<<(Bb*128+TB-1)/TB,TB>>>(bidx,H,Zb);
    gemm(Zb,Wp1,bp1,Tb,Bb,128,128,1);
    gemm(Tb,Wp2,bp2,E1,Bb,128,128,0);
    k_rownorm<<<gWB,TB>>>(E1,N1);

    gemm(feat,Wg2,nullptr,XW,Nn,256,128,0);
    k_spmm128<<<gW,TB>>>(rp2s,col2s,val2s,XW,H,1);
    k_gather<<<(Bb*128+TB-1)/TB,TB>>>(bidx,H,Zb);
    gemm(Zb,Wp1,bp1,Tb,Bb,128,128,1);
    gemm(Tb,Wp2,bp2,E2,Bb,128,128,0);
    k_rownorm<<<gWB,TB>>>(E2,N2);

    // ---- contrasts ----
    dim3 cg(64,64);
    int gB=(Bb+TB-1)/TB;
    k_zero_f<<<gB,TB>>>(RS,Bb); k_zero_f<<<gB,TB>>>(CS,Bb);
    k_contrast<<<cg,256>>>(EV,E1,NV,N1,RS,CS,DG);
    k_creduce<<<1,1024>>>(RS,CS,DG,out+(long)48*Nn+0);
    k_zero_f<<<gB,TB>>>(RS,Bb); k_zero_f<<<gB,TB>>>(CS,Bb);
    k_contrast<<<cg,256>>>(EV,E2,NV,N2,RS,CS,DG);
    k_creduce<<<1,1024>>>(RS,CS,DG,out+(long)48*Nn+1);
    k_zero_f<<<gB,TB>>>(RS,Bb); k_zero_f<<<gB,TB>>>(CS,Bb);
    k_contrast<<<cg,256>>>(E1,E2,N1,N2,RS,CS,DG);
    k_creduce<<<1,1024>>>(RS,CS,DG,out+(long)48*Nn+2);
}

// round 4
// speedup vs baseline: 1.3460x; 1.2236x over previous
#include <cuda_runtime.h>
#include <math.h>

#define Nn 30000
#define Ee 480000
#define Bb 4096
#define EPSF 1e-8f

typedef unsigned long long u64;
__device__ __forceinline__ u64 pk2(float x,float y){u64 r;asm("mov.b64 %0,{%1,%2};":"=l"(r):"f"(x),"f"(y));return r;}
__device__ __forceinline__ float2 up2(u64 v){float2 r;asm("mov.b64 {%0,%1},%2;":"=f"(r.x),"=f"(r.y):"l"(v));return r;}
__device__ __forceinline__ void fma2(u64&d,u64 a,u64 b){asm("fma.rn.f32x2 %0,%1,%2,%0;":"+l"(d):"l"(a),"l"(b));}

// ------------- device scratch -------------
__device__ float g_XW[Nn*128];
__device__ float g_H[Nn*128];
__device__ float g_emb[Nn*64];
__device__ float g_S16[Nn*16];
__device__ float g_C16[Nn*16];
__device__ float g_dr[Nn], g_dc[Nn], g_w1[Nn], g_w2[Nn], g_b1[Nn], g_b2[Nn];
__device__ int   g_cnt1[Nn], g_cnt1b[Nn], g_cnt2[Nn], g_cnt2b[Nn], g_cur[Nn];
__device__ int   g_rp1d[Nn+1], g_rp2d[Nn+1], g_rp1s[Nn+1], g_rp2s[Nn+1];
__device__ int   g_col1d[Ee];   __device__ float g_val1d[Ee];
__device__ int   g_col2d[Ee];   __device__ float g_val2d[Ee];
__device__ int   g_col1s[2*Ee]; __device__ float g_val1s[2*Ee];
__device__ int   g_col2s[2*Ee]; __device__ float g_val2s[2*Ee];
__device__ float g_Z[3*Bb*128], g_T[3*Bb*128], g_E[3*Bb*128];
__device__ float g_RS[3*Bb], g_CS[3*Bb], g_DG[3*Bb];

// ------------- small utils -------------
__global__ void k_zero4(int* a,int* b,int* c,int* d,int n){
    int i=blockIdx.x*blockDim.x+threadIdx.x; if(i<n){a[i]=0;b[i]=0;c[i]=0;d[i]=0;} }
__global__ void k_zero_f2(float* a, float* b, int n){
    int i=blockIdx.x*blockDim.x+threadIdx.x; if(i<n){a[i]=0.f;b[i]=0.f;} }
__global__ void k_copy_i(const int* __restrict__ a, int* __restrict__ b, int n){
    int i=blockIdx.x*blockDim.x+threadIdx.x; if(i<n) b[i]=a[i]; }

__global__ void k_count2(const int* __restrict__ ind1, const int* __restrict__ ind2,
                         int* cd1, int* cs1, int* cd2, int* cs2){
    int e=blockIdx.x*blockDim.x+threadIdx.x; if(e>=Ee) return;
    int r1=ind1[e], c1=ind1[Ee+e];
    atomicAdd(&cd1[r1],1); atomicAdd(&cs1[r1],1); atomicAdd(&cs1[c1],1);
    int r2=ind2[e], c2=ind2[Ee+e];
    atomicAdd(&cd2[r2],1); atomicAdd(&cs2[r2],1); atomicAdd(&cs2[c2],1);
}

__global__ void k_scan4(const int* c0,int* r0,const int* c1,int* r1,
                        const int* c2,int* r2,const int* c3,int* r3,int n){
    const int* cnt; int* rp;
    switch(blockIdx.x){
        case 0: cnt=c0; rp=r0; break;
        case 1: cnt=c1; rp=r1; break;
        case 2: cnt=c2; rp=r2; break;
        default:cnt=c3; rp=r3; break;
    }
    const int T=1024;
    int tid=threadIdx.x;
    int chunk=(n+T-1)/T;
    int s=tid*chunk; if(s>n) s=n;
    int e=s+chunk;   if(e>n) e=n;
    int sum=0;
    for(int i=s;i<e;i++) sum+=cnt[i];
    __shared__ int wsum[32];
    int lane=tid&31, wid=tid>>5;
    int v=sum;
#pragma unroll
    for(int o=1;o<32;o<<=1){int t=__shfl_up_sync(0xffffffffu,v,o); if(lane>=o) v+=t;}
    if(lane==31) wsum[wid]=v;
    __syncthreads();
    if(wid==0){
        int w=wsum[lane];
#pragma unroll
        for(int o=1;o<32;o<<=1){int t=__shfl_up_sync(0xffffffffu,w,o); if(lane>=o) w+=t;}
        wsum[lane]=w;
    }
    __syncthreads();
    int excl=v-sum+(wid?wsum[wid-1]:0);
    int run=excl;
    for(int i=s;i<e;i++){ rp[i]=run; run+=cnt[i]; }
    if(tid==T-1) rp[n]=run;
}

__global__ void k_scatter_dir(const int* __restrict__ ind, const float* __restrict__ vals,
                              int* cur, int* __restrict__ col, float* __restrict__ val){
    int e=blockIdx.x*blockDim.x+threadIdx.x; if(e>=Ee) return;
    int r=ind[e], c=ind[Ee+e];
    int p=atomicAdd(&cur[r],1);
    col[p]=c; val[p]=vals[e];
}

__global__ void k_scatter_sym(const int* __restrict__ rpd, const int* __restrict__ cold,
                              const float* __restrict__ vald, int* cur,
                              int* __restrict__ cols, float* __restrict__ vals){
    int r=blockIdx.x*blockDim.x+threadIdx.x; if(r>=Nn) return;
    for(int i=rpd[r];i<rpd[r+1];i++){
        int c=cold[i]; float v=vald[i];
        int p=atomicAdd(&cur[r],1); cols[p]=c; vals[p]=v;
        int q=atomicAdd(&cur[c],1); cols[q]=r; vals[q]=v;
    }
}

// ------------- dense GEMM 128x128 tile, 8x8/thread, f32x2 -------------
// C[n,M]=A[n,K]@W[K,M] (+bias, act 0=none 1=elu). M<=128 mult of 8, K mult of 16.
__global__ __launch_bounds__(256) void k_gemm128(
        const float* __restrict__ A, const float* __restrict__ W,
        const float* __restrict__ bias, float* __restrict__ C,
        int n, int K, int M, int act){
    __shared__ __align__(16) float sA[16*130];
    __shared__ __align__(16) float sW[16*128];
    int tid=threadIdx.x, tx=tid&15, ty=tid>>4;
    int br=blockIdx.y*128;
    u64 acc[8][4];
#pragma unroll
    for(int i=0;i<8;i++){acc[i][0]=0;acc[i][1]=0;acc[i][2]=0;acc[i][3]=0;}
    int ra=tid>>2, fa=(tid&3)<<2;        // A loader: rows ra, ra+64; k chunk fa
    int cw=(tid&31)<<2, kw=tid>>5;       // W loader: col chunk cw; k rows kw, kw+8

    for(int k0=0;k0<K;k0+=16){
        // load A tile [128 x 16]
#pragma unroll
        for(int h=0;h<2;h++){
            int r=ra+h*64, gr=br+r;
            float4 v=make_float4(0.f,0.f,0.f,0.f);
            if(gr<n) v=*(const float4*)(A+(long)gr*K+k0+fa);
            sA[(fa+0)*130+r]=v.x; sA[(fa+1)*130+r]=v.y;
            sA[(fa+2)*130+r]=v.z; sA[(fa+3)*130+r]=v.w;
        }
        // load W tile [16 x 128]
#pragma unroll
        for(int h=0;h<2;h++){
            int kk=kw+h*8;
            float4 v=make_float4(0.f,0.f,0.f,0.f);
            if(cw<M) v=*(const float4*)(W+(long)(k0+kk)*M+cw);
            *(float4*)&sW[kk*128+cw]=v;
        }
        __syncthreads();
#pragma unroll
        for(int kk=0;kk<16;kk++){
            const float* sak=&sA[kk*130+ty*8];
            float2 a01=*(const float2*)(sak);
            float2 a23=*(const float2*)(sak+2);
            float2 a45=*(const float2*)(sak+4);
            float2 a67=*(const float2*)(sak+6);
            const ulonglong2* bw=(const ulonglong2*)&sW[kk*128+tx*8];
            ulonglong2 bA=bw[0], bB=bw[1];
            u64 s0=pk2(a01.x,a01.x), s1=pk2(a01.y,a01.y);
            u64 s2=pk2(a23.x,a23.x), s3=pk2(a23.y,a23.y);
            u64 s4=pk2(a45.x,a45.x), s5=pk2(a45.y,a45.y);
            u64 s6=pk2(a67.x,a67.x), s7=pk2(a67.y,a67.y);
            fma2(acc[0][0],s0,bA.x); fma2(acc[0][1],s0,bA.y); fma2(acc[0][2],s0,bB.x); fma2(acc[0][3],s0,bB.y);
            fma2(acc[1][0],s1,bA.x); fma2(acc[1][1],s1,bA.y); fma2(acc[1][2],s1,bB.x); fma2(acc[1][3],s1,bB.y);
            fma2(acc[2][0],s2,bA.x); fma2(acc[2][1],s2,bA.y); fma2(acc[2][2],s2,bB.x); fma2(acc[2][3],s2,bB.y);
            fma2(acc[3][0],s3,bA.x); fma2(acc[3][1],s3,bA.y); fma2(acc[3][2],s3,bB.x); fma2(acc[3][3],s3,bB.y);
            fma2(acc[4][0],s4,bA.x); fma2(acc[4][1],s4,bA.y); fma2(acc[4][2],s4,bB.x); fma2(acc[4][3],s4,bB.y);
            fma2(acc[5][0],s5,bA.x); fma2(acc[5][1],s5,bA.y); fma2(acc[5][2],s5,bB.x); fma2(acc[5][3],s5,bB.y);
            fma2(acc[6][0],s6,bA.x); fma2(acc[6][1],s6,bA.y); fma2(acc[6][2],s6,bB.x); fma2(acc[6][3],s6,bB.y);
            fma2(acc[7][0],s7,bA.x); fma2(acc[7][1],s7,bA.y); fma2(acc[7][2],s7,bB.x); fma2(acc[7][3],s7,bB.y);
        }
        __syncthreads();
    }
    if(tx*8 >= M) return;
    float bb[8];
#pragma unroll
    for(int q=0;q<8;q++) bb[q]=bias?bias[tx*8+q]:0.f;
#pragma unroll
    for(int i=0;i<8;i++){
        int gr=br+ty*8+i; if(gr>=n) continue;
        float vv[8];
#pragma unroll
        for(int p=0;p<4;p++){float2 t=up2(acc[i][p]); vv[2*p]=t.x; vv[2*p+1]=t.y;}
#pragma unroll
        for(int q=0;q<8;q++){
            float v=vv[q]+bb[q];
            if(act==1) v=(v>0.f)?v:expm1f(v);
            vv[q]=v;
        }
        float* cp=C+(long)gr*M+tx*8;
        *(float4*)cp=make_float4(vv[0],vv[1],vv[2],vv[3]);
        *(float4*)(cp+4)=make_float4(vv[4],vv[5],vv[6],vv[7]);
    }
}

// ------------- GEMM M=16 (W2 in smem): C[n,16]=H[n,128]@W2[128,16] -------------
__global__ void k_gemm16(const float* __restrict__ H, const float* __restrict__ W2,
                         float* __restrict__ C, int n){
    __shared__ float sW[128*16];
    int tid=threadIdx.y*16+threadIdx.x;
#pragma unroll
    for(int q=0;q<2;q++) ((float4*)sW)[tid*2+q]=((const float4*)W2)[tid*2+q];
    __syncthreads();
    int r=blockIdx.x*16+threadIdx.y, j=threadIdx.x;
    if(r>=n) return;
    const float4* H4=(const float4*)(H+(long)r*128);
    float acc=0.f;
#pragma unroll
    for(int k4=0;k4<32;k4++){
        float4 h=H4[k4];
        acc+=h.x*sW[(k4*4+0)*16+j];
        acc+=h.y*sW[(k4*4+1)*16+j];
        acc+=h.z*sW[(k4*4+2)*16+j];
        acc+=h.w*sW[(k4*4+3)*16+j];
    }
    C[(long)r*16+j]=acc;
}

// ------------- SpMM (warp per row, 2-way unrolled) -------------
__device__ __forceinline__ float4 spmm_row128(const int* __restrict__ rp,
        const int* __restrict__ col, const float* __restrict__ val,
        const float4* __restrict__ X4, int w, int lane){
    int s=rp[w], e=rp[w+1];
    float4 A=make_float4(0.f,0.f,0.f,0.f), B=A;
    int i=s;
    for(; i+1<e; i+=2){
        int c0=col[i], c1=col[i+1];
        float v0=val[i], v1=val[i+1];
        float4 x0=X4[(long)c0*32+lane];
        float4 x1=X4[(long)c1*32+lane];
        A.x+=v0*x0.x; A.y+=v0*x0.y; A.z+=v0*x0.z; A.w+=v0*x0.w;
        B.x+=v1*x1.x; B.y+=v1*x1.y; B.z+=v1*x1.z; B.w+=v1*x1.w;
    }
    if(i<e){
        int c=col[i]; float v=val[i];
        float4 x=X4[(long)c*32+lane];
        A.x+=v*x.x; A.y+=v*x.y; A.z+=v*x.z; A.w+=v*x.w;
    }
    A.x+=B.x; A.y+=B.y; A.z+=B.z; A.w+=B.w;
    return A;
}

__global__ void k_spmm128(const int* __restrict__ rp, const int* __restrict__ col,
                          const float* __restrict__ val, const float* __restrict__ X,
                          float* __restrict__ Y){
    int w=(blockIdx.x*blockDim.x+threadIdx.x)>>5; if(w>=Nn) return;
    int lane=threadIdx.x&31;
    float4 a=spmm_row128(rp,col,val,(const float4*)X,w,lane);
    a.x=fmaxf(a.x,0.f); a.y=fmaxf(a.y,0.f); a.z=fmaxf(a.z,0.f); a.w=fmaxf(a.w,0.f);
    ((float4*)Y)[(long)w*32+lane]=a;
}

__global__ void k_spmm128f(const int* __restrict__ rp1, const int* __restrict__ col1,
                           const float* __restrict__ val1,
                           const int* __restrict__ rp2, const int* __restrict__ col2,
                           const float* __restrict__ val2,
                           const float* __restrict__ b1, const float* __restrict__ b2,
                           const float* __restrict__ X, float* __restrict__ Y){
    int w=(blockIdx.x*blockDim.x+threadIdx.x)>>5; if(w>=Nn) return;
    int lane=threadIdx.x&31;
    float4 a1=spmm_row128(rp1,col1,val1,(const float4*)X,w,lane);
    float4 a2=spmm_row128(rp2,col2,val2,(const float4*)X,w,lane);
    float f1=b1[w], f2=b2[w];
    float4 r;
    r.x=fmaxf(f1*a1.x+f2*a2.x,0.f); r.y=fmaxf(f1*a1.y+f2*a2.y,0.f);
    r.z=fmaxf(f1*a1.z+f2*a2.z,0.f); r.w=fmaxf(f1*a1.w+f2*a2.w,0.f);
    ((float4*)Y)[(long)w*32+lane]=r;
}

// gathered variants: only rows in bidx, compact output [Bb x 128]
__global__ void k_spmm128g(const int* __restrict__ bidx,
                           const int* __restrict__ rp, const int* __restrict__ col,
                           const float* __restrict__ val, const float* __restrict__ X,
                           float* __restrict__ Z){
    int w=(blockIdx.x*blockDim.x+threadIdx.x)>>5; if(w>=Bb) return;
    int lane=threadIdx.x&31;
    int row=bidx[w];
    float4 a=spmm_row128(rp,col,val,(const float4*)X,row,lane);
    a.x=fmaxf(a.x,0.f); a.y=fmaxf(a.y,0.f); a.z=fmaxf(a.z,0.f); a.w=fmaxf(a.w,0.f);
    ((float4*)Z)[(long)w*32+lane]=a;
}

__global__ void k_spmm128fg(const int* __restrict__ bidx,
                            const int* __restrict__ rp1, const int* __restrict__ col1,
                            const float* __restrict__ val1,
                            const int* __restrict__ rp2, const int* __restrict__ col2,
                            const float* __restrict__ val2,
                            const float* __restrict__ b1, const float* __restrict__ b2,
                            const float* __restrict__ X, float* __restrict__ Z){
    int w=(blockIdx.x*blockDim.x+threadIdx.x)>>5; if(w>=Bb) return;
    int lane=threadIdx.x&31;
    int row=bidx[w];
    float4 a1=spmm_row128(rp1,col1,val1,(const float4*)X,row,lane);
    float4 a2=spmm_row128(rp2,col2,val2,(const float4*)X,row,lane);
    float f1=b1[row], f2=b2[row];
    float4 r;
    r.x=fmaxf(f1*a1.x+f2*a2.x,0.f); r.y=fmaxf(f1*a1.y+f2*a2.y,0.f);
    r.z=fmaxf(f1*a1.z+f2*a2.z,0.f); r.w=fmaxf(f1*a1.w+f2*a2.w,0.f);
    ((float4*)Z)[(long)w*32+lane]=r;
}

__global__ void k_spmm64(const int* __restrict__ rp, const int* __restrict__ col,
                         const float* __restrict__ val, const float* __restrict__ X,
                         float* __restrict__ Y){
    int w=(blockIdx.x*blockDim.x+threadIdx.x)>>5; if(w>=Nn) return;
    int lane=threadIdx.x&31;
    const float2* X2=(const float2*)X;
    int s=rp[w], e=rp[w+1];
    float2 A=make_float2(0.f,0.f), B=A;
    int i=s;
    for(; i+1<e; i+=2){
        int c0=col[i], c1=col[i+1];
        float v0=val[i], v1=val[i+1];
        float2 x0=X2[(long)c0*32+lane];
        float2 x1=X2[(long)c1*32+lane];
        A.x+=v0*x0.x; A.y+=v0*x0.y;
        B.x+=v1*x1.x; B.y+=v1*x1.y;
    }
    if(i<e){
        int c=col[i]; float v=val[i];
        float2 x=X2[(long)c*32+lane];
        A.x+=v*x.x; A.y+=v*x.y;
    }
    A.x=fmaxf(A.x+B.x,0.f); A.y=fmaxf(A.y+B.y,0.f);
    ((float2*)Y)[(long)w*32+lane]=A;
}

__global__ void k_spmm16(const int* __restrict__ rp, const int* __restrict__ col,
                         const float* __restrict__ val, const float* __restrict__ X,
                         float* __restrict__ Y){
    int row=blockIdx.x*16+threadIdx.y; int j=threadIdx.x;
    if(row>=Nn) return;
    float acc=0.f;
    for(int i=rp[row];i<rp[row+1];i++) acc+=val[i]*X[(long)col[i]*16+j];
    Y[(long)row*16+j]=acc;
}

__global__ void k_spmm16f(const int* __restrict__ rp1, const int* __restrict__ col1,
                          const float* __restrict__ val1,
                          const int* __restrict__ rp2, const int* __restrict__ col2,
                          const float* __restrict__ val2,
                          const float* __restrict__ b1, const float* __restrict__ b2,
                          const float* __restrict__ X, float* __restrict__ Y){
    int row=blockIdx.x*16+threadIdx.y; int j=threadIdx.x;
    if(row>=Nn) return;
    float a1=0.f, a2=0.f;
    for(int i=rp1[row];i<rp1[row+1];i++) a1+=val1[i]*X[(long)col1[i]*16+j];
    for(int i=rp2[row];i<rp2[row+1];i++) a2+=val2[i]*X[(long)col2[i]*16+j];
    Y[(long)row*16+j]=b1[row]*a1+b2[row]*a2;
}

// ------------- gen_view helpers -------------
__global__ void k_nodedot(const float* __restrict__ emb, const float* __restrict__ Wm,
                          float* __restrict__ dr, float* __restrict__ dc){
    int node=(blockIdx.x*blockDim.x+threadIdx.x)>>5; if(node>=Nn) return;
    int lane=threadIdx.x&31;
    float2 e=((const float2*)(emb+(long)node*64))[lane];
    float2 wr=((const float2*)Wm)[lane];
    float2 wc=((const float2*)Wm)[lane+32];
    float a=e.x*wr.x+e.y*wr.y;
    float b=e.x*wc.x+e.y*wc.y;
#pragma unroll
    for(int o=16;o;o>>=1){
        a+=__shfl_xor_sync(0xffffffffu,a,o);
        b+=__shfl_xor_sync(0xffffffffu,b,o);
    }
    if(lane==0){dr[node]=a; dc[node]=b;}
}

__global__ void k_gensoftmax(const int* __restrict__ rp, const int* __restrict__ col,
                             float* __restrict__ val, const float* __restrict__ dr,
                             const float* __restrict__ dc, const float* __restrict__ bm,
                             float com){
    int row=(blockIdx.x*blockDim.x+threadIdx.x)>>5; if(row>=Nn) return;
    int lane=threadIdx.x&31;
    int s=rp[row], e=rp[row+1];
    if(s==e) return;
    float base=dr[row]+bm[0];
    float m=-3.4e38f;
    for(int i=s+lane;i<e;i+=32) m=fmaxf(m, base+dc[col[i]]);
#pragma unroll
    for(int o=16;o;o>>=1) m=fmaxf(m,__shfl_xor_sync(0xffffffffu,m,o));
    float ss=0.f;
    for(int i=s+lane;i<e;i+=32) ss+=__expf(base+dc[col[i]]-m);
#pragma unroll
    for(int o=16;o;o>>=1) ss+=__shfl_xor_sync(0xffffffffu,ss,o);
    float inv=com/ss;
    for(int i=s+lane;i<e;i+=32) val[i]+=__expf(base+dc[col[i]]-m)*inv;
}

// ------------- 16-class softmax + logits + top2 weight -------------
__global__ void k_softmax_w(const float* __restrict__ C, float* __restrict__ lg,
                            float* __restrict__ w){
    int node=blockIdx.x*blockDim.x+threadIdx.x; if(node>=Nn) return;
    float x[16];
    const float4* p=(const float4*)(C+(long)node*16);
#pragma unroll
    for(int q=0;q<4;q++){float4 t=p[q]; x[4*q]=t.x; x[4*q+1]=t.y; x[4*q+2]=t.z; x[4*q+3]=t.w;}
    float m=x[0];
#pragma unroll
    for(int j=1;j<16;j++) m=fmaxf(m,x[j]);
    float s=0.f;
#pragma unroll
    for(int j=0;j<16;j++){x[j]=__expf(x[j]-m); s+=x[j];}
    float inv=1.f/s;
    float fir=0.f, sec=0.f;
#pragma unroll
    for(int j=0;j<16;j++){
        float pr=x[j]*inv;
        lg[(long)node*16+j]=logf(pr+EPSF);
        if(pr>fir){sec=fir; fir=pr;} else if(pr>sec) sec=pr;
    }
    if(w) w[node]=sqrtf((fir+EPSF)*(fir-sec+EPSF));
}

__global__ void k_bal(const float* __restrict__ w1, const float* __restrict__ w2,
                      float* __restrict__ b1, float* __restrict__ b2){
    int i=blockIdx.x*blockDim.x+threadIdx.x; if(i>=Nn) return;
    float a=w1[i], b=w2[i], inv=1.f/(a+b);
    b1[i]=a*inv; b2[i]=b*inv;
}

// normalize rows in place (3*Bb rows of 128)
__global__ void k_normrows(float* __restrict__ E){
    int row=(blockIdx.x*blockDim.x+threadIdx.x)>>5; if(row>=3*Bb) return;
    int lane=threadIdx.x&31;
    float4* p=(float4*)(E+(long)row*128);
    float4 v=p[lane];
    float s=v.x*v.x+v.y*v.y+v.z*v.z+v.w*v.w;
#pragma unroll
    for(int o=16;o;o>>=1) s+=__shfl_xor_sync(0xffffffffu,s,o);
    float inv=rsqrtf(s);
    v.x*=inv; v.y*=inv; v.z*=inv; v.w*=inv;
    p[lane]=v;
}

// ------------- contrast: 128x128 tiles, z=pair; rows pre-normalized -------------
__global__ __launch_bounds__(256) void k_contrast3(
        const float* __restrict__ E, float* RS, float* CS, float* DG){
    __shared__ __align__(16) float sA[16*130];
    __shared__ __align__(16) float sW[16*128];
    __shared__ float sRS[128], sCS[128];
    int pair=blockIdx.z;
    const float* z1; const float* z2;
    if(pair==0){ z1=E;            z2=E+(long)Bb*128; }
    else if(pair==1){ z1=E;       z2=E+(long)2*Bb*128; }
    else { z1=E+(long)Bb*128;     z2=E+(long)2*Bb*128; }
    float* rs=RS+(long)pair*Bb;
    float* cs=CS+(long)pair*Bb;
    float* dg=DG+(long)pair*Bb;

    int tid=threadIdx.x, tx=tid&15, ty=tid>>4;
    int br=blockIdx.y*128, bc=blockIdx.x*128;
    u64 acc[8][4];
#pragma unroll
    for(int i=0;i<8;i++){acc[i][0]=0;acc[i][1]=0;acc[i][2]=0;acc[i][3]=0;}
    int ra=tid>>2, fa=(tid&3)<<2;
    int cw=(tid&31)<<2, kw=tid>>5;

    for(int k0=0;k0<128;k0+=16){
#pragma unroll
        for(int h=0;h<2;h++){
            int r=ra+h*64;
            float4 v=*(const float4*)(z1+(long)(br+r)*128+k0+fa);
            sA[(fa+0)*130+r]=v.x; sA[(fa+1)*130+r]=v.y;
            sA[(fa+2)*130+r]=v.z; sA[(fa+3)*130+r]=v.w;
        }
#pragma unroll
        for(int h=0;h<2;h++){
            int kk=kw+h*8;
            // z2 tile transposed: sW[kk][c] = z2[(bc+c)][k0+kk]; load 4 cols' element kk? 
            // simpler: each thread loads float4 along K of one z2 row and scatters.
            // reuse A-style loader: rows of z2 are the "columns" here.
            int c=ra+h*64;
            float4 v=*(const float4*)(z2+(long)(bc+c)*128+k0+fa);
            if(h==0&&kk==kw){} // (kept structure; scatter below)
            sW[(fa+0)*128+c]=v.x; sW[(fa+1)*128+c]=v.y;
            sW[(fa+2)*128+c]=v.z; sW[(fa+3)*128+c]=v.w;
        }
        __syncthreads();
#pragma unroll
        for(int kk=0;kk<16;kk++){
            const float* sak=&sA[kk*130+ty*8];
            float2 a01=*(const float2*)(sak);
            float2 a23=*(const float2*)(sak+2);
            float2 a45=*(const float2*)(sak+4);
            float2 a67=*(const float2*)(sak+6);
            const ulonglong2* bw=(const ulonglong2*)&sW[kk*128+tx*8];
            ulonglong2 bA=bw[0], bB=bw[1];
            u64 s0=pk2(a01.x,a01.x), s1=pk2(a01.y,a01.y);
            u64 s2=pk2(a23.x,a23.x), s3=pk2(a23.y,a23.y);
            u64 s4=pk2(a45.x,a45.x), s5=pk2(a45.y,a45.y);
            u64 s6=pk2(a67.x,a67.x), s7=pk2(a67.y,a67.y);
            fma2(acc[0][0],s0,bA.x); fma2(acc[0][1],s0,bA.y); fma2(acc[0][2],s0,bB.x); fma2(acc[0][3],s0,bB.y);
            fma2(acc[1][0],s1,bA.x); fma2(acc[1][1],s1,bA.y); fma2(acc[1][2],s1,bB.x); fma2(acc[1][3],s1,bB.y);
            fma2(acc[2][0],s2,bA.x); fma2(acc[2][1],s2,bA.y); fma2(acc[2][2],s2,bB.x); fma2(acc[2][3],s2,bB.y);
            fma2(acc[3][0],s3,bA.x); fma2(acc[3][1],s3,bA.y); fma2(acc[3][2],s3,bB.x); fma2(acc[3][3],s3,bB.y);
            fma2(acc[4][0],s4,bA.x); fma2(acc[4][1],s4,bA.y); fma2(acc[4][2],s4,bB.x); fma2(acc[4][3],s4,bB.y);
            fma2(acc[5][0],s5,bA.x); fma2(acc[5][1],s5,bA.y); fma2(acc[5][2],s5,bB.x); fma2(acc[5][3],s5,bB.y);
            fma2(acc[6][0],s6,bA.x); fma2(acc[6][1],s6,bA.y); fma2(acc[6][2],s6,bB.x); fma2(acc[6][3],s6,bB.y);
            fma2(acc[7][0],s7,bA.x); fma2(acc[7][1],s7,bA.y); fma2(acc[7][2],s7,bB.x); fma2(acc[7][3],s7,bB.y);
        }
        __syncthreads();
    }
    if(tid<128){sRS[tid]=0.f; sCS[tid]=0.f;}
    __syncthreads();
    float rsum[8]={0,0,0,0,0,0,0,0}, csum[8]={0,0,0,0,0,0,0,0};
#pragma unroll
    for(int i=0;i<8;i++){
        float vv[8];
#pragma unroll
        for(int p=0;p<4;p++){float2 t=up2(acc[i][p]); vv[2*p]=t.x; vv[2*p+1]=t.y;}
        int gr=br+ty*8+i;
#pragma unroll
        for(int j=0;j<8;j++){
            float e=__expf(2.0f*vv[j]);
            rsum[i]+=e; csum[j]+=e;
            if(gr==bc+tx*8+j) dg[gr]=e;
        }
    }
#pragma unroll
    for(int i=0;i<8;i++) atomicAdd(&sRS[ty*8+i], rsum[i]);
#pragma unroll
    for(int j=0;j<8;j++) atomicAdd(&sCS[tx*8+j], csum[j]);
    __syncthreads();
    if(tid<128){atomicAdd(&rs[br+tid], sRS[tid]); atomicAdd(&cs[bc+tid], sCS[tid]);}
}

__global__ void k_creduce3(const float* __restrict__ RS, const float* __restrict__ CS,
                           const float* __restrict__ DG, float* out){
    __shared__ float sh[1024];
    int pair=blockIdx.x;
    const float* rs=RS+(long)pair*Bb;
    const float* cs=CS+(long)pair*Bb;
    const float* dg=DG+(long)pair*Bb;
    int tid=threadIdx.x;
    float a=0.f;
    for(int i=tid;i<Bb;i+=1024){
        a+=-logf(dg[i]/(rs[i]+EPSF)+EPSF);
        a+=-logf(dg[i]/(cs[i]+EPSF)+EPSF);
    }
    sh[tid]=a; __syncthreads();
    for(int d=512;d;d>>=1){ if(tid<d) sh[tid]+=sh[tid+d]; __syncthreads(); }
    if(tid==0) out[pair]=0.5f*sh[0]/(float)Bb;
}

// ------------- host -------------
#define GSA(var) ([]{ void* _p; cudaGetSymbolAddress(&_p, var); return _p; }())

extern "C" void kernel_launch(void* const* d_in, const int* in_sizes, int n_in,
                              void* d_out, int out_size){
    const float* feat  =(const float*)d_in[0];
    const int*   i1    =(const int*)  d_in[1];
    const float* v1    =(const float*)d_in[2];
    const int*   i2    =(const int*)  d_in[3];
    const float* v2    =(const float*)d_in[4];
    const int*   bidx  =(const int*)  d_in[5];
    const float* Wgen1 =(const float*)d_in[6];
    const float* Wm1   =(const float*)d_in[7];
    const float* bm1   =(const float*)d_in[8];
    const float* Wgen2 =(const float*)d_in[9];
    const float* Wm2   =(const float*)d_in[10];
    const float* bm2   =(const float*)d_in[11];
    const float* W1v1  =(const float*)d_in[12];
    const float* W2v1  =(const float*)d_in[13];
    const float* W1v2  =(const float*)d_in[14];
    const float* W2v2  =(const float*)d_in[15];
    const float* W1v   =(const float*)d_in[16];
    const float* W2v   =(const float*)d_in[17];
    const float* Wg    =(const float*)d_in[18];
    const float* Wg1   =(const float*)d_in[19];
    const float* Wg2   =(const float*)d_in[20];
    const float* Wp1   =(const float*)d_in[21];
    const float* bp1   =(const float*)d_in[22];
    const float* Wp2   =(const float*)d_in[23];
    const float* bp2   =(const float*)d_in[24];
    float* out=(float*)d_out;

    float* XW  =(float*)GSA(g_XW);   float* H   =(float*)GSA(g_H);
    float* emb =(float*)GSA(g_emb);  float* S16 =(float*)GSA(g_S16);
    float* C16 =(float*)GSA(g_C16);
    float* dr=(float*)GSA(g_dr), *dc=(float*)GSA(g_dc);
    float* w1=(float*)GSA(g_w1), *w2=(float*)GSA(g_w2);
    float* b1=(float*)GSA(g_b1), *b2=(float*)GSA(g_b2);
    int* cnt1=(int*)GSA(g_cnt1), *cnt1b=(int*)GSA(g_cnt1b);
    int* cnt2=(int*)GSA(g_cnt2), *cnt2b=(int*)GSA(g_cnt2b);
    int* cur=(int*)GSA(g_cur);
    int* rp1d=(int*)GSA(g_rp1d), *rp2d=(int*)GSA(g_rp2d);
    int* rp1s=(int*)GSA(g_rp1s), *rp2s=(int*)GSA(g_rp2s);
    int* col1d=(int*)GSA(g_col1d);   float* val1d=(float*)GSA(g_val1d);
    int* col2d=(int*)GSA(g_col2d);   float* val2d=(float*)GSA(g_val2d);
    int* col1s=(int*)GSA(g_col1s);   float* val1s=(float*)GSA(g_val1s);
    int* col2s=(int*)GSA(g_col2s);   float* val2s=(float*)GSA(g_val2s);
    float* Z=(float*)GSA(g_Z), *T=(float*)GSA(g_T), *E=(float*)GSA(g_E);
    float* RS=(float*)GSA(g_RS), *CS=(float*)GSA(g_CS), *DG=(float*)GSA(g_DG);

    const int TB=256;
    int gN  =(Nn+TB-1)/TB;
    int gE  =(Ee+TB-1)/TB;
    int gW  =(Nn*32+TB-1)/TB;
    int gWB =(Bb*32+TB-1)/TB;
    int gW3B=(3*Bb*32+TB-1)/TB;
    dim3 b16(16,16); int g16=(Nn+15)/16;

    auto gemm=[&](const float* A,const float* W,const float* bias,float* C,
                  int n,int K,int M,int act){
        dim3 grid(1,(n+127)/128);
        k_gemm128<<<grid,256>>>(A,W,bias,C,n,K,M,act);
    };

    // ---- CSR build ----
    k_zero4<<<gN,TB>>>(cnt1,cnt1b,cnt2,cnt2b,Nn);
    k_count2<<<gE,TB>>>(i1,i2,cnt1,cnt1b,cnt2,cnt2b);
    k_scan4<<<4,1024>>>(cnt1,rp1d,cnt1b,rp1s,cnt2,rp2d,cnt2b,rp2s,Nn);
    k_copy_i<<<gN,TB>>>(rp1d,cur,Nn);
    k_scatter_dir<<<gE,TB>>>(i1,v1,cur,col1d,val1d);
    k_copy_i<<<gN,TB>>>(rp2d,cur,Nn);
    k_scatter_dir<<<gE,TB>>>(i2,v2,cur,col2d,val2d);

    // ---- gen_view ----
    gemm(feat,Wgen1,nullptr,XW,Nn,256,64,0);
    k_spmm64<<<gW,TB>>>(rp1d,col1d,val1d,XW,emb);
    k_nodedot<<<gW,TB>>>(emb,Wm1,dr,dc);
    k_gensoftmax<<<gW,TB>>>(rp1d,col1d,val1d,dr,dc,bm1,0.5f);
    gemm(feat,Wgen2,nullptr,XW,Nn,256,64,0);
    k_spmm64<<<gW,TB>>>(rp2d,col2d,val2d,XW,emb);
    k_nodedot<<<gW,TB>>>(emb,Wm2,dr,dc);
    k_gensoftmax<<<gW,TB>>>(rp2d,col2d,val2d,dr,dc,bm2,0.5f);

    // ---- symmetrize ----
    k_copy_i<<<gN,TB>>>(rp1s,cur,Nn);
    k_scatter_sym<<<gN,TB>>>(rp1d,col1d,val1d,cur,col1s,val1s);
    k_copy_i<<<gN,TB>>>(rp2s,cur,Nn);
    k_scatter_sym<<<gN,TB>>>(rp2d,col2d,val2d,cur,col2s,val2s);

    // ---- classifier v1 ----
    gemm(feat,W1v1,nullptr,XW,Nn,256,128,0);
    k_spmm128<<<gW,TB>>>(rp1s,col1s,val1s,XW,H);
    k_gemm16<<<g16,b16>>>(H,W2v1,S16,Nn);
    k_spmm16<<<g16,b16>>>(rp1s,col1s,val1s,S16,C16);
    k_softmax_w<<<gN,TB>>>(C16,out+(long)16*Nn,w1);
    // ---- classifier v2 ----
    gemm(feat,W1v2,nullptr,XW,Nn,256,128,0);
    k_spmm128<<<gW,TB>>>(rp2s,col2s,val2s,XW,H);
    k_gemm16<<<g16,b16>>>(H,W2v2,S16,Nn);
    k_spmm16<<<g16,b16>>>(rp2s,col2s,val2s,S16,C16);
    k_softmax_w<<<gN,TB>>>(C16,out+(long)32*Nn,w2);

    k_bal<<<gN,TB>>>(w1,w2,b1,b2);

    // ---- fused classifier ----
    gemm(feat,W1v,nullptr,XW,Nn,256,128,0);
    k_spmm128f<<<gW,TB>>>(rp1s,col1s,val1s,rp2s,col2s,val2s,b1,b2,XW,H);
    k_gemm16<<<g16,b16>>>(H,W2v,S16,Nn);
    k_spmm16f<<<g16,b16>>>(rp1s,col1s,val1s,rp2s,col2s,val2s,b1,b2,S16,C16);
    k_softmax_w<<<gN,TB>>>(C16,out,nullptr);

    // ---- MI embeddings: spmm only for batched rows, batched projections ----
    gemm(feat,Wg,nullptr,XW,Nn,256,128,0);
    k_spmm128fg<<<gWB,TB>>>(bidx,rp1s,col1s,val1s,rp2s,col2s,val2s,b1,b2,XW,Z);
    gemm(feat,Wg1,nullptr,XW,Nn,256,128,0);
    k_spmm128g<<<gWB,TB>>>(bidx,rp1s,col1s,val1s,XW,Z+(long)Bb*128);
    gemm(feat,Wg2,nullptr,XW,Nn,256,128,0);
    k_spmm128g<<<gWB,TB>>>(bidx,rp2s,col2s,val2s,XW,Z+(long)2*Bb*128);

    gemm(Z,Wp1,bp1,T,3*Bb,128,128,1);   // ELU
    gemm(T,Wp2,bp2,E,3*Bb,128,128,0);
    k_normrows<<<gW3B,TB>>>(E);

    // ---- contrasts ----
    int gB3=(3*Bb+TB-1)/TB;
    k_zero_f2<<<gB3,TB>>>(RS,CS,3*Bb);
    dim3 cg(32,32,3);
    k_contrast3<<<cg,256>>>(E,RS,CS,DG);
    k_creduce3<<<3,1024>>>(RS,CS,DG,out+(long)48*Nn);
}

// round 5
// speedup vs baseline: 1.3817x; 1.0265x over previous
#include <cuda_runtime.h>
#include <math.h>

#define Nn 30000
#define Ee 480000
#define Bb 4096
#define EPSF 1e-8f

typedef unsigned long long u64;
__device__ __forceinline__ u64 pk2(float x,float y){u64 r;asm("mov.b64 %0,{%1,%2};":"=l"(r):"f"(x),"f"(y));return r;}
__device__ __forceinline__ float2 up2(u64 v){float2 r;asm("mov.b64 {%0,%1},%2;":"=f"(r.x),"=f"(r.y):"l"(v));return r;}
__device__ __forceinline__ void fma2(u64&d,u64 a,u64 b){asm("fma.rn.f32x2 %0,%1,%2,%0;":"+l"(d):"l"(a),"l"(b));}

// ------------- device scratch -------------
__device__ float g_Wp[256*896];
__device__ float g_X64a[Nn*64], g_X64b[Nn*64];
__device__ float g_XC1[Nn*128], g_XC2[Nn*128], g_XCf[Nn*128];
__device__ float g_XG[Nn*128], g_XG1[Nn*128], g_XG2[Nn*128];
__device__ float g_H[Nn*128];
__device__ float g_emb[Nn*64];
__device__ float g_S16[Nn*16];
__device__ float g_C16[Nn*16];
__device__ float g_dr[Nn], g_dc[Nn], g_w1[Nn], g_w2[Nn], g_b1[Nn], g_b2[Nn];
__device__ int   g_cnt1[Nn], g_cnt1b[Nn], g_cnt2[Nn], g_cnt2b[Nn];
__device__ int   g_cur1d[Nn], g_cur2d[Nn], g_cur1s[Nn], g_cur2s[Nn];
__device__ int   g_rp1d[Nn+1], g_rp2d[Nn+1], g_rp1s[Nn+1], g_rp2s[Nn+1];
__device__ int   g_col1d[Ee];   __device__ float g_val1d[Ee];
__device__ int   g_col2d[Ee];   __device__ float g_val2d[Ee];
__device__ int   g_col1s[2*Ee]; __device__ float g_val1s[2*Ee];
__device__ int   g_col2s[2*Ee]; __device__ float g_val2s[2*Ee];
__device__ float g_Z[3*Bb*128], g_T[3*Bb*128], g_E[3*Bb*128];
__device__ float g_RS[3*Bb], g_CS[3*Bb], g_DG[3*Bb];

// ------------- pack weights: [256 x 896] = Wgen1|Wgen2|W1v1|W1v2|W1v|Wg|Wg1|Wg2 -------------
__global__ void k_pack(const float* __restrict__ wg1, const float* __restrict__ wg2,
                       const float* __restrict__ a, const float* __restrict__ b,
                       const float* __restrict__ c, const float* __restrict__ d,
                       const float* __restrict__ e, const float* __restrict__ f,
                       float* __restrict__ Wp){
    int i=blockIdx.x*blockDim.x+threadIdx.x; if(i>=256*896) return;
    int row=i/896, col=i%896;
    float v;
    if(col<64) v=wg1[row*64+col];
    else if(col<128) v=wg2[row*64+col-64];
    else{
        int blk=(col-128)>>7, lc=(col-128)&127;
        const float* s;
        switch(blk){case 0:s=a;break;case 1:s=b;break;case 2:s=c;break;
                    case 3:s=d;break;case 4:s=e;break;default:s=f;break;}
        v=s[row*128+lc];
    }
    Wp[i]=v;
}

// ------------- small utils -------------
__global__ void k_zero4(int* a,int* b,int* c,int* d,int n){
    int i=blockIdx.x*blockDim.x+threadIdx.x; if(i<n){a[i]=0;b[i]=0;c[i]=0;d[i]=0;} }
__global__ void k_zero_f2(float* a, float* b, int n){
    int i=blockIdx.x*blockDim.x+threadIdx.x; if(i<n){a[i]=0.f;b[i]=0.f;} }

__global__ void k_count2(const int* __restrict__ ind1, const int* __restrict__ ind2,
                         int* cd1, int* cs1, int* cd2, int* cs2){
    int e=blockIdx.x*blockDim.x+threadIdx.x; if(e>=Ee) return;
    int r1=ind1[e], c1=ind1[Ee+e];
    atomicAdd(&cd1[r1],1); atomicAdd(&cs1[r1],1); atomicAdd(&cs1[c1],1);
    int r2=ind2[e], c2=ind2[Ee+e];
    atomicAdd(&cd2[r2],1); atomicAdd(&cs2[r2],1); atomicAdd(&cs2[c2],1);
}

// 4 independent scans; also writes cur copies
__global__ void k_scan4(const int* c0,int* r0,int* u0,const int* c1,int* r1,int* u1,
                        const int* c2,int* r2,int* u2,const int* c3,int* r3,int* u3,int n){
    const int* cnt; int* rp; int* cu;
    switch(blockIdx.x){
        case 0: cnt=c0; rp=r0; cu=u0; break;
        case 1: cnt=c1; rp=r1; cu=u1; break;
        case 2: cnt=c2; rp=r2; cu=u2; break;
        default:cnt=c3; rp=r3; cu=u3; break;
    }
    const int T=1024;
    int tid=threadIdx.x;
    int chunk=(n+T-1)/T;
    int s=tid*chunk; if(s>n) s=n;
    int e=s+chunk;   if(e>n) e=n;
    int sum=0;
    for(int i=s;i<e;i++) sum+=cnt[i];
    __shared__ int wsum[32];
    int lane=tid&31, wid=tid>>5;
    int v=sum;
#pragma unroll
    for(int o=1;o<32;o<<=1){int t=__shfl_up_sync(0xffffffffu,v,o); if(lane>=o) v+=t;}
    if(lane==31) wsum[wid]=v;
    __syncthreads();
    if(wid==0){
        int w=wsum[lane];
#pragma unroll
        for(int o=1;o<32;o<<=1){int t=__shfl_up_sync(0xffffffffu,w,o); if(lane>=o) w+=t;}
        wsum[lane]=w;
    }
    __syncthreads();
    int excl=v-sum+(wid?wsum[wid-1]:0);
    int run=excl;
    for(int i=s;i<e;i++){ rp[i]=run; cu[i]=run; run+=cnt[i]; }
    if(tid==T-1) rp[n]=run;
}

__global__ void k_scatter_dir(const int* __restrict__ ind, const float* __restrict__ vals,
                              int* cur, int* __restrict__ col, float* __restrict__ val){
    int e=blockIdx.x*blockDim.x+threadIdx.x; if(e>=Ee) return;
    int r=ind[e], c=ind[Ee+e];
    int p=atomicAdd(&cur[r],1);
    col[p]=c; val[p]=vals[e];
}

__global__ void k_scatter_sym(const int* __restrict__ rpd, const int* __restrict__ cold,
                              const float* __restrict__ vald, int* cur,
                              int* __restrict__ cols, float* __restrict__ vals){
    int r=blockIdx.x*blockDim.x+threadIdx.x; if(r>=Nn) return;
    for(int i=rpd[r];i<rpd[r+1];i++){
        int c=cold[i]; float v=vald[i];
        int p=atomicAdd(&cur[r],1); cols[p]=c; vals[p]=v;
        int q=atomicAdd(&cur[c],1); cols[q]=r; vals[q]=v;
    }
}

// ------------- inner-product macro (8x8, f32x2) -------------
#define MMA_KK(sak, sWk) do{ \
    float2 a01=*(const float2*)(sak); \
    float2 a23=*(const float2*)((sak)+2); \
    float2 a45=*(const float2*)((sak)+4); \
    float2 a67=*(const float2*)((sak)+6); \
    const ulonglong2* bw=(const ulonglong2*)(sWk); \
    ulonglong2 bA=bw[0], bB=bw[1]; \
    u64 s0=pk2(a01.x,a01.x), s1=pk2(a01.y,a01.y); \
    u64 s2=pk2(a23.x,a23.x), s3=pk2(a23.y,a23.y); \
    u64 s4=pk2(a45.x,a45.x), s5=pk2(a45.y,a45.y); \
    u64 s6=pk2(a67.x,a67.x), s7=pk2(a67.y,a67.y); \
    fma2(acc[0][0],s0,bA.x); fma2(acc[0][1],s0,bA.y); fma2(acc[0][2],s0,bB.x); fma2(acc[0][3],s0,bB.y); \
    fma2(acc[1][0],s1,bA.x); fma2(acc[1][1],s1,bA.y); fma2(acc[1][2],s1,bB.x); fma2(acc[1][3],s1,bB.y); \
    fma2(acc[2][0],s2,bA.x); fma2(acc[2][1],s2,bA.y); fma2(acc[2][2],s2,bB.x); fma2(acc[2][3],s2,bB.y); \
    fma2(acc[3][0],s3,bA.x); fma2(acc[3][1],s3,bA.y); fma2(acc[3][2],s3,bB.x); fma2(acc[3][3],s3,bB.y); \
    fma2(acc[4][0],s4,bA.x); fma2(acc[4][1],s4,bA.y); fma2(acc[4][2],s4,bB.x); fma2(acc[4][3],s4,bB.y); \
    fma2(acc[5][0],s5,bA.x); fma2(acc[5][1],s5,bA.y); fma2(acc[5][2],s5,bB.x); fma2(acc[5][3],s5,bB.y); \
    fma2(acc[6][0],s6,bA.x); fma2(acc[6][1],s6,bA.y); fma2(acc[6][2],s6,bB.x); fma2(acc[6][3],s6,bB.y); \
    fma2(acc[7][0],s7,bA.x); fma2(acc[7][1],s7,bA.y); fma2(acc[7][2],s7,bB.x); fma2(acc[7][3],s7,bB.y); \
}while(0)

// ------------- packed GEMM: XWall = feat[30000x256] @ Wp[256x896], scattered outputs -------------
__global__ __launch_bounds__(256) void k_gemmP(
        const float* __restrict__ A, const float* __restrict__ Wp,
        float* __restrict__ e1, float* __restrict__ e2,
        float* __restrict__ x0, float* __restrict__ x1, float* __restrict__ x2,
        float* __restrict__ x3, float* __restrict__ x4, float* __restrict__ x5){
    __shared__ __align__(16) float sA[32*130];
    __shared__ __align__(16) float sW[32*128];
    int tid=threadIdx.x, tx=tid&15, ty=tid>>4;
    int bx=blockIdx.x;
    int br=blockIdx.y*128;
    u64 acc[8][4];
#pragma unroll
    for(int i=0;i<8;i++){acc[i][0]=0;acc[i][1]=0;acc[i][2]=0;acc[i][3]=0;}
    int ra=tid>>3, fa=(tid&7)<<2;       // A loader: 32 rows/pass x 4 passes, k chunk fa
    int cw=(tid&31)<<2, kw=tid>>5;      // W loader

    for(int k0=0;k0<256;k0+=32){
#pragma unroll
        for(int h=0;h<4;h++){
            int r=ra+h*32, gr=br+r;
            float4 v=make_float4(0.f,0.f,0.f,0.f);
            if(gr<Nn) v=*(const float4*)(A+(long)gr*256+k0+fa);
            sA[(fa+0)*130+r]=v.x; sA[(fa+1)*130+r]=v.y;
            sA[(fa+2)*130+r]=v.z; sA[(fa+3)*130+r]=v.w;
        }
#pragma unroll
        for(int h=0;h<4;h++){
            int kk=kw+h*8;
            float4 v=*(const float4*)(Wp+(long)(k0+kk)*896+bx*128+cw);
            *(float4*)&sW[kk*128+cw]=v;
        }
        __syncthreads();
#pragma unroll
        for(int kk=0;kk<32;kk++){
            MMA_KK(&sA[kk*130+ty*8], &sW[kk*128+tx*8]);
        }
        __syncthreads();
    }
    // scatter outputs
    float* dst; int w; int c0;
    if(bx==0){
        if(tx<8){ dst=e1; w=64; c0=tx*8; } else { dst=e2; w=64; c0=(tx-8)*8; }
    } else {
        switch(bx-1){case 0:dst=x0;break;case 1:dst=x1;break;case 2:dst=x2;break;
                     case 3:dst=x3;break;case 4:dst=x4;break;default:dst=x5;break;}
        w=128; c0=tx*8;
    }
#pragma unroll
    for(int i=0;i<8;i++){
        int gr=br+ty*8+i; if(gr>=Nn) continue;
        float vv[8];
#pragma unroll
        for(int p=0;p<4;p++){float2 t=up2(acc[i][p]); vv[2*p]=t.x; vv[2*p+1]=t.y;}
        float* cp=dst+(long)gr*w+c0;
        *(float4*)cp=make_float4(vv[0],vv[1],vv[2],vv[3]);
        *(float4*)(cp+4)=make_float4(vv[4],vv[5],vv[6],vv[7]);
    }
}

// ------------- generic GEMM (proj): C[n,128]=A[n,K]@W[K,128] (+bias, act 0=none 1=elu) -------------
__global__ __launch_bounds__(256) void k_gemm128(
        const float* __restrict__ A, const float* __restrict__ W,
        const float* __restrict__ bias, float* __restrict__ C,
        int n, int K, int act){
    __shared__ __align__(16) float sA[32*130];
    __shared__ __align__(16) float sW[32*128];
    int tid=threadIdx.x, tx=tid&15, ty=tid>>4;
    int br=blockIdx.y*128;
    u64 acc[8][4];
#pragma unroll
    for(int i=0;i<8;i++){acc[i][0]=0;acc[i][1]=0;acc[i][2]=0;acc[i][3]=0;}
    int ra=tid>>3, fa=(tid&7)<<2;
    int cw=(tid&31)<<2, kw=tid>>5;

    for(int k0=0;k0<K;k0+=32){
#pragma unroll
        for(int h=0;h<4;h++){
            int r=ra+h*32, gr=br+r;
            float4 v=make_float4(0.f,0.f,0.f,0.f);
            if(gr<n) v=*(const float4*)(A+(long)gr*K+k0+fa);
            sA[(fa+0)*130+r]=v.x; sA[(fa+1)*130+r]=v.y;
            sA[(fa+2)*130+r]=v.z; sA[(fa+3)*130+r]=v.w;
        }
#pragma unroll
        for(int h=0;h<4;h++){
            int kk=kw+h*8;
            float4 v=*(const float4*)(W+(long)(k0+kk)*128+cw);
            *(float4*)&sW[kk*128+cw]=v;
        }
        __syncthreads();
#pragma unroll
        for(int kk=0;kk<32;kk++){
            MMA_KK(&sA[kk*130+ty*8], &sW[kk*128+tx*8]);
        }
        __syncthreads();
    }
    float bb[8];
#pragma unroll
    for(int q=0;q<8;q++) bb[q]=bias?bias[tx*8+q]:0.f;
#pragma unroll
    for(int i=0;i<8;i++){
        int gr=br+ty*8+i; if(gr>=n) continue;
        float vv[8];
#pragma unroll
        for(int p=0;p<4;p++){float2 t=up2(acc[i][p]); vv[2*p]=t.x; vv[2*p+1]=t.y;}
#pragma unroll
        for(int q=0;q<8;q++){
            float v=vv[q]+bb[q];
            if(act==1) v=(v>0.f)?v:expm1f(v);
            vv[q]=v;
        }
        float* cp=C+(long)gr*128+tx*8;
        *(float4*)cp=make_float4(vv[0],vv[1],vv[2],vv[3]);
        *(float4*)(cp+4)=make_float4(vv[4],vv[5],vv[6],vv[7]);
    }
}

// ------------- GEMM M=16 (W2 in smem) -------------
__global__ void k_gemm16(const float* __restrict__ H, const float* __restrict__ W2,
                         float* __restrict__ C, int n){
    __shared__ float sW[128*16];
    int tid=threadIdx.y*16+threadIdx.x;
#pragma unroll
    for(int q=0;q<2;q++) ((float4*)sW)[tid*2+q]=((const float4*)W2)[tid*2+q];
    __syncthreads();
    int r=blockIdx.x*16+threadIdx.y, j=threadIdx.x;
    if(r>=n) return;
    const float4* H4=(const float4*)(H+(long)r*128);
    float acc=0.f;
#pragma unroll
    for(int k4=0;k4<32;k4++){
        float4 h=H4[k4];
        acc+=h.x*sW[(k4*4+0)*16+j];
        acc+=h.y*sW[(k4*4+1)*16+j];
        acc+=h.z*sW[(k4*4+2)*16+j];
        acc+=h.w*sW[(k4*4+3)*16+j];
    }
    C[(long)r*16+j]=acc;
}

// ------------- SpMM (warp per row, 2-way unrolled) -------------
__device__ __forceinline__ float4 spmm_row128(const int* __restrict__ rp,
        const int* __restrict__ col, const float* __restrict__ val,
        const float4* __restrict__ X4, int w, int lane){
    int s=rp[w], e=rp[w+1];
    float4 A=make_float4(0.f,0.f,0.f,0.f), B=A;
    int i=s;
    for(; i+1<e; i+=2){
        int c0=col[i], c1=col[i+1];
        float v0=val[i], v1=val[i+1];
        float4 x0=X4[(long)c0*32+lane];
        float4 x1=X4[(long)c1*32+lane];
        A.x+=v0*x0.x; A.y+=v0*x0.y; A.z+=v0*x0.z; A.w+=v0*x0.w;
        B.x+=v1*x1.x; B.y+=v1*x1.y; B.z+=v1*x1.z; B.w+=v1*x1.w;
    }
    if(i<e){
        int c=col[i]; float v=val[i];
        float4 x=X4[(long)c*32+lane];
        A.x+=v*x.x; A.y+=v*x.y; A.z+=v*x.z; A.w+=v*x.w;
    }
    A.x+=B.x; A.y+=B.y; A.z+=B.z; A.w+=B.w;
    return A;
}

__global__ void k_spmm128(const int* __restrict__ rp, const int* __restrict__ col,
                          const float* __restrict__ val, const float* __restrict__ X,
                          float* __restrict__ Y){
    int w=(blockIdx.x*blockDim.x+threadIdx.x)>>5; if(w>=Nn) return;
    int lane=threadIdx.x&31;
    float4 a=spmm_row128(rp,col,val,(const float4*)X,w,lane);
    a.x=fmaxf(a.x,0.f); a.y=fmaxf(a.y,0.f); a.z=fmaxf(a.z,0.f); a.w=fmaxf(a.w,0.f);
    ((float4*)Y)[(long)w*32+lane]=a;
}

__global__ void k_spmm128f(const int* __restrict__ rp1, const int* __restrict__ col1,
                           const float* __restrict__ val1,
                           const int* __restrict__ rp2, const int* __restrict__ col2,
                           const float* __restrict__ val2,
                           const float* __restrict__ b1, const float* __restrict__ b2,
                           const float* __restrict__ X, float* __restrict__ Y){
    int w=(blockIdx.x*blockDim.x+threadIdx.x)>>5; if(w>=Nn) return;
    int lane=threadIdx.x&31;
    float4 a1=spmm_row128(rp1,col1,val1,(const float4*)X,w,lane);
    float4 a2=spmm_row128(rp2,col2,val2,(const float4*)X,w,lane);
    float f1=b1[w], f2=b2[w];
    float4 r;
    r.x=fmaxf(f1*a1.x+f2*a2.x,0.f); r.y=fmaxf(f1*a1.y+f2*a2.y,0.f);
    r.z=fmaxf(f1*a1.z+f2*a2.z,0.f); r.w=fmaxf(f1*a1.w+f2*a2.w,0.f);
    ((float4*)Y)[(long)w*32+lane]=r;
}

__global__ void k_spmm128g(const int* __restrict__ bidx,
                           const int* __restrict__ rp, const int* __restrict__ col,
                           const float* __restrict__ val, const float* __restrict__ X,
                           float* __restrict__ Z){
    int w=(blockIdx.x*blockDim.x+threadIdx.x)>>5; if(w>=Bb) return;
    int lane=threadIdx.x&31;
    int row=bidx[w];
    float4 a=spmm_row128(rp,col,val,(const float4*)X,row,lane);
    a.x=fmaxf(a.x,0.f); a.y=fmaxf(a.y,0.f); a.z=fmaxf(a.z,0.f); a.w=fmaxf(a.w,0.f);
    ((float4*)Z)[(long)w*32+lane]=a;
}

__global__ void k_spmm128fg(const int* __restrict__ bidx,
                            const int* __restrict__ rp1, const int* __restrict__ col1,
                            const float* __restrict__ val1,
                            const int* __restrict__ rp2, const int* __restrict__ col2,
                            const float* __restrict__ val2,
                            const float* __restrict__ b1, const float* __restrict__ b2,
                            const float* __restrict__ X, float* __restrict__ Z){
    int w=(blockIdx.x*blockDim.x+threadIdx.x)>>5; if(w>=Bb) return;
    int lane=threadIdx.x&31;
    int row=bidx[w];
    float4 a1=spmm_row128(rp1,col1,val1,(const float4*)X,row,lane);
    float4 a2=spmm_row128(rp2,col2,val2,(const float4*)X,row,lane);
    float f1=b1[row], f2=b2[row];
    float4 r;
    r.x=fmaxf(f1*a1.x+f2*a2.x,0.f); r.y=fmaxf(f1*a1.y+f2*a2.y,0.f);
    r.z=fmaxf(f1*a1.z+f2*a2.z,0.f); r.w=fmaxf(f1*a1.w+f2*a2.w,0.f);
    ((float4*)Z)[(long)w*32+lane]=r;
}

__global__ void k_spmm64(const int* __restrict__ rp, const int* __restrict__ col,
                         const float* __restrict__ val, const float* __restrict__ X,
                         float* __restrict__ Y){
    int w=(blockIdx.x*blockDim.x+threadIdx.x)>>5; if(w>=Nn) return;
    int lane=threadIdx.x&31;
    const float2* X2=(const float2*)X;
    int s=rp[w], e=rp[w+1];
    float2 A=make_float2(0.f,0.f), B=A;
    int i=s;
    for(; i+1<e; i+=2){
        int c0=col[i], c1=col[i+1];
        float v0=val[i], v1=val[i+1];
        float2 x0=X2[(long)c0*32+lane];
        float2 x1=X2[(long)c1*32+lane];
        A.x+=v0*x0.x; A.y+=v0*x0.y;
        B.x+=v1*x1.x; B.y+=v1*x1.y;
    }
    if(i<e){
        int c=col[i]; float v=val[i];
        float2 x=X2[(long)c*32+lane];
        A.x+=v*x.x; A.y+=v*x.y;
    }
    A.x=fmaxf(A.x+B.x,0.f); A.y=fmaxf(A.y+B.y,0.f);
    ((float2*)Y)[(long)w*32+lane]=A;
}

__global__ void k_spmm16(const int* __restrict__ rp, const int* __restrict__ col,
                         const float* __restrict__ val, const float* __restrict__ X,
                         float* __restrict__ Y){
    int row=blockIdx.x*16+threadIdx.y; int j=threadIdx.x;
    if(row>=Nn) return;
    float acc=0.f;
    for(int i=rp[row];i<rp[row+1];i++) acc+=val[i]*X[(long)col[i]*16+j];
    Y[(long)row*16+j]=acc;
}

__global__ void k_spmm16f(const int* __restrict__ rp1, const int* __restrict__ col1,
                          const float* __restrict__ val1,
                          const int* __restrict__ rp2, const int* __restrict__ col2,
                          const float* __restrict__ val2,
                          const float* __restrict__ b1, const float* __restrict__ b2,
                          const float* __restrict__ X, float* __restrict__ Y){
    int row=blockIdx.x*16+threadIdx.y; int j=threadIdx.x;
    if(row>=Nn) return;
    float a1=0.f, a2=0.f;
    for(int i=rp1[row];i<rp1[row+1];i++) a1+=val1[i]*X[(long)col1[i]*16+j];
    for(int i=rp2[row];i<rp2[row+1];i++) a2+=val2[i]*X[(long)col2[i]*16+j];
    Y[(long)row*16+j]=b1[row]*a1+b2[row]*a2;
}

// ------------- gen_view helpers -------------
__global__ void k_nodedot(const float* __restrict__ emb, const float* __restrict__ Wm,
                          float* __restrict__ dr, float* __restrict__ dc){
    int node=(blockIdx.x*blockDim.x+threadIdx.x)>>5; if(node>=Nn) return;
    int lane=threadIdx.x&31;
    float2 e=((const float2*)(emb+(long)node*64))[lane];
    float2 wr=((const float2*)Wm)[lane];
    float2 wc=((const float2*)Wm)[lane+32];
    float a=e.x*wr.x+e.y*wr.y;
    float b=e.x*wc.x+e.y*wc.y;
#pragma unroll
    for(int o=16;o;o>>=1){
        a+=__shfl_xor_sync(0xffffffffu,a,o);
        b+=__shfl_xor_sync(0xffffffffu,b,o);
    }
    if(lane==0){dr[node]=a; dc[node]=b;}
}

__global__ void k_gensoftmax(const int* __restrict__ rp, const int* __restrict__ col,
                             float* __restrict__ val, const float* __restrict__ dr,
                             const float* __restrict__ dc, const float* __restrict__ bm,
                             float com){
    int row=(blockIdx.x*blockDim.x+threadIdx.x)>>5; if(row>=Nn) return;
    int lane=threadIdx.x&31;
    int s=rp[row], e=rp[row+1];
    if(s==e) return;
    float base=dr[row]+bm[0];
    float m=-3.4e38f;
    for(int i=s+lane;i<e;i+=32) m=fmaxf(m, base+dc[col[i]]);
#pragma unroll
    for(int o=16;o;o>>=1) m=fmaxf(m,__shfl_xor_sync(0xffffffffu,m,o));
    float ss=0.f;
    for(int i=s+lane;i<e;i+=32) ss+=__expf(base+dc[col[i]]-m);
#pragma unroll
    for(int o=16;o;o>>=1) ss+=__shfl_xor_sync(0xffffffffu,ss,o);
    float inv=com/ss;
    for(int i=s+lane;i<e;i+=32) val[i]+=__expf(base+dc[col[i]]-m)*inv;
}

// ------------- 16-class softmax + logits + top2 weight -------------
__global__ void k_softmax_w(const float* __restrict__ C, float* __restrict__ lg,
                            float* __restrict__ w){
    int node=blockIdx.x*blockDim.x+threadIdx.x; if(node>=Nn) return;
    float x[16];
    const float4* p=(const float4*)(C+(long)node*16);
#pragma unroll
    for(int q=0;q<4;q++){float4 t=p[q]; x[4*q]=t.x; x[4*q+1]=t.y; x[4*q+2]=t.z; x[4*q+3]=t.w;}
    float m=x[0];
#pragma unroll
    for(int j=1;j<16;j++) m=fmaxf(m,x[j]);
    float s=0.f;
#pragma unroll
    for(int j=0;j<16;j++){x[j]=__expf(x[j]-m); s+=x[j];}
    float inv=1.f/s;
    float fir=0.f, sec=0.f;
#pragma unroll
    for(int j=0;j<16;j++){
        float pr=x[j]*inv;
        lg[(long)node*16+j]=logf(pr+EPSF);
        if(pr>fir){sec=fir; fir=pr;} else if(pr>sec) sec=pr;
    }
    if(w) w[node]=sqrtf((fir+EPSF)*(fir-sec+EPSF));
}

__global__ void k_bal(const float* __restrict__ w1, const float* __restrict__ w2,
                      float* __restrict__ b1, float* __restrict__ b2){
    int i=blockIdx.x*blockDim.x+threadIdx.x; if(i>=Nn) return;
    float a=w1[i], b=w2[i], inv=1.f/(a+b);
    b1[i]=a*inv; b2[i]=b*inv;
}

__global__ void k_normrows(float* __restrict__ E){
    int row=(blockIdx.x*blockDim.x+threadIdx.x)>>5; if(row>=3*Bb) return;
    int lane=threadIdx.x&31;
    float4* p=(float4*)(E+(long)row*128);
    float4 v=p[lane];
    float s=v.x*v.x+v.y*v.y+v.z*v.z+v.w*v.w;
#pragma unroll
    for(int o=16;o;o>>=1) s+=__shfl_xor_sync(0xffffffffu,s,o);
    float inv=rsqrtf(s);
    v.x*=inv; v.y*=inv; v.z*=inv; v.w*=inv;
    p[lane]=v;
}

// ------------- contrast: 128x128 tiles, z=pair; rows pre-normalized -------------
__global__ __launch_bounds__(256) void k_contrast3(
        const float* __restrict__ E, float* RS, float* CS, float* DG){
    __shared__ __align__(16) float sA[32*130];
    __shared__ __align__(16) float sW[32*128];
    __shared__ float sRS[128], sCS[128];
    int pair=blockIdx.z;
    const float* z1; const float* z2;
    if(pair==0){ z1=E;            z2=E+(long)Bb*128; }
    else if(pair==1){ z1=E;       z2=E+(long)2*Bb*128; }
    else { z1=E+(long)Bb*128;     z2=E+(long)2*Bb*128; }
    float* rs=RS+(long)pair*Bb;
    float* cs=CS+(long)pair*Bb;
    float* dg=DG+(long)pair*Bb;

    int tid=threadIdx.x, tx=tid&15, ty=tid>>4;
    int br=blockIdx.y*128, bc=blockIdx.x*128;
    u64 acc[8][4];
#pragma unroll
    for(int i=0;i<8;i++){acc[i][0]=0;acc[i][1]=0;acc[i][2]=0;acc[i][3]=0;}
    int ra=tid>>3, fa=(tid&7)<<2;

    for(int k0=0;k0<128;k0+=32){
#pragma unroll
        for(int h=0;h<4;h++){
            int r=ra+h*32;
            float4 v=*(const float4*)(z1+(long)(br+r)*128+k0+fa);
            sA[(fa+0)*130+r]=v.x; sA[(fa+1)*130+r]=v.y;
            sA[(fa+2)*130+r]=v.z; sA[(fa+3)*130+r]=v.w;
        }
#pragma unroll
        for(int h=0;h<4;h++){
            int c=ra+h*32;
            float4 v=*(const float4*)(z2+(long)(bc+c)*128+k0+fa);
            sW[(fa+0)*128+c]=v.x; sW[(fa+1)*128+c]=v.y;
            sW[(fa+2)*128+c]=v.z; sW[(fa+3)*128+c]=v.w;
        }
        __syncthreads();
#pragma unroll
        for(int kk=0;kk<32;kk++){
            MMA_KK(&sA[kk*130+ty*8], &sW[kk*128+tx*8]);
        }
        __syncthreads();
    }
    if(tid<128){sRS[tid]=0.f; sCS[tid]=0.f;}
    __syncthreads();
    float rsum[8]={0,0,0,0,0,0,0,0}, csum[8]={0,0,0,0,0,0,0,0};
#pragma unroll
    for(int i=0;i<8;i++){
        float vv[8];
#pragma unroll
        for(int p=0;p<4;p++){float2 t=up2(acc[i][p]); vv[2*p]=t.x; vv[2*p+1]=t.y;}
        int gr=br+ty*8+i;
#pragma unroll
        for(int j=0;j<8;j++){
            float e=__expf(2.0f*vv[j]);
            rsum[i]+=e; csum[j]+=e;
            if(gr==bc+tx*8+j) dg[gr]=e;
        }
    }
#pragma unroll
    for(int i=0;i<8;i++) atomicAdd(&sRS[ty*8+i], rsum[i]);
#pragma unroll
    for(int j=0;j<8;j++) atomicAdd(&sCS[tx*8+j], csum[j]);
    __syncthreads();
    if(tid<128){atomicAdd(&rs[br+tid], sRS[tid]); atomicAdd(&cs[bc+tid], sCS[tid]);}
}

__global__ void k_creduce3(const float* __restrict__ RS, const float* __restrict__ CS,
                           const float* __restrict__ DG, float* out){
    __shared__ float sh[1024];
    int pair=blockIdx.x;
    const float* rs=RS+(long)pair*Bb;
    const float* cs=CS+(long)pair*Bb;
    const float* dg=DG+(long)pair*Bb;
    int tid=threadIdx.x;
    float a=0.f;
    for(int i=tid;i<Bb;i+=1024){
        a+=-logf(dg[i]/(rs[i]+EPSF)+EPSF);
        a+=-logf(dg[i]/(cs[i]+EPSF)+EPSF);
    }
    sh[tid]=a; __syncthreads();
    for(int d=512;d;d>>=1){ if(tid<d) sh[tid]+=sh[tid+d]; __syncthreads(); }
    if(tid==0) out[pair]=0.5f*sh[0]/(float)Bb;
}

// ------------- host -------------
#define GSA(var) ([]{ void* _p; cudaGetSymbolAddress(&_p, var); return _p; }())

extern "C" void kernel_launch(void* const* d_in, const int* in_sizes, int n_in,
                              void* d_out, int out_size){
    const float* feat  =(const float*)d_in[0];
    const int*   i1    =(const int*)  d_in[1];
    const float* v1    =(const float*)d_in[2];
    const int*   i2    =(const int*)  d_in[3];
    const float* v2    =(const float*)d_in[4];
    const int*   bidx  =(const int*)  d_in[5];
    const float* Wgen1 =(const float*)d_in[6];
    const float* Wm1   =(const float*)d_in[7];
    const float* bm1   =(const float*)d_in[8];
    const float* Wgen2 =(const float*)d_in[9];
    const float* Wm2   =(const float*)d_in[10];
    const float* bm2   =(const float*)d_in[11];
    const float* W1v1  =(const float*)d_in[12];
    const float* W2v1  =(const float*)d_in[13];
    const float* W1v2  =(const float*)d_in[14];
    const float* W2v2  =(const float*)d_in[15];
    const float* W1v   =(const float*)d_in[16];
    const float* W2v   =(const float*)d_in[17];
    const float* Wg    =(const float*)d_in[18];
    const float* Wg1   =(const float*)d_in[19];
    const float* Wg2   =(const float*)d_in[20];
    const float* Wp1   =(const float*)d_in[21];
    const float* bp1   =(const float*)d_in[22];
    const float* Wp2   =(const float*)d_in[23];
    const float* bp2   =(const float*)d_in[24];
    float* out=(float*)d_out;

    float* Wp=(float*)GSA(g_Wp);
    float* X64a=(float*)GSA(g_X64a); float* X64b=(float*)GSA(g_X64b);
    float* XC1=(float*)GSA(g_XC1); float* XC2=(float*)GSA(g_XC2); float* XCf=(float*)GSA(g_XCf);
    float* XG=(float*)GSA(g_XG); float* XG1=(float*)GSA(g_XG1); float* XG2=(float*)GSA(g_XG2);
    float* H=(float*)GSA(g_H);
    float* emb =(float*)GSA(g_emb);  float* S16 =(float*)GSA(g_S16);
    float* C16 =(float*)GSA(g_C16);
    float* dr=(float*)GSA(g_dr), *dc=(float*)GSA(g_dc);
    float* w1=(float*)GSA(g_w1), *w2=(float*)GSA(g_w2);
    float* b1=(float*)GSA(g_b1), *b2=(float*)GSA(g_b2);
    int* cnt1=(int*)GSA(g_cnt1), *cnt1b=(int*)GSA(g_cnt1b);
    int* cnt2=(int*)GSA(g_cnt2), *cnt2b=(int*)GSA(g_cnt2b);
    int* cur1d=(int*)GSA(g_cur1d), *cur2d=(int*)GSA(g_cur2d);
    int* cur1s=(int*)GSA(g_cur1s), *cur2s=(int*)GSA(g_cur2s);
    int* rp1d=(int*)GSA(g_rp1d), *rp2d=(int*)GSA(g_rp2d);
    int* rp1s=(int*)GSA(g_rp1s), *rp2s=(int*)GSA(g_rp2s);
    int* col1d=(int*)GSA(g_col1d);   float* val1d=(float*)GSA(g_val1d);
    int* col2d=(int*)GSA(g_col2d);   float* val2d=(float*)GSA(g_val2d);
    int* col1s=(int*)GSA(g_col1s);   float* val1s=(float*)GSA(g_val1s);
    int* col2s=(int*)GSA(g_col2s);   float* val2s=(float*)GSA(g_val2s);
    float* Z=(float*)GSA(g_Z), *T=(float*)GSA(g_T), *E=(float*)GSA(g_E);
    float* RS=(float*)GSA(g_RS), *CS=(float*)GSA(g_CS), *DG=(float*)GSA(g_DG);

    const int TB=256;
    int gN  =(Nn+TB-1)/TB;
    int gE  =(Ee+TB-1)/TB;
    int gW  =(Nn*32+TB-1)/TB;
    int gWB =(Bb*32+TB-1)/TB;
    int gW3B=(3*Bb*32+TB-1)/TB;
    dim3 b16(16,16); int g16=(Nn+15)/16;

    // ---- pack + CSR build + one wide GEMM ----
    k_pack<<<(256*896+TB-1)/TB,TB>>>(Wgen1,Wgen2,W1v1,W1v2,W1v,Wg,Wg1,Wg2,Wp);
    k_zero4<<<gN,TB>>>(cnt1,cnt1b,cnt2,cnt2b,Nn);
    k_count2<<<gE,TB>>>(i1,i2,cnt1,cnt1b,cnt2,cnt2b);
    k_scan4<<<4,1024>>>(cnt1,rp1d,cur1d,cnt1b,rp1s,cur1s,cnt2,rp2d,cur2d,cnt2b,rp2s,cur2s,Nn);
    k_gemmP<<<dim3(7,(Nn+127)/128),256>>>(feat,Wp,X64a,X64b,XC1,XC2,XCf,XG,XG1,XG2);
    k_scatter_dir<<<gE,TB>>>(i1,v1,cur1d,col1d,val1d);
    k_scatter_dir<<<gE,TB>>>(i2,v2,cur2d,col2d,val2d);

    // ---- gen_view ----
    k_spmm64<<<gW,TB>>>(rp1d,col1d,val1d,X64a,emb);
    k_nodedot<<<gW,TB>>>(emb,Wm1,dr,dc);
    k_gensoftmax<<<gW,TB>>>(rp1d,col1d,val1d,dr,dc,bm1,0.5f);
    k_spmm64<<<gW,TB>>>(rp2d,col2d,val2d,X64b,emb);
    k_nodedot<<<gW,TB>>>(emb,Wm2,dr,dc);
    k_gensoftmax<<<gW,TB>>>(rp2d,col2d,val2d,dr,dc,bm2,0.5f);

    // ---- symmetrize ----
    k_scatter_sym<<<gN,TB>>>(rp1d,col1d,val1d,cur1s,col1s,val1s);
    k_scatter_sym<<<gN,TB>>>(rp2d,col2d,val2d,cur2s,col2s,val2s);

    // ---- classifier v1 ----
    k_spmm128<<<gW,TB>>>(rp1s,col1s,val1s,XC1,H);
    k_gemm16<<<g16,b16>>>(H,W2v1,S16,Nn);
    k_spmm16<<<g16,b16>>>(rp1s,col1s,val1s,S16,C16);
    k_softmax_w<<<gN,TB>>>(C16,out+(long)16*Nn,w1);
    // ---- classifier v2 ----
    k_spmm128<<<gW,TB>>>(rp2s,col2s,val2s,XC2,H);
    k_gemm16<<<g16,b16>>>(H,W2v2,S16,Nn);
    k_spmm16<<<g16,b16>>>(rp2s,col2s,val2s,S16,C16);
    k_softmax_w<<<gN,TB>>>(C16,out+(long)32*Nn,w2);

    k_bal<<<gN,TB>>>(w1,w2,b1,b2);

    // ---- fused classifier ----
    k_spmm128f<<<gW,TB>>>(rp1s,col1s,val1s,rp2s,col2s,val2s,b1,b2,XCf,H);
    k_gemm16<<<g16,b16>>>(H,W2v,S16,Nn);
    k_spmm16f<<<g16,b16>>>(rp1s,col1s,val1s,rp2s,col2s,val2s,b1,b2,S16,C16);
    k_softmax_w<<<gN,TB>>>(C16,out,nullptr);

    // ---- MI embeddings ----
    k_spmm128fg<<<gWB,TB>>>(bidx,rp1s,col1s,val1s,rp2s,col2s,val2s,b1,b2,XG,Z);
    k_spmm128g<<<gWB,TB>>>(bidx,rp1s,col1s,val1s,XG1,Z+(long)Bb*128);
    k_spmm128g<<<gWB,TB>>>(bidx,rp2s,col2s,val2s,XG2,Z+(long)2*Bb*128);

    k_gemm128<<<dim3(1,(3*Bb+127)/128),256>>>(Z,Wp1,bp1,T,3*Bb,128,1);
    k_gemm128<<<dim3(1,(3*Bb+127)/128),256>>>(T,Wp2,bp2,E,3*Bb,128,0);
    k_normrows<<<gW3B,TB>>>(E);

    // ---- contrasts ----
    int gB3=(3*Bb+TB-1)/TB;
    k_zero_f2<<<gB3,TB>>>(RS,CS,3*Bb);
    dim3 cg(32,32,3);
    k_contrast3<<<cg,256>>>(E,RS,CS,DG);
    k_creduce3<<<3,1024>>>(RS,CS,DG,out+(long)48*Nn);
}

// round 7
// speedup vs baseline: 1.4958x; 1.0826x over previous
#include <cuda_runtime.h>
#include <math.h>

#define Nn 30000
#define Ee 480000
#define Bb 4096
#define EPSF 1e-8f

typedef unsigned long long u64;
__device__ __forceinline__ u64 pk2(float x,float y){u64 r;asm("mov.b64 %0,{%1,%2};":"=l"(r):"f"(x),"f"(y));return r;}
__device__ __forceinline__ float2 up2(u64 v){float2 r;asm("mov.b64 {%0,%1},%2;":"=f"(r.x),"=f"(r.y):"l"(v));return r;}
__device__ __forceinline__ void fma2(u64&d,u64 a,u64 b){asm("fma.rn.f32x2 %0,%1,%2,%0;":"+l"(d):"l"(a),"l"(b));}

// ------------- device scratch -------------
__device__ float g_Wp[256*896];
__device__ float g_X64a[Nn*64], g_X64b[Nn*64];
__device__ float g_XC1[Nn*128], g_XC2[Nn*128], g_XCf[Nn*128];
__device__ float g_XG[Nn*128], g_XG1[Nn*128], g_XG2[Nn*128];
__device__ float g_Ha[Nn*128], g_Hb[Nn*128];
__device__ float g_emba[Nn*64], g_embb[Nn*64];
__device__ float g_S16a[Nn*16], g_S16b[Nn*16];
__device__ float g_C16a[Nn*16], g_C16b[Nn*16];
__device__ float g_dra[Nn], g_dca[Nn], g_drb[Nn], g_dcb[Nn];
__device__ float g_w1[Nn], g_w2[Nn], g_b1[Nn], g_b2[Nn];
__device__ int   g_cnt1[Nn], g_cnt1b[Nn], g_cnt2[Nn], g_cnt2b[Nn];
__device__ int   g_cur1d[Nn], g_cur2d[Nn], g_cur1s[Nn], g_cur2s[Nn];
__device__ int   g_rp1d[Nn+1], g_rp2d[Nn+1], g_rp1s[Nn+1], g_rp2s[Nn+1];
__device__ int   g_col1d[Ee];   __device__ float g_val1d[Ee];
__device__ int   g_col2d[Ee];   __device__ float g_val2d[Ee];
__device__ int   g_col1s[2*Ee]; __device__ float g_val1s[2*Ee];
__device__ int   g_col2s[2*Ee]; __device__ float g_val2s[2*Ee];
__device__ float g_Z[3*Bb*128], g_T[3*Bb*128], g_E[3*Bb*128];
__device__ float g_RS[3*Bb], g_CS[3*Bb], g_DG[3*Bb];

// ------------- pack weights -------------
__global__ void k_pack(const float* __restrict__ wg1, const float* __restrict__ wg2,
                       const float* __restrict__ a, const float* __restrict__ b,
                       const float* __restrict__ c, const float* __restrict__ d,
                       const float* __restrict__ e, const float* __restrict__ f,
                       float* __restrict__ Wp){
    int i=blockIdx.x*blockDim.x+threadIdx.x; if(i>=256*896) return;
    int row=i/896, col=i%896;
    float v;
    if(col<64) v=wg1[row*64+col];
    else if(col<128) v=wg2[row*64+col-64];
    else{
        int blk=(col-128)>>7, lc=(col-128)&127;
        const float* s;
        switch(blk){case 0:s=a;break;case 1:s=b;break;case 2:s=c;break;
                    case 3:s=d;break;case 4:s=e;break;default:s=f;break;}
        v=s[row*128+lc];
    }
    Wp[i]=v;
}

// ------------- small utils -------------
__global__ void k_zero4(int* a,int* b,int* c,int* d,int n){
    int i=blockIdx.x*blockDim.x+threadIdx.x; if(i<n){a[i]=0;b[i]=0;c[i]=0;d[i]=0;} }
__global__ void k_zero_f2(float* a, float* b, int n){
    int i=blockIdx.x*blockDim.x+threadIdx.x; if(i<n){a[i]=0.f;b[i]=0.f;} }

__global__ void k_count2(const int* __restrict__ ind1, const int* __restrict__ ind2,
                         int* cd1, int* cs1, int* cd2, int* cs2){
    int e=blockIdx.x*blockDim.x+threadIdx.x; if(e>=Ee) return;
    int r1=ind1[e], c1=ind1[Ee+e];
    atomicAdd(&cd1[r1],1); atomicAdd(&cs1[r1],1); atomicAdd(&cs1[c1],1);
    int r2=ind2[e], c2=ind2[Ee+e];
    atomicAdd(&cd2[r2],1); atomicAdd(&cs2[r2],1); atomicAdd(&cs2[c2],1);
}

// 4 independent scans; register-staged, fully unrolled (CHUNK=30)
__global__ void k_scan4(const int* c0,int* r0,int* u0,const int* c1,int* r1,int* u1,
                        const int* c2,int* r2,int* u2,const int* c3,int* r3,int* u3){
    const int* cnt; int* rp; int* cu;
    switch(blockIdx.x){
        case 0: cnt=c0; rp=r0; cu=u0; break;
        case 1: cnt=c1; rp=r1; cu=u1; break;
        case 2: cnt=c2; rp=r2; cu=u2; break;
        default:cnt=c3; rp=r3; cu=u3; break;
    }
    const int CH=30;
    int tid=threadIdx.x;
    int s=tid*CH;
    int vloc[CH];
#pragma unroll
    for(int i=0;i<CH;i++){int idx=s+i; vloc[i]=(idx<Nn)?cnt[idx]:0;}
    int sum=0;
#pragma unroll
    for(int i=0;i<CH;i++) sum+=vloc[i];
    __shared__ int wsum[32];
    int lane=tid&31, wid=tid>>5;
    int v=sum;
#pragma unroll
    for(int o=1;o<32;o<<=1){int t=__shfl_up_sync(0xffffffffu,v,o); if(lane>=o) v+=t;}
    if(lane==31) wsum[wid]=v;
    __syncthreads();
    if(wid==0){
        int w=wsum[lane];
#pragma unroll
        for(int o=1;o<32;o<<=1){int t=__shfl_up_sync(0xffffffffu,w,o); if(lane>=o) w+=t;}
        wsum[lane]=w;
    }
    __syncthreads();
    int excl=v-sum+(wid?wsum[wid-1]:0);
    int run=excl;
#pragma unroll
    for(int i=0;i<CH;i++){
        int idx=s+i;
        if(idx<Nn){ rp[idx]=run; cu[idx]=run; run+=vloc[i]; }
    }
    if(tid==1023) rp[Nn]=run;
}

__global__ void k_scatter_dir(const int* __restrict__ ind, const float* __restrict__ vals,
                              int* cur, int* __restrict__ col, float* __restrict__ val){
    int e=blockIdx.x*blockDim.x+threadIdx.x; if(e>=Ee) return;
    int r=ind[e], c=ind[Ee+e];
    int p=atomicAdd(&cur[r],1);
    col[p]=c; val[p]=vals[e];
}

__global__ void k_scatter_sym(const int* __restrict__ rpd, const int* __restrict__ cold,
                              const float* __restrict__ vald, int* cur,
                              int* __restrict__ cols, float* __restrict__ vals){
    int r=blockIdx.x*blockDim.x+threadIdx.x; if(r>=Nn) return;
    for(int i=rpd[r];i<rpd[r+1];i++){
        int c=cold[i]; float v=vald[i];
        int p=atomicAdd(&cur[r],1); cols[p]=c; vals[p]=v;
        int q=atomicAdd(&cur[c],1); cols[q]=r; vals[q]=v;
    }
}

// ------------- inner-product macro (8x8, f32x2) -------------
#define MMA_KK(sak, sWk) do{ \
    float2 a01=*(const float2*)(sak); \
    float2 a23=*(const float2*)((sak)+2); \
    float2 a45=*(const float2*)((sak)+4); \
    float2 a67=*(const float2*)((sak)+6); \
    const ulonglong2* bw=(const ulonglong2*)(sWk); \
    ulonglong2 bA=bw[0], bB=bw[1]; \
    u64 s0=pk2(a01.x,a01.x), s1=pk2(a01.y,a01.y); \
    u64 s2=pk2(a23.x,a23.x), s3=pk2(a23.y,a23.y); \
    u64 s4=pk2(a45.x,a45.x), s5=pk2(a45.y,a45.y); \
    u64 s6=pk2(a67.x,a67.x), s7=pk2(a67.y,a67.y); \
    fma2(acc[0][0],s0,bA.x); fma2(acc[0][1],s0,bA.y); fma2(acc[0][2],s0,bB.x); fma2(acc[0][3],s0,bB.y); \
    fma2(acc[1][0],s1,bA.x); fma2(acc[1][1],s1,bA.y); fma2(acc[1][2],s1,bB.x); fma2(acc[1][3],s1,bB.y); \
    fma2(acc[2][0],s2,bA.x); fma2(acc[2][1],s2,bA.y); fma2(acc[2][2],s2,bB.x); fma2(acc[2][3],s2,bB.y); \
    fma2(acc[3][0],s3,bA.x); fma2(acc[3][1],s3,bA.y); fma2(acc[3][2],s3,bB.x); fma2(acc[3][3],s3,bB.y); \
    fma2(acc[4][0],s4,bA.x); fma2(acc[4][1],s4,bA.y); fma2(acc[4][2],s4,bB.x); fma2(acc[4][3],s4,bB.y); \
    fma2(acc[5][0],s5,bA.x); fma2(acc[5][1],s5,bA.y); fma2(acc[5][2],s5,bB.x); fma2(acc[5][3],s5,bB.y); \
    fma2(acc[6][0],s6,bA.x); fma2(acc[6][1],s6,bA.y); fma2(acc[6][2],s6,bB.x); fma2(acc[6][3],s6,bB.y); \
    fma2(acc[7][0],s7,bA.x); fma2(acc[7][1],s7,bA.y); fma2(acc[7][2],s7,bB.x); fma2(acc[7][3],s7,bB.y); \
}while(0)

// ------------- packed GEMM: feat[30000x256] @ Wp[256x896] -------------
__global__ __launch_bounds__(256) void k_gemmP(
        const float* __restrict__ A, const float* __restrict__ Wp,
        float* __restrict__ e1, float* __restrict__ e2,
        float* __restrict__ x0, float* __restrict__ x1, float* __restrict__ x2,
        float* __restrict__ x3, float* __restrict__ x4, float* __restrict__ x5){
    __shared__ __align__(16) float sA[32*130];
    __shared__ __align__(16) float sW[32*128];
    int tid=threadIdx.x, tx=tid&15, ty=tid>>4;
    int bx=blockIdx.x;
    int br=blockIdx.y*128;
    u64 acc[8][4];
#pragma unroll
    for(int i=0;i<8;i++){acc[i][0]=0;acc[i][1]=0;acc[i][2]=0;acc[i][3]=0;}
    int ra=tid>>3, fa=(tid&7)<<2;
    int cw=(tid&31)<<2, kw=tid>>5;

    for(int k0=0;k0<256;k0+=32){
#pragma unroll
        for(int h=0;h<4;h++){
            int r=ra+h*32, gr=br+r;
            float4 v=make_float4(0.f,0.f,0.f,0.f);
            if(gr<Nn) v=*(const float4*)(A+(long)gr*256+k0+fa);
            sA[(fa+0)*130+r]=v.x; sA[(fa+1)*130+r]=v.y;
            sA[(fa+2)*130+r]=v.z; sA[(fa+3)*130+r]=v.w;
        }
#pragma unroll
        for(int h=0;h<4;h++){
            int kk=kw+h*8;
            float4 v=*(const float4*)(Wp+(long)(k0+kk)*896+bx*128+cw);
            *(float4*)&sW[kk*128+cw]=v;
        }
        __syncthreads();
#pragma unroll
        for(int kk=0;kk<32;kk++){
            MMA_KK(&sA[kk*130+ty*8], &sW[kk*128+tx*8]);
        }
        __syncthreads();
    }
    float* dst; int w; int c0;
    if(bx==0){
        if(tx<8){ dst=e1; w=64; c0=tx*8; } else { dst=e2; w=64; c0=(tx-8)*8; }
    } else {
        switch(bx-1){case 0:dst=x0;break;case 1:dst=x1;break;case 2:dst=x2;break;
                     case 3:dst=x3;break;case 4:dst=x4;break;default:dst=x5;break;}
        w=128; c0=tx*8;
    }
#pragma unroll
    for(int i=0;i<8;i++){
        int gr=br+ty*8+i; if(gr>=Nn) continue;
        float vv[8];
#pragma unroll
        for(int p=0;p<4;p++){float2 t=up2(acc[i][p]); vv[2*p]=t.x; vv[2*p+1]=t.y;}
        float* cp=dst+(long)gr*w+c0;
        *(float4*)cp=make_float4(vv[0],vv[1],vv[2],vv[3]);
        *(float4*)(cp+4)=make_float4(vv[4],vv[5],vv[6],vv[7]);
    }
}

// ------------- generic GEMM: C[n,128]=A[n,K]@W[K,128] (+bias, act) -------------
__global__ __launch_bounds__(256) void k_gemm128(
        const float* __restrict__ A, const float* __restrict__ W,
        const float* __restrict__ bias, float* __restrict__ C,
        int n, int K, int act){
    __shared__ __align__(16) float sA[32*130];
    __shared__ __align__(16) float sW[32*128];
    int tid=threadIdx.x, tx=tid&15, ty=tid>>4;
    int br=blockIdx.y*128;
    u64 acc[8][4];
#pragma unroll
    for(int i=0;i<8;i++){acc[i][0]=0;acc[i][1]=0;acc[i][2]=0;acc[i][3]=0;}
    int ra=tid>>3, fa=(tid&7)<<2;
    int cw=(tid&31)<<2, kw=tid>>5;

    for(int k0=0;k0<K;k0+=32){
#pragma unroll
        for(int h=0;h<4;h++){
            int r=ra+h*32, gr=br+r;
            float4 v=make_float4(0.f,0.f,0.f,0.f);
            if(gr<n) v=*(const float4*)(A+(long)gr*K+k0+fa);
            sA[(fa+0)*130+r]=v.x; sA[(fa+1)*130+r]=v.y;
            sA[(fa+2)*130+r]=v.z; sA[(fa+3)*130+r]=v.w;
        }
#pragma unroll
        for(int h=0;h<4;h++){
            int kk=kw+h*8;
            float4 v=*(const float4*)(W+(long)(k0+kk)*128+cw);
            *(float4*)&sW[kk*128+cw]=v;
        }
        __syncthreads();
#pragma unroll
        for(int kk=0;kk<32;kk++){
            MMA_KK(&sA[kk*130+ty*8], &sW[kk*128+tx*8]);
        }
        __syncthreads();
    }
    float bb[8];
#pragma unroll
    for(int q=0;q<8;q++) bb[q]=bias?bias[tx*8+q]:0.f;
#pragma unroll
    for(int i=0;i<8;i++){
        int gr=br+ty*8+i; if(gr>=n) continue;
        float vv[8];
#pragma unroll
        for(int p=0;p<4;p++){float2 t=up2(acc[i][p]); vv[2*p]=t.x; vv[2*p+1]=t.y;}
#pragma unroll
        for(int q=0;q<8;q++){
            float v=vv[q]+bb[q];
            if(act==1) v=(v>0.f)?v:expm1f(v);
            vv[q]=v;
        }
        float* cp=C+(long)gr*128+tx*8;
        *(float4*)cp=make_float4(vv[0],vv[1],vv[2],vv[3]);
        *(float4*)(cp+4)=make_float4(vv[4],vv[5],vv[6],vv[7]);
    }
}

// ------------- GEMM M=16 (W2 in smem) -------------
__global__ void k_gemm16(const float* __restrict__ H, const float* __restrict__ W2,
                         float* __restrict__ C, int n){
    __shared__ float sW[128*16];
    int tid=threadIdx.y*16+threadIdx.x;
#pragma unroll
    for(int q=0;q<2;q++) ((float4*)sW)[tid*2+q]=((const float4*)W2)[tid*2+q];
    __syncthreads();
    int r=blockIdx.x*16+threadIdx.y, j=threadIdx.x;
    if(r>=n) return;
    const float4* H4=(const float4*)(H+(long)r*128);
    float acc=0.f;
#pragma unroll
    for(int k4=0;k4<32;k4++){
        float4 h=H4[k4];
        acc+=h.x*sW[(k4*4+0)*16+j];
        acc+=h.y*sW[(k4*4+1)*16+j];
        acc+=h.z*sW[(k4*4+2)*16+j];
        acc+=h.w*sW[(k4*4+3)*16+j];
    }
    C[(long)r*16+j]=acc;
}

// ------------- SpMM (warp per row, 2-way unrolled) -------------
__device__ __forceinline__ float4 spmm_row128(const int* __restrict__ rp,
        const int* __restrict__ col, const float* __restrict__ val,
        const float4* __restrict__ X4, int w, int lane){
    int s=rp[w], e=rp[w+1];
    float4 A=make_float4(0.f,0.f,0.f,0.f), B=A;
    int i=s;
    for(; i+1<e; i+=2){
        int c0=col[i], c1=col[i+1];
        float v0=val[i], v1=val[i+1];
        float4 x0=X4[(long)c0*32+lane];
        float4 x1=X4[(long)c1*32+lane];
        A.x+=v0*x0.x; A.y+=v0*x0.y; A.z+=v0*x0.z; A.w+=v0*x0.w;
        B.x+=v1*x1.x; B.y+=v1*x1.y; B.z+=v1*x1.z; B.w+=v1*x1.w;
    }
    if(i<e){
        int c=col[i]; float v=val[i];
        float4 x=X4[(long)c*32+lane];
        A.x+=v*x.x; A.y+=v*x.y; A.z+=v*x.z; A.w+=v*x.w;
    }
    A.x+=B.x; A.y+=B.y; A.z+=B.z; A.w+=B.w;
    return A;
}

__global__ void k_spmm128(const int* __restrict__ rp, const int* __restrict__ col,
                          const float* __restrict__ val, const float* __restrict__ X,
                          float* __restrict__ Y){
    int w=(blockIdx.x*blockDim.x+threadIdx.x)>>5; if(w>=Nn) return;
    int lane=threadIdx.x&31;
    float4 a=spmm_row128(rp,col,val,(const float4*)X,w,lane);
    a.x=fmaxf(a.x,0.f); a.y=fmaxf(a.y,0.f); a.z=fmaxf(a.z,0.f); a.w=fmaxf(a.w,0.f);
    ((float4*)Y)[(long)w*32+lane]=a;
}

__global__ void k_spmm128f(const int* __restrict__ rp1, const int* __restrict__ col1,
                           const float* __restrict__ val1,
                           const int* __restrict__ rp2, const int* __restrict__ col2,
                           const float* __restrict__ val2,
                           const float* __restrict__ b1, const float* __restrict__ b2,
                           const float* __restrict__ X, float* __restrict__ Y){
    int w=(blockIdx.x*blockDim.x+threadIdx.x)>>5; if(w>=Nn) return;
    int lane=threadIdx.x&31;
    float4 a1=spmm_row128(rp1,col1,val1,(const float4*)X,w,lane);
    float4 a2=spmm_row128(rp2,col2,val2,(const float4*)X,w,lane);
    float f1=b1[w], f2=b2[w];
    float4 r;
    r.x=fmaxf(f1*a1.x+f2*a2.x,0.f); r.y=fmaxf(f1*a1.y+f2*a2.y,0.f);
    r.z=fmaxf(f1*a1.z+f2*a2.z,0.f); r.w=fmaxf(f1*a1.w+f2*a2.w,0.f);
    ((float4*)Y)[(long)w*32+lane]=r;
}

__global__ void k_spmm128g(const int* __restrict__ bidx,
                           const int* __restrict__ rp, const int* __restrict__ col,
                           const float* __restrict__ val, const float* __restrict__ X,
                           float* __restrict__ Z){
    int w=(blockIdx.x*blockDim.x+threadIdx.x)>>5; if(w>=Bb) return;
    int lane=threadIdx.x&31;
    int row=bidx[w];
    float4 a=spmm_row128(rp,col,val,(const float4*)X,row,lane);
    a.x=fmaxf(a.x,0.f); a.y=fmaxf(a.y,0.f); a.z=fmaxf(a.z,0.f); a.w=fmaxf(a.w,0.f);
    ((float4*)Z)[(long)w*32+lane]=a;
}

__global__ void k_spmm128fg(const int* __restrict__ bidx,
                            const int* __restrict__ rp1, const int* __restrict__ col1,
                            const float* __restrict__ val1,
                            const int* __restrict__ rp2, const int* __restrict__ col2,
                            const float* __restrict__ val2,
                            const float* __restrict__ b1, const float* __restrict__ b2,
                            const float* __restrict__ X, float* __restrict__ Z){
    int w=(blockIdx.x*blockDim.x+threadIdx.x)>>5; if(w>=Bb) return;
    int lane=threadIdx.x&31;
    int row=bidx[w];
    float4 a1=spmm_row128(rp1,col1,val1,(const float4*)X,row,lane);
    float4 a2=spmm_row128(rp2,col2,val2,(const float4*)X,row,lane);
    float f1=b1[row], f2=b2[row];
    float4 r;
    r.x=fmaxf(f1*a1.x+f2*a2.x,0.f); r.y=fmaxf(f1*a1.y+f2*a2.y,0.f);
    r.z=fmaxf(f1*a1.z+f2*a2.z,0.f); r.w=fmaxf(f1*a1.w+f2*a2.w,0.f);
    ((float4*)Z)[(long)w*32+lane]=r;
}

__global__ void k_spmm64(const int* __restrict__ rp, const int* __restrict__ col,
                         const float* __restrict__ val, const float* __restrict__ X,
                         float* __restrict__ Y){
    int w=(blockIdx.x*blockDim.x+threadIdx.x)>>5; if(w>=Nn) return;
    int lane=threadIdx.x&31;
    const float2* X2=(const float2*)X;
    int s=rp[w], e=rp[w+1];
    float2 A=make_float2(0.f,0.f), B=A;
    int i=s;
    for(; i+1<e; i+=2){
        int c0=col[i], c1=col[i+1];
        float v0=val[i], v1=val[i+1];
        float2 x0=X2[(long)c0*32+lane];
        float2 x1=X2[(long)c1*32+lane];
        A.x+=v0*x0.x; A.y+=v0*x0.y;
        B.x+=v1*x1.x; B.y+=v1*x1.y;
    }
    if(i<e){
        int c=col[i]; float v=val[i];
        float2 x=X2[(long)c*32+lane];
        A.x+=v*x.x; A.y+=v*x.y;
    }
    A.x=fmaxf(A.x+B.x,0.f); A.y=fmaxf(A.y+B.y,0.f);
    ((float2*)Y)[(long)w*32+lane]=A;
}

__global__ void k_spmm16(const int* __restrict__ rp, const int* __restrict__ col,
                         const float* __restrict__ val, const float* __restrict__ X,
                         float* __restrict__ Y){
    int row=blockIdx.x*16+threadIdx.y; int j=threadIdx.x;
    if(row>=Nn) return;
    float acc=0.f;
    for(int i=rp[row];i<rp[row+1];i++) acc+=val[i]*X[(long)col[i]*16+j];
    Y[(long)row*16+j]=acc;
}

__global__ void k_spmm16f(const int* __restrict__ rp1, const int* __restrict__ col1,
                          const float* __restrict__ val1,
                          const int* __restrict__ rp2, const int* __restrict__ col2,
                          const float* __restrict__ val2,
                          const float* __restrict__ b1, const float* __restrict__ b2,
                          const float* __restrict__ X, float* __restrict__ Y){
    int row=blockIdx.x*16+threadIdx.y; int j=threadIdx.x;
    if(row>=Nn) return;
    float a1=0.f, a2=0.f;
    for(int i=rp1[row];i<rp1[row+1];i++) a1+=val1[i]*X[(long)col1[i]*16+j];
    for(int i=rp2[row];i<rp2[row+1];i++) a2+=val2[i]*X[(long)col2[i]*16+j];
    Y[(long)row*16+j]=b1[row]*a1+b2[row]*a2;
}

// ------------- gen_view helpers -------------
__global__ void k_nodedot(const float* __restrict__ emb, const float* __restrict__ Wm,
                          float* __restrict__ dr, float* __restrict__ dc){
    int node=(blockIdx.x*blockDim.x+threadIdx.x)>>5; if(node>=Nn) return;
    int lane=threadIdx.x&31;
    float2 e=((const float2*)(emb+(long)node*64))[lane];
    float2 wr=((const float2*)Wm)[lane];
    float2 wc=((const float2*)Wm)[lane+32];
    float a=e.x*wr.x+e.y*wr.y;
    float b=e.x*wc.x+e.y*wc.y;
#pragma unroll
    for(int o=16;o;o>>=1){
        a+=__shfl_xor_sync(0xffffffffu,a,o);
        b+=__shfl_xor_sync(0xffffffffu,b,o);
    }
    if(lane==0){dr[node]=a; dc[node]=b;}
}

__global__ void k_gensoftmax(const int* __restrict__ rp, const int* __restrict__ col,
                             float* __restrict__ val, const float* __restrict__ dr,
                             const float* __restrict__ dc, const float* __restrict__ bm,
                             float com){
    int row=(blockIdx.x*blockDim.x+threadIdx.x)>>5; if(row>=Nn) return;
    int lane=threadIdx.x&31;
    int s=rp[row], e=rp[row+1];
    if(s==e) return;
    float base=dr[row]+bm[0];
    float m=-3.4e38f;
    for(int i=s+lane;i<e;i+=32) m=fmaxf(m, base+dc[col[i]]);
#pragma unroll
    for(int o=16;o;o>>=1) m=fmaxf(m,__shfl_xor_sync(0xffffffffu,m,o));
    float ss=0.f;
    for(int i=s+lane;i<e;i+=32) ss+=__expf(base+dc[col[i]]-m);
#pragma unroll
    for(int o=16;o;o>>=1) ss+=__shfl_xor_sync(0xffffffffu,ss,o);
    float inv=com/ss;
    for(int i=s+lane;i<e;i+=32) val[i]+=__expf(base+dc[col[i]]-m)*inv;
}

// ------------- 16-class softmax + logits + top2 weight -------------
__global__ void k_softmax_w(const float* __restrict__ C, float* __restrict__ lg,
                            float* __restrict__ w){
    int node=blockIdx.x*blockDim.x+threadIdx.x; if(node>=Nn) return;
    float x[16];
    const float4* p=(const float4*)(C+(long)node*16);
#pragma unroll
    for(int q=0;q<4;q++){float4 t=p[q]; x[4*q]=t.x; x[4*q+1]=t.y; x[4*q+2]=t.z; x[4*q+3]=t.w;}
    float m=x[0];
#pragma unroll
    for(int j=1;j<16;j++) m=fmaxf(m,x[j]);
    float s=0.f;
#pragma unroll
    for(int j=0;j<16;j++){x[j]=__expf(x[j]-m); s+=x[j];}
    float inv=1.f/s;
    float fir=0.f, sec=0.f;
#pragma unroll
    for(int j=0;j<16;j++){
        float pr=x[j]*inv;
        lg[(long)node*16+j]=logf(pr+EPSF);
        if(pr>fir){sec=fir; fir=pr;} else if(pr>sec) sec=pr;
    }
    if(w) w[node]=sqrtf((fir+EPSF)*(fir-sec+EPSF));
}

__global__ void k_bal(const float* __restrict__ w1, const float* __restrict__ w2,
                      float* __restrict__ b1, float* __restrict__ b2){
    int i=blockIdx.x*blockDim.x+threadIdx.x; if(i>=Nn) return;
    float a=w1[i], b=w2[i], inv=1.f/(a+b);
    b1[i]=a*inv; b2[i]=b*inv;
}

__global__ void k_normrows(float* __restrict__ E){
    int row=(blockIdx.x*blockDim.x+threadIdx.x)>>5; if(row>=3*Bb) return;
    int lane=threadIdx.x&31;
    float4* p=(float4*)(E+(long)row*128);
    float4 v=p[lane];
    float s=v.x*v.x+v.y*v.y+v.z*v.z+v.w*v.w;
#pragma unroll
    for(int o=16;o;o>>=1) s+=__shfl_xor_sync(0xffffffffu,s,o);
    float inv=rsqrtf(s);
    v.x*=inv; v.y*=inv; v.z*=inv; v.w*=inv;
    p[lane]=v;
}

// ------------- contrast -------------
__global__ __launch_bounds__(256) void k_contrast3(
        const float* __restrict__ E, float* RS, float* CS, float* DG){
    __shared__ __align__(16) float sA[32*130];
    __shared__ __align__(16) float sW[32*128];
    __shared__ float sRS[128], sCS[128];
    int pair=blockIdx.z;
    const float* z1; const float* z2;
    if(pair==0){ z1=E;            z2=E+(long)Bb*128; }
    else if(pair==1){ z1=E;       z2=E+(long)2*Bb*128; }
    else { z1=E+(long)Bb*128;     z2=E+(long)2*Bb*128; }
    float* rs=RS+(long)pair*Bb;
    float* cs=CS+(long)pair*Bb;
    float* dg=DG+(long)pair*Bb;

    int tid=threadIdx.x, tx=tid&15, ty=tid>>4;
    int br=blockIdx.y*128, bc=blockIdx.x*128;
    u64 acc[8][4];
#pragma unroll
    for(int i=0;i<8;i++){acc[i][0]=0;acc[i][1]=0;acc[i][2]=0;acc[i][3]=0;}
    int ra=tid>>3, fa=(tid&7)<<2;

    for(int k0=0;k0<128;k0+=32){
#pragma unroll
        for(int h=0;h<4;h++){
            int r=ra+h*32;
            float4 v=*(const float4*)(z1+(long)(br+r)*128+k0+fa);
            sA[(fa+0)*130+r]=v.x; sA[(fa+1)*130+r]=v.y;
            sA[(fa+2)*130+r]=v.z; sA[(fa+3)*130+r]=v.w;
        }
#pragma unroll
        for(int h=0;h<4;h++){
            int c=ra+h*32;
            float4 v=*(const float4*)(z2+(long)(bc+c)*128+k0+fa);
            sW[(fa+0)*128+c]=v.x; sW[(fa+1)*128+c]=v.y;
            sW[(fa+2)*128+c]=v.z; sW[(fa+3)*128+c]=v.w;
        }
        __syncthreads();
#pragma unroll
        for(int kk=0;kk<32;kk++){
            MMA_KK(&sA[kk*130+ty*8], &sW[kk*128+tx*8]);
        }
        __syncthreads();
    }
    if(tid<128){sRS[tid]=0.f; sCS[tid]=0.f;}
    __syncthreads();
    float rsum[8]={0,0,0,0,0,0,0,0}, csum[8]={0,0,0,0,0,0,0,0};
#pragma unroll
    for(int i=0;i<8;i++){
        float vv[8];
#pragma unroll
        for(int p=0;p<4;p++){float2 t=up2(acc[i][p]); vv[2*p]=t.x; vv[2*p+1]=t.y;}
        int gr=br+ty*8+i;
#pragma unroll
        for(int j=0;j<8;j++){
            float e=__expf(2.0f*vv[j]);
            rsum[i]+=e; csum[j]+=e;
            if(gr==bc+tx*8+j) dg[gr]=e;
        }
    }
#pragma unroll
    for(int i=0;i<8;i++) atomicAdd(&sRS[ty*8+i], rsum[i]);
#pragma unroll
    for(int j=0;j<8;j++) atomicAdd(&sCS[tx*8+j], csum[j]);
    __syncthreads();
    if(tid<128){atomicAdd(&rs[br+tid], sRS[tid]); atomicAdd(&cs[bc+tid], sCS[tid]);}
}

__global__ void k_creduce3(const float* __restrict__ RS, const float* __restrict__ CS,
                           const float* __restrict__ DG, float* out){
    __shared__ float sh[1024];
    int pair=blockIdx.x;
    const float* rs=RS+(long)pair*Bb;
    const float* cs=CS+(long)pair*Bb;
    const float* dg=DG+(long)pair*Bb;
    int tid=threadIdx.x;
    float a=0.f;
    for(int i=tid;i<Bb;i+=1024){
        a+=-logf(dg[i]/(rs[i]+EPSF)+EPSF);
        a+=-logf(dg[i]/(cs[i]+EPSF)+EPSF);
    }
    sh[tid]=a; __syncthreads();
    for(int d=512;d;d>>=1){ if(tid<d) sh[tid]+=sh[tid+d]; __syncthreads(); }
    if(tid==0) out[pair]=0.5f*sh[0]/(float)Bb;
}

// ------------- host -------------
#define GSA(var) ([]{ void* _p; cudaGetSymbolAddress(&_p, var); return _p; }())

extern "C" void kernel_launch(void* const* d_in, const int* in_sizes, int n_in,
                              void* d_out, int out_size){
    const float* feat  =(const float*)d_in[0];
    const int*   i1    =(const int*)  d_in[1];
    const float* v1    =(const float*)d_in[2];
    const int*   i2    =(const int*)  d_in[3];
    const float* v2    =(const float*)d_in[4];
    const int*   bidx  =(const int*)  d_in[5];
    const float* Wgen1 =(const float*)d_in[6];
    const float* Wm1   =(const float*)d_in[7];
    const float* bm1   =(const float*)d_in[8];
    const float* Wgen2 =(const float*)d_in[9];
    const float* Wm2   =(const float*)d_in[10];
    const float* bm2   =(const float*)d_in[11];
    const float* W1v1  =(const float*)d_in[12];
    const float* W2v1  =(const float*)d_in[13];
    const float* W1v2  =(const float*)d_in[14];
    const float* W2v2  =(const float*)d_in[15];
    const float* W1v   =(const float*)d_in[16];
    const float* W2v   =(const float*)d_in[17];
    const float* Wg    =(const float*)d_in[18];
    const float* Wg1   =(const float*)d_in[19];
    const float* Wg2   =(const float*)d_in[20];
    const float* Wp1   =(const float*)d_in[21];
    const float* bp1   =(const float*)d_in[22];
    const float* Wp2   =(const float*)d_in[23];
    const float* bp2   =(const float*)d_in[24];
    float* out=(float*)d_out;

    float* Wp=(float*)GSA(g_Wp);
    float* X64a=(float*)GSA(g_X64a); float* X64b=(float*)GSA(g_X64b);
    float* XC1=(float*)GSA(g_XC1); float* XC2=(float*)GSA(g_XC2); float* XCf=(float*)GSA(g_XCf);
    float* XG=(float*)GSA(g_XG); float* XG1=(float*)GSA(g_XG1); float* XG2=(float*)GSA(g_XG2);
    float* Ha=(float*)GSA(g_Ha); float* Hb=(float*)GSA(g_Hb);
    float* emba=(float*)GSA(g_emba); float* embb=(float*)GSA(g_embb);
    float* S16a=(float*)GSA(g_S16a); float* S16b=(float*)GSA(g_S16b);
    float* C16a=(float*)GSA(g_C16a); float* C16b=(float*)GSA(g_C16b);
    float* dra=(float*)GSA(g_dra), *dca=(float*)GSA(g_dca);
    float* drb=(float*)GSA(g_drb), *dcb=(float*)GSA(g_dcb);
    float* w1=(float*)GSA(g_w1), *w2=(float*)GSA(g_w2);
    float* b1=(float*)GSA(g_b1), *b2=(float*)GSA(g_b2);
    int* cnt1=(int*)GSA(g_cnt1), *cnt1b=(int*)GSA(g_cnt1b);
    int* cnt2=(int*)GSA(g_cnt2), *cnt2b=(int*)GSA(g_cnt2b);
    int* cur1d=(int*)GSA(g_cur1d), *cur2d=(int*)GSA(g_cur2d);
    int* cur1s=(int*)GSA(g_cur1s), *cur2s=(int*)GSA(g_cur2s);
    int* rp1d=(int*)GSA(g_rp1d), *rp2d=(int*)GSA(g_rp2d);
    int* rp1s=(int*)GSA(g_rp1s), *rp2s=(int*)GSA(g_rp2s);
    int* col1d=(int*)GSA(g_col1d);   float* val1d=(float*)GSA(g_val1d);
    int* col2d=(int*)GSA(g_col2d);   float* val2d=(float*)GSA(g_val2d);
    int* col1s=(int*)GSA(g_col1s);   float* val1s=(float*)GSA(g_val1s);
    int* col2s=(int*)GSA(g_col2s);   float* val2s=(float*)GSA(g_val2s);
    float* Z=(float*)GSA(g_Z), *T=(float*)GSA(g_T), *E=(float*)GSA(g_E);
    float* RS=(float*)GSA(g_RS), *CS=(float*)GSA(g_CS), *DG=(float*)GSA(g_DG);

    const int TB=256;
    int gN  =(Nn+TB-1)/TB;
    int gE  =(Ee+TB-1)/TB;
    int gW  =(Nn*32+TB-1)/TB;
    int gWB =(Bb*32+TB-1)/TB;
    int gW3B=(3*Bb*32+TB-1)/TB;
    dim3 b16(16,16); int g16=(Nn+15)/16;

    // streams + events created ONCE (first call = harness correctness run,
    // before the pre-capture memory baseline) and reused forever — no
    // allocations during capture or replay, nothing to free at teardown.
    static cudaStream_t s1=0, s2=0;
    static cudaEvent_t eRoot=0,eScan=0,eG=0,eW1=0,eW2=0,eZ1=0,eZ2=0;
    if(!s1){
        cudaStreamCreateWithFlags(&s1, cudaStreamNonBlocking);
        cudaStreamCreateWithFlags(&s2, cudaStreamNonBlocking);
        cudaEventCreateWithFlags(&eRoot,cudaEventDisableTiming);
        cudaEventCreateWithFlags(&eScan,cudaEventDisableTiming);
        cudaEventCreateWithFlags(&eG,  cudaEventDisableTiming);
        cudaEventCreateWithFlags(&eW1, cudaEventDisableTiming);
        cudaEventCreateWithFlags(&eW2, cudaEventDisableTiming);
        cudaEventCreateWithFlags(&eZ1, cudaEventDisableTiming);
        cudaEventCreateWithFlags(&eZ2, cudaEventDisableTiming);
    }

    cudaEventRecord(eRoot, 0);
    cudaStreamWaitEvent(s1, eRoot, 0);
    cudaStreamWaitEvent(s2, eRoot, 0);

    // ---- stream 0: pack + big GEMM ----
    k_pack<<<(256*896+TB-1)/TB,TB>>>(Wgen1,Wgen2,W1v1,W1v2,W1v,Wg,Wg1,Wg2,Wp);
    k_zero_f2<<<(3*Bb+TB-1)/TB,TB>>>(RS,CS,3*Bb);
    k_gemmP<<<dim3(7,(Nn+127)/128),256>>>(feat,Wp,X64a,X64b,XC1,XC2,XCf,XG,XG1,XG2);
    cudaEventRecord(eG, 0);

    // ---- s1: CSR build + view1 pipeline ----
    k_zero4<<<gN,TB,0,s1>>>(cnt1,cnt1b,cnt2,cnt2b,Nn);
    k_count2<<<gE,TB,0,s1>>>(i1,i2,cnt1,cnt1b,cnt2,cnt2b);
    k_scan4<<<4,1024,0,s1>>>(cnt1,rp1d,cur1d,cnt1b,rp1s,cur1s,cnt2,rp2d,cur2d,cnt2b,rp2s,cur2s);
    cudaEventRecord(eScan, s1);
    k_scatter_dir<<<gE,TB,0,s1>>>(i1,v1,cur1d,col1d,val1d);
    cudaStreamWaitEvent(s1, eG, 0);
    k_spmm64<<<gW,TB,0,s1>>>(rp1d,col1d,val1d,X64a,emba);
    k_nodedot<<<gW,TB,0,s1>>>(emba,Wm1,dra,dca);
    k_gensoftmax<<<gW,TB,0,s1>>>(rp1d,col1d,val1d,dra,dca,bm1,0.5f);
    k_scatter_sym<<<gN,TB,0,s1>>>(rp1d,col1d,val1d,cur1s,col1s,val1s);
    k_spmm128<<<gW,TB,0,s1>>>(rp1s,col1s,val1s,XC1,Ha);
    k_gemm16<<<g16,b16,0,s1>>>(Ha,W2v1,S16a,Nn);
    k_spmm16<<<g16,b16,0,s1>>>(rp1s,col1s,val1s,S16a,C16a);
    k_softmax_w<<<gN,TB,0,s1>>>(C16a,out+(long)16*Nn,w1);
    cudaEventRecord(eW1, s1);
    k_spmm128g<<<gWB,TB,0,s1>>>(bidx,rp1s,col1s,val1s,XG1,Z+(long)Bb*128);
    cudaEventRecord(eZ1, s1);

    // ---- s2: view2 pipeline ----
    cudaStreamWaitEvent(s2, eScan, 0);
    k_scatter_dir<<<gE,TB,0,s2>>>(i2,v2,cur2d,col2d,val2d);
    cudaStreamWaitEvent(s2, eG, 0);
    k_spmm64<<<gW,TB,0,s2>>>(rp2d,col2d,val2d,X64b,embb);
    k_nodedot<<<gW,TB,0,s2>>>(embb,Wm2,drb,dcb);
    k_gensoftmax<<<gW,TB,0,s2>>>(rp2d,col2d,val2d,drb,dcb,bm2,0.5f);
    k_scatter_sym<<<gN,TB,0,s2>>>(rp2d,col2d,val2d,cur2s,col2s,val2s);
    k_spmm128<<<gW,TB,0,s2>>>(rp2s,col2s,val2s,XC2,Hb);
    k_gemm16<<<g16,b16,0,s2>>>(Hb,W2v2,S16b,Nn);
    k_spmm16<<<g16,b16,0,s2>>>(rp2s,col2s,val2s,S16b,C16b);
    k_softmax_w<<<gN,TB,0,s2>>>(C16b,out+(long)32*Nn,w2);
    cudaEventRecord(eW2, s2);
    k_spmm128g<<<gWB,TB,0,s2>>>(bidx,rp2s,col2s,val2s,XG2,Z+(long)2*Bb*128);
    cudaEventRecord(eZ2, s2);

    // ---- stream 0: fused classifier + MI + contrast ----
    cudaStreamWaitEvent(0, eW1, 0);
    cudaStreamWaitEvent(0, eW2, 0);
    k_bal<<<gN,TB>>>(w1,w2,b1,b2);
    k_spmm128fg<<<gWB,TB>>>(bidx,rp1s,col1s,val1s,rp2s,col2s,val2s,b1,b2,XG,Z);
    k_spmm128f<<<gW,TB>>>(rp1s,col1s,val1s,rp2s,col2s,val2s,b1,b2,XCf,Ha);
    k_gemm16<<<g16,b16>>>(Ha,W2v,S16a,Nn);
    k_spmm16f<<<g16,b16>>>(rp1s,col1s,val1s,rp2s,col2s,val2s,b1,b2,S16a,C16a);
    k_softmax_w<<<gN,TB>>>(C16a,out,nullptr);

    cudaStreamWaitEvent(0, eZ1, 0);
    cudaStreamWaitEvent(0, eZ2, 0);
    k_gemm128<<<dim3(1,(3*Bb+127)/128),256>>>(Z,Wp1,bp1,T,3*Bb,128,1);
    k_gemm128<<<dim3(1,(3*Bb+127)/128),256>>>(T,Wp2,bp2,E,3*Bb,128,0);
    k_normrows<<<gW3B,TB>>>(E);
    dim3 cg(32,32,3);
    k_contrast3<<<cg,256>>>(E,RS,CS,DG);
    k_creduce3<<<3,1024>>>(RS,CS,DG,out+(long)48*Nn);
}

// round 8
// speedup vs baseline: 1.7330x; 1.1586x over previous
#include <cuda_runtime.h>
#include <math.h>

#define Nn 30000
#define Ee 480000
#define Bb 4096
#define EPSF 1e-8f

typedef unsigned long long u64;
__device__ __forceinline__ u64 pk2(float x,float y){u64 r;asm("mov.b64 %0,{%1,%2};":"=l"(r):"f"(x),"f"(y));return r;}
__device__ __forceinline__ float2 up2(u64 v){float2 r;asm("mov.b64 {%0,%1},%2;":"=f"(r.x),"=f"(r.y):"l"(v));return r;}
__device__ __forceinline__ void fma2(u64&d,u64 a,u64 b){asm("fma.rn.f32x2 %0,%1,%2,%0;":"+l"(d):"l"(a),"l"(b));}

// ------------- device scratch -------------
__device__ float g_Wp[256*896];
__device__ float g_X64a[Nn*64], g_X64b[Nn*64];
__device__ float g_XC1[Nn*128], g_XC2[Nn*128], g_XCf[Nn*128];
__device__ float g_XG[Nn*128], g_XG1[Nn*128], g_XG2[Nn*128];
__device__ float g_Ha[Nn*128], g_Hb[Nn*128];
__device__ float g_emba[Nn*64], g_embb[Nn*64];
__device__ float g_S16a[Nn*16], g_S16b[Nn*16];
__device__ float g_C16a[Nn*16], g_C16b[Nn*16];
__device__ float g_dra[Nn], g_dca[Nn], g_drb[Nn], g_dcb[Nn];
__device__ float g_w1[Nn], g_w2[Nn], g_b1[Nn], g_b2[Nn];
__device__ int   g_cnt1[Nn], g_cnt1b[Nn], g_cnt2[Nn], g_cnt2b[Nn];
__device__ int   g_cur1d[Nn], g_cur2d[Nn], g_cur1s[Nn], g_cur2s[Nn];
__device__ int   g_rp1d[Nn+1], g_rp2d[Nn+1], g_rp1s[Nn+1], g_rp2s[Nn+1];
__device__ int   g_col1d[Ee];   __device__ float g_val1d[Ee];
__device__ int   g_col2d[Ee];   __device__ float g_val2d[Ee];
__device__ int   g_col1s[2*Ee]; __device__ float g_val1s[2*Ee];
__device__ int   g_col2s[2*Ee]; __device__ float g_val2s[2*Ee];
__device__ float g_Z[3*Bb*128], g_T[3*Bb*128], g_E[3*Bb*128];
__device__ float g_RS[3*Bb], g_CS[3*Bb], g_DG[3*Bb];

// ------------- pack weights -------------
__global__ void k_pack(const float* __restrict__ wg1, const float* __restrict__ wg2,
                       const float* __restrict__ a, const float* __restrict__ b,
                       const float* __restrict__ c, const float* __restrict__ d,
                       const float* __restrict__ e, const float* __restrict__ f,
                       float* __restrict__ Wp){
    int i=blockIdx.x*blockDim.x+threadIdx.x; if(i>=256*896) return;
    int row=i/896, col=i%896;
    float v;
    if(col<64) v=wg1[row*64+col];
    else if(col<128) v=wg2[row*64+col-64];
    else{
        int blk=(col-128)>>7, lc=(col-128)&127;
        const float* s;
        switch(blk){case 0:s=a;break;case 1:s=b;break;case 2:s=c;break;
                    case 3:s=d;break;case 4:s=e;break;default:s=f;break;}
        v=s[row*128+lc];
    }
    Wp[i]=v;
}

// ------------- small utils -------------
__global__ void k_zero4(int* a,int* b,int* c,int* d,int n){
    int i=blockIdx.x*blockDim.x+threadIdx.x; if(i<n){a[i]=0;b[i]=0;c[i]=0;d[i]=0;} }
__global__ void k_zero_f2(float* a, float* b, int n){
    int i=blockIdx.x*blockDim.x+threadIdx.x; if(i<n){a[i]=0.f;b[i]=0.f;} }

__global__ void k_count2(const int* __restrict__ ind1, const int* __restrict__ ind2,
                         int* cd1, int* cs1, int* cd2, int* cs2){
    int e=blockIdx.x*blockDim.x+threadIdx.x; if(e>=Ee) return;
    int r1=ind1[e], c1=ind1[Ee+e];
    atomicAdd(&cd1[r1],1); atomicAdd(&cs1[r1],1); atomicAdd(&cs1[c1],1);
    int r2=ind2[e], c2=ind2[Ee+e];
    atomicAdd(&cd2[r2],1); atomicAdd(&cs2[r2],1); atomicAdd(&cs2[c2],1);
}

// 4 independent scans; register-staged, fully unrolled (CHUNK=30)
__global__ void k_scan4(const int* c0,int* r0,int* u0,const int* c1,int* r1,int* u1,
                        const int* c2,int* r2,int* u2,const int* c3,int* r3,int* u3){
    const int* cnt; int* rp; int* cu;
    switch(blockIdx.x){
        case 0: cnt=c0; rp=r0; cu=u0; break;
        case 1: cnt=c1; rp=r1; cu=u1; break;
        case 2: cnt=c2; rp=r2; cu=u2; break;
        default:cnt=c3; rp=r3; cu=u3; break;
    }
    const int CH=30;
    int tid=threadIdx.x;
    int s=tid*CH;
    int vloc[CH];
#pragma unroll
    for(int i=0;i<CH;i++){int idx=s+i; vloc[i]=(idx<Nn)?cnt[idx]:0;}
    int sum=0;
#pragma unroll
    for(int i=0;i<CH;i++) sum+=vloc[i];
    __shared__ int wsum[32];
    int lane=tid&31, wid=tid>>5;
    int v=sum;
#pragma unroll
    for(int o=1;o<32;o<<=1){int t=__shfl_up_sync(0xffffffffu,v,o); if(lane>=o) v+=t;}
    if(lane==31) wsum[wid]=v;
    __syncthreads();
    if(wid==0){
        int w=wsum[lane];
#pragma unroll
        for(int o=1;o<32;o<<=1){int t=__shfl_up_sync(0xffffffffu,w,o); if(lane>=o) w+=t;}
        wsum[lane]=w;
    }
    __syncthreads();
    int excl=v-sum+(wid?wsum[wid-1]:0);
    int run=excl;
#pragma unroll
    for(int i=0;i<CH;i++){
        int idx=s+i;
        if(idx<Nn){ rp[idx]=run; cu[idx]=run; run+=vloc[i]; }
    }
    if(tid==1023) rp[Nn]=run;
}

__global__ void k_scatter_dir(const int* __restrict__ ind, const float* __restrict__ vals,
                              int* cur, int* __restrict__ col, float* __restrict__ val){
    int e=blockIdx.x*blockDim.x+threadIdx.x; if(e>=Ee) return;
    int r=ind[e], c=ind[Ee+e];
    int p=atomicAdd(&cur[r],1);
    col[p]=c; val[p]=vals[e];
}

__global__ void k_scatter_sym(const int* __restrict__ rpd, const int* __restrict__ cold,
                              const float* __restrict__ vald, int* cur,
                              int* __restrict__ cols, float* __restrict__ vals){
    int r=blockIdx.x*blockDim.x+threadIdx.x; if(r>=Nn) return;
    for(int i=rpd[r];i<rpd[r+1];i++){
        int c=cold[i]; float v=vald[i];
        int p=atomicAdd(&cur[r],1); cols[p]=c; vals[p]=v;
        int q=atomicAdd(&cur[c],1); cols[q]=r; vals[q]=v;
    }
}

// ------------- inner-product macro (8x8, f32x2) -------------
#define MMA_KK(sak, sWk) do{ \
    float2 a01=*(const float2*)(sak); \
    float2 a23=*(const float2*)((sak)+2); \
    float2 a45=*(const float2*)((sak)+4); \
    float2 a67=*(const float2*)((sak)+6); \
    const ulonglong2* bw=(const ulonglong2*)(sWk); \
    ulonglong2 bA=bw[0], bB=bw[1]; \
    u64 s0=pk2(a01.x,a01.x), s1=pk2(a01.y,a01.y); \
    u64 s2=pk2(a23.x,a23.x), s3=pk2(a23.y,a23.y); \
    u64 s4=pk2(a45.x,a45.x), s5=pk2(a45.y,a45.y); \
    u64 s6=pk2(a67.x,a67.x), s7=pk2(a67.y,a67.y); \
    fma2(acc[0][0],s0,bA.x); fma2(acc[0][1],s0,bA.y); fma2(acc[0][2],s0,bB.x); fma2(acc[0][3],s0,bB.y); \
    fma2(acc[1][0],s1,bA.x); fma2(acc[1][1],s1,bA.y); fma2(acc[1][2],s1,bB.x); fma2(acc[1][3],s1,bB.y); \
    fma2(acc[2][0],s2,bA.x); fma2(acc[2][1],s2,bA.y); fma2(acc[2][2],s2,bB.x); fma2(acc[2][3],s2,bB.y); \
    fma2(acc[3][0],s3,bA.x); fma2(acc[3][1],s3,bA.y); fma2(acc[3][2],s3,bB.x); fma2(acc[3][3],s3,bB.y); \
    fma2(acc[4][0],s4,bA.x); fma2(acc[4][1],s4,bA.y); fma2(acc[4][2],s4,bB.x); fma2(acc[4][3],s4,bB.y); \
    fma2(acc[5][0],s5,bA.x); fma2(acc[5][1],s5,bA.y); fma2(acc[5][2],s5,bB.x); fma2(acc[5][3],s5,bB.y); \
    fma2(acc[6][0],s6,bA.x); fma2(acc[6][1],s6,bA.y); fma2(acc[6][2],s6,bB.x); fma2(acc[6][3],s6,bB.y); \
    fma2(acc[7][0],s7,bA.x); fma2(acc[7][1],s7,bA.y); fma2(acc[7][2],s7,bB.x); fma2(acc[7][3],s7,bB.y); \
}while(0)

// ------------- packed GEMM slice: feat[30000x256] @ Wp[:,128*bx:128*(bx+1)] -------------
__global__ __launch_bounds__(256) void k_gemmP(
        const float* __restrict__ A, const float* __restrict__ Wp, int bxoff,
        float* __restrict__ e1, float* __restrict__ e2,
        float* __restrict__ x0, float* __restrict__ x1, float* __restrict__ x2,
        float* __restrict__ x3, float* __restrict__ x4, float* __restrict__ x5){
    __shared__ __align__(16) float sA[32*130];
    __shared__ __align__(16) float sW[32*128];
    int tid=threadIdx.x, tx=tid&15, ty=tid>>4;
    int bx=blockIdx.x+bxoff;
    int br=blockIdx.y*128;
    u64 acc[8][4];
#pragma unroll
    for(int i=0;i<8;i++){acc[i][0]=0;acc[i][1]=0;acc[i][2]=0;acc[i][3]=0;}
    int ra=tid>>3, fa=(tid&7)<<2;
    int cw=(tid&31)<<2, kw=tid>>5;

    for(int k0=0;k0<256;k0+=32){
#pragma unroll
        for(int h=0;h<4;h++){
            int r=ra+h*32, gr=br+r;
            float4 v=make_float4(0.f,0.f,0.f,0.f);
            if(gr<Nn) v=*(const float4*)(A+(long)gr*256+k0+fa);
            sA[(fa+0)*130+r]=v.x; sA[(fa+1)*130+r]=v.y;
            sA[(fa+2)*130+r]=v.z; sA[(fa+3)*130+r]=v.w;
        }
#pragma unroll
        for(int h=0;h<4;h++){
            int kk=kw+h*8;
            float4 v=*(const float4*)(Wp+(long)(k0+kk)*896+bx*128+cw);
            *(float4*)&sW[kk*128+cw]=v;
        }
        __syncthreads();
#pragma unroll
        for(int kk=0;kk<32;kk++){
            MMA_KK(&sA[kk*130+ty*8], &sW[kk*128+tx*8]);
        }
        __syncthreads();
    }
    float* dst; int w; int c0;
    if(bx==0){
        if(tx<8){ dst=e1; w=64; c0=tx*8; } else { dst=e2; w=64; c0=(tx-8)*8; }
    } else {
        switch(bx-1){case 0:dst=x0;break;case 1:dst=x1;break;case 2:dst=x2;break;
                     case 3:dst=x3;break;case 4:dst=x4;break;default:dst=x5;break;}
        w=128; c0=tx*8;
    }
#pragma unroll
    for(int i=0;i<8;i++){
        int gr=br+ty*8+i; if(gr>=Nn) continue;
        float vv[8];
#pragma unroll
        for(int p=0;p<4;p++){float2 t=up2(acc[i][p]); vv[2*p]=t.x; vv[2*p+1]=t.y;}
        float* cp=dst+(long)gr*w+c0;
        *(float4*)cp=make_float4(vv[0],vv[1],vv[2],vv[3]);
        *(float4*)(cp+4)=make_float4(vv[4],vv[5],vv[6],vv[7]);
    }
}

// ------------- generic GEMM: C[n,128]=A[n,K]@W[K,128] (+bias, act) -------------
__global__ __launch_bounds__(256) void k_gemm128(
        const float* __restrict__ A, const float* __restrict__ W,
        const float* __restrict__ bias, float* __restrict__ C,
        int n, int K, int act){
    __shared__ __align__(16) float sA[32*130];
    __shared__ __align__(16) float sW[32*128];
    int tid=threadIdx.x, tx=tid&15, ty=tid>>4;
    int br=blockIdx.y*128;
    u64 acc[8][4];
#pragma unroll
    for(int i=0;i<8;i++){acc[i][0]=0;acc[i][1]=0;acc[i][2]=0;acc[i][3]=0;}
    int ra=tid>>3, fa=(tid&7)<<2;
    int cw=(tid&31)<<2, kw=tid>>5;

    for(int k0=0;k0<K;k0+=32){
#pragma unroll
        for(int h=0;h<4;h++){
            int r=ra+h*32, gr=br+r;
            float4 v=make_float4(0.f,0.f,0.f,0.f);
            if(gr<n) v=*(const float4*)(A+(long)gr*K+k0+fa);
            sA[(fa+0)*130+r]=v.x; sA[(fa+1)*130+r]=v.y;
            sA[(fa+2)*130+r]=v.z; sA[(fa+3)*130+r]=v.w;
        }
#pragma unroll
        for(int h=0;h<4;h++){
            int kk=kw+h*8;
            float4 v=*(const float4*)(W+(long)(k0+kk)*128+cw);
            *(float4*)&sW[kk*128+cw]=v;
        }
        __syncthreads();
#pragma unroll
        for(int kk=0;kk<32;kk++){
            MMA_KK(&sA[kk*130+ty*8], &sW[kk*128+tx*8]);
        }
        __syncthreads();
    }
    float bb[8];
#pragma unroll
    for(int q=0;q<8;q++) bb[q]=bias?bias[tx*8+q]:0.f;
#pragma unroll
    for(int i=0;i<8;i++){
        int gr=br+ty*8+i; if(gr>=n) continue;
        float vv[8];
#pragma unroll
        for(int p=0;p<4;p++){float2 t=up2(acc[i][p]); vv[2*p]=t.x; vv[2*p+1]=t.y;}
#pragma unroll
        for(int q=0;q<8;q++){
            float v=vv[q]+bb[q];
            if(act==1) v=(v>0.f)?v:expm1f(v);
            vv[q]=v;
        }
        float* cp=C+(long)gr*128+tx*8;
        *(float4*)cp=make_float4(vv[0],vv[1],vv[2],vv[3]);
        *(float4*)(cp+4)=make_float4(vv[4],vv[5],vv[6],vv[7]);
    }
}

// ------------- GEMM M=16 (W2 in smem) -------------
__global__ void k_gemm16(const float* __restrict__ H, const float* __restrict__ W2,
                         float* __restrict__ C, int n){
    __shared__ float sW[128*16];
    int tid=threadIdx.y*16+threadIdx.x;
#pragma unroll
    for(int q=0;q<2;q++) ((float4*)sW)[tid*2+q]=((const float4*)W2)[tid*2+q];
    __syncthreads();
    int r=blockIdx.x*16+threadIdx.y, j=threadIdx.x;
    if(r>=n) return;
    const float4* H4=(const float4*)(H+(long)r*128);
    float acc=0.f;
#pragma unroll
    for(int k4=0;k4<32;k4++){
        float4 h=H4[k4];
        acc+=h.x*sW[(k4*4+0)*16+j];
        acc+=h.y*sW[(k4*4+1)*16+j];
        acc+=h.z*sW[(k4*4+2)*16+j];
        acc+=h.w*sW[(k4*4+3)*16+j];
    }
    C[(long)r*16+j]=acc;
}

// ------------- SpMM (warp per row, 2-way unrolled) -------------
__device__ __forceinline__ float4 spmm_row128(const int* __restrict__ rp,
        const int* __restrict__ col, const float* __restrict__ val,
        const float4* __restrict__ X4, int w, int lane){
    int s=rp[w], e=rp[w+1];
    float4 A=make_float4(0.f,0.f,0.f,0.f), B=A;
    int i=s;
    for(; i+1<e; i+=2){
        int c0=col[i], c1=col[i+1];
        float v0=val[i], v1=val[i+1];
        float4 x0=X4[(long)c0*32+lane];
        float4 x1=X4[(long)c1*32+lane];
        A.x+=v0*x0.x; A.y+=v0*x0.y; A.z+=v0*x0.z; A.w+=v0*x0.w;
        B.x+=v1*x1.x; B.y+=v1*x1.y; B.z+=v1*x1.z; B.w+=v1*x1.w;
    }
    if(i<e){
        int c=col[i]; float v=val[i];
        float4 x=X4[(long)c*32+lane];
        A.x+=v*x.x; A.y+=v*x.y; A.z+=v*x.z; A.w+=v*x.w;
    }
    A.x+=B.x; A.y+=B.y; A.z+=B.z; A.w+=B.w;
    return A;
}

__global__ void k_spmm128(const int* __restrict__ rp, const int* __restrict__ col,
                          const float* __restrict__ val, const float* __restrict__ X,
                          float* __restrict__ Y){
    int w=(blockIdx.x*blockDim.x+threadIdx.x)>>5; if(w>=Nn) return;
    int lane=threadIdx.x&31;
    float4 a=spmm_row128(rp,col,val,(const float4*)X,w,lane);
    a.x=fmaxf(a.x,0.f); a.y=fmaxf(a.y,0.f); a.z=fmaxf(a.z,0.f); a.w=fmaxf(a.w,0.f);
    ((float4*)Y)[(long)w*32+lane]=a;
}

__global__ void k_spmm128f(const int* __restrict__ rp1, const int* __restrict__ col1,
                           const float* __restrict__ val1,
                           const int* __restrict__ rp2, const int* __restrict__ col2,
                           const float* __restrict__ val2,
                           const float* __restrict__ b1, const float* __restrict__ b2,
                           const float* __restrict__ X, float* __restrict__ Y){
    int w=(blockIdx.x*blockDim.x+threadIdx.x)>>5; if(w>=Nn) return;
    int lane=threadIdx.x&31;
    float4 a1=spmm_row128(rp1,col1,val1,(const float4*)X,w,lane);
    float4 a2=spmm_row128(rp2,col2,val2,(const float4*)X,w,lane);
    float f1=b1[w], f2=b2[w];
    float4 r;
    r.x=fmaxf(f1*a1.x+f2*a2.x,0.f); r.y=fmaxf(f1*a1.y+f2*a2.y,0.f);
    r.z=fmaxf(f1*a1.z+f2*a2.z,0.f); r.w=fmaxf(f1*a1.w+f2*a2.w,0.f);
    ((float4*)Y)[(long)w*32+lane]=r;
}

__global__ void k_spmm128g(const int* __restrict__ bidx,
                           const int* __restrict__ rp, const int* __restrict__ col,
                           const float* __restrict__ val, const float* __restrict__ X,
                           float* __restrict__ Z){
    int w=(blockIdx.x*blockDim.x+threadIdx.x)>>5; if(w>=Bb) return;
    int lane=threadIdx.x&31;
    int row=bidx[w];
    float4 a=spmm_row128(rp,col,val,(const float4*)X,row,lane);
    a.x=fmaxf(a.x,0.f); a.y=fmaxf(a.y,0.f); a.z=fmaxf(a.z,0.f); a.w=fmaxf(a.w,0.f);
    ((float4*)Z)[(long)w*32+lane]=a;
}

__global__ void k_spmm128fg(const int* __restrict__ bidx,
                            const int* __restrict__ rp1, const int* __restrict__ col1,
                            const float* __restrict__ val1,
                            const int* __restrict__ rp2, const int* __restrict__ col2,
                            const float* __restrict__ val2,
                            const float* __restrict__ b1, const float* __restrict__ b2,
                            const float* __restrict__ X, float* __restrict__ Z){
    int w=(blockIdx.x*blockDim.x+threadIdx.x)>>5; if(w>=Bb) return;
    int lane=threadIdx.x&31;
    int row=bidx[w];
    float4 a1=spmm_row128(rp1,col1,val1,(const float4*)X,row,lane);
    float4 a2=spmm_row128(rp2,col2,val2,(const float4*)X,row,lane);
    float f1=b1[row], f2=b2[row];
    float4 r;
    r.x=fmaxf(f1*a1.x+f2*a2.x,0.f); r.y=fmaxf(f1*a1.y+f2*a2.y,0.f);
    r.z=fmaxf(f1*a1.z+f2*a2.z,0.f); r.w=fmaxf(f1*a1.w+f2*a2.w,0.f);
    ((float4*)Z)[(long)w*32+lane]=r;
}

__global__ void k_spmm64(const int* __restrict__ rp, const int* __restrict__ col,
                         const float* __restrict__ val, const float* __restrict__ X,
                         float* __restrict__ Y){
    int w=(blockIdx.x*blockDim.x+threadIdx.x)>>5; if(w>=Nn) return;
    int lane=threadIdx.x&31;
    const float2* X2=(const float2*)X;
    int s=rp[w], e=rp[w+1];
    float2 A=make_float2(0.f,0.f), B=A;
    int i=s;
    for(; i+1<e; i+=2){
        int c0=col[i], c1=col[i+1];
        float v0=val[i], v1=val[i+1];
        float2 x0=X2[(long)c0*32+lane];
        float2 x1=X2[(long)c1*32+lane];
        A.x+=v0*x0.x; A.y+=v0*x0.y;
        B.x+=v1*x1.x; B.y+=v1*x1.y;
    }
    if(i<e){
        int c=col[i]; float v=val[i];
        float2 x=X2[(long)c*32+lane];
        A.x+=v*x.x; A.y+=v*x.y;
    }
    A.x=fmaxf(A.x+B.x,0.f); A.y=fmaxf(A.y+B.y,0.f);
    ((float2*)Y)[(long)w*32+lane]=A;
}

__global__ void k_spmm16(const int* __restrict__ rp, const int* __restrict__ col,
                         const float* __restrict__ val, const float* __restrict__ X,
                         float* __restrict__ Y){
    int row=blockIdx.x*16+threadIdx.y; int j=threadIdx.x;
    if(row>=Nn) return;
    float acc=0.f;
    for(int i=rp[row];i<rp[row+1];i++) acc+=val[i]*X[(long)col[i]*16+j];
    Y[(long)row*16+j]=acc;
}

__global__ void k_spmm16f(const int* __restrict__ rp1, const int* __restrict__ col1,
                          const float* __restrict__ val1,
                          const int* __restrict__ rp2, const int* __restrict__ col2,
                          const float* __restrict__ val2,
                          const float* __restrict__ b1, const float* __restrict__ b2,
                          const float* __restrict__ X, float* __restrict__ Y){
    int row=blockIdx.x*16+threadIdx.y; int j=threadIdx.x;
    if(row>=Nn) return;
    float a1=0.f, a2=0.f;
    for(int i=rp1[row];i<rp1[row+1];i++) a1+=val1[i]*X[(long)col1[i]*16+j];
    for(int i=rp2[row];i<rp2[row+1];i++) a2+=val2[i]*X[(long)col2[i]*16+j];
    Y[(long)row*16+j]=b1[row]*a1+b2[row]*a2;
}

// ------------- gen_view helpers -------------
__global__ void k_nodedot(const float* __restrict__ emb, const float* __restrict__ Wm,
                          float* __restrict__ dr, float* __restrict__ dc){
    int node=(blockIdx.x*blockDim.x+threadIdx.x)>>5; if(node>=Nn) return;
    int lane=threadIdx.x&31;
    float2 e=((const float2*)(emb+(long)node*64))[lane];
    float2 wr=((const float2*)Wm)[lane];
    float2 wc=((const float2*)Wm)[lane+32];
    float a=e.x*wr.x+e.y*wr.y;
    float b=e.x*wc.x+e.y*wc.y;
#pragma unroll
    for(int o=16;o;o>>=1){
        a+=__shfl_xor_sync(0xffffffffu,a,o);
        b+=__shfl_xor_sync(0xffffffffu,b,o);
    }
    if(lane==0){dr[node]=a; dc[node]=b;}
}

__global__ void k_gensoftmax(const int* __restrict__ rp, const int* __restrict__ col,
                             float* __restrict__ val, const float* __restrict__ dr,
                             const float* __restrict__ dc, const float* __restrict__ bm,
                             float com){
    int row=(blockIdx.x*blockDim.x+threadIdx.x)>>5; if(row>=Nn) return;
    int lane=threadIdx.x&31;
    int s=rp[row], e=rp[row+1];
    if(s==e) return;
    float base=dr[row]+bm[0];
    float m=-3.4e38f;
    for(int i=s+lane;i<e;i+=32) m=fmaxf(m, base+dc[col[i]]);
#pragma unroll
    for(int o=16;o;o>>=1) m=fmaxf(m,__shfl_xor_sync(0xffffffffu,m,o));
    float ss=0.f;
    for(int i=s+lane;i<e;i+=32) ss+=__expf(base+dc[col[i]]-m);
#pragma unroll
    for(int o=16;o;o>>=1) ss+=__shfl_xor_sync(0xffffffffu,ss,o);
    float inv=com/ss;
    for(int i=s+lane;i<e;i+=32) val[i]+=__expf(base+dc[col[i]]-m)*inv;
}

// ------------- 16-class softmax + logits + top2 weight -------------
__global__ void k_softmax_w(const float* __restrict__ C, float* __restrict__ lg,
                            float* __restrict__ w){
    int node=blockIdx.x*blockDim.x+threadIdx.x; if(node>=Nn) return;
    float x[16];
    const float4* p=(const float4*)(C+(long)node*16);
#pragma unroll
    for(int q=0;q<4;q++){float4 t=p[q]; x[4*q]=t.x; x[4*q+1]=t.y; x[4*q+2]=t.z; x[4*q+3]=t.w;}
    float m=x[0];
#pragma unroll
    for(int j=1;j<16;j++) m=fmaxf(m,x[j]);
    float s=0.f;
#pragma unroll
    for(int j=0;j<16;j++){x[j]=__expf(x[j]-m); s+=x[j];}
    float inv=1.f/s;
    float fir=0.f, sec=0.f;
#pragma unroll
    for(int j=0;j<16;j++){
        float pr=x[j]*inv;
        lg[(long)node*16+j]=logf(pr+EPSF);
        if(pr>fir){sec=fir; fir=pr;} else if(pr>sec) sec=pr;
    }
    if(w) w[node]=sqrtf((fir+EPSF)*(fir-sec+EPSF));
}

__global__ void k_bal(const float* __restrict__ w1, const float* __restrict__ w2,
                      float* __restrict__ b1, float* __restrict__ b2){
    int i=blockIdx.x*blockDim.x+threadIdx.x; if(i>=Nn) return;
    float a=w1[i], b=w2[i], inv=1.f/(a+b);
    b1[i]=a*inv; b2[i]=b*inv;
}

__global__ void k_normrows(float* __restrict__ E, int nrows){
    int row=(blockIdx.x*blockDim.x+threadIdx.x)>>5; if(row>=nrows) return;
    int lane=threadIdx.x&31;
    float4* p=(float4*)(E+(long)row*128);
    float4 v=p[lane];
    float s=v.x*v.x+v.y*v.y+v.z*v.z+v.w*v.w;
#pragma unroll
    for(int o=16;o;o>>=1) s+=__shfl_xor_sync(0xffffffffu,s,o);
    float inv=rsqrtf(s);
    v.x*=inv; v.y*=inv; v.z*=inv; v.w*=inv;
    p[lane]=v;
}

// ------------- contrast pair: exp(2*z1.z2) row/col sums + diag -------------
__global__ __launch_bounds__(256) void k_contrast(
        const float* __restrict__ z1, const float* __restrict__ z2,
        float* __restrict__ rs, float* __restrict__ cs, float* __restrict__ dg){
    __shared__ __align__(16) float sA[32*130];
    __shared__ __align__(16) float sW[32*128];
    __shared__ float sRS[128], sCS[128];
    int tid=threadIdx.x, tx=tid&15, ty=tid>>4;
    int br=blockIdx.y*128, bc=blockIdx.x*128;
    u64 acc[8][4];
#pragma unroll
    for(int i=0;i<8;i++){acc[i][0]=0;acc[i][1]=0;acc[i][2]=0;acc[i][3]=0;}
    int ra=tid>>3, fa=(tid&7)<<2;

    for(int k0=0;k0<128;k0+=32){
#pragma unroll
        for(int h=0;h<4;h++){
            int r=ra+h*32;
            float4 v=*(const float4*)(z1+(long)(br+r)*128+k0+fa);
            sA[(fa+0)*130+r]=v.x; sA[(fa+1)*130+r]=v.y;
            sA[(fa+2)*130+r]=v.z; sA[(fa+3)*130+r]=v.w;
        }
#pragma unroll
        for(int h=0;h<4;h++){
            int c=ra+h*32;
            float4 v=*(const float4*)(z2+(long)(bc+c)*128+k0+fa);
            sW[(fa+0)*128+c]=v.x; sW[(fa+1)*128+c]=v.y;
            sW[(fa+2)*128+c]=v.z; sW[(fa+3)*128+c]=v.w;
        }
        __syncthreads();
#pragma unroll
        for(int kk=0;kk<32;kk++){
            MMA_KK(&sA[kk*130+ty*8], &sW[kk*128+tx*8]);
        }
        __syncthreads();
    }
    if(tid<128){sRS[tid]=0.f; sCS[tid]=0.f;}
    __syncthreads();
    float rsum[8]={0,0,0,0,0,0,0,0}, csum[8]={0,0,0,0,0,0,0,0};
#pragma unroll
    for(int i=0;i<8;i++){
        float vv[8];
#pragma unroll
        for(int p=0;p<4;p++){float2 t=up2(acc[i][p]); vv[2*p]=t.x; vv[2*p+1]=t.y;}
        int gr=br+ty*8+i;
#pragma unroll
        for(int j=0;j<8;j++){
            float e=__expf(2.0f*vv[j]);
            rsum[i]+=e; csum[j]+=e;
            if(gr==bc+tx*8+j) dg[gr]=e;
        }
    }
#pragma unroll
    for(int i=0;i<8;i++) atomicAdd(&sRS[ty*8+i], rsum[i]);
#pragma unroll
    for(int j=0;j<8;j++) atomicAdd(&sCS[tx*8+j], csum[j]);
    __syncthreads();
    if(tid<128){atomicAdd(&rs[br+tid], sRS[tid]); atomicAdd(&cs[bc+tid], sCS[tid]);}
}

__global__ void k_creduce3(const float* __restrict__ RS, const float* __restrict__ CS,
                           const float* __restrict__ DG, float* out){
    __shared__ float sh[1024];
    int pair=blockIdx.x;
    const float* rs=RS+(long)pair*Bb;
    const float* cs=CS+(long)pair*Bb;
    const float* dg=DG+(long)pair*Bb;
    int tid=threadIdx.x;
    float a=0.f;
    for(int i=tid;i<Bb;i+=1024){
        a+=-logf(dg[i]/(rs[i]+EPSF)+EPSF);
        a+=-logf(dg[i]/(cs[i]+EPSF)+EPSF);
    }
    sh[tid]=a; __syncthreads();
    for(int d=512;d;d>>=1){ if(tid<d) sh[tid]+=sh[tid+d]; __syncthreads(); }
    if(tid==0) out[pair]=0.5f*sh[0]/(float)Bb;
}

// ------------- host -------------
#define GSA(var) ([]{ void* _p; cudaGetSymbolAddress(&_p, var); return _p; }())

extern "C" void kernel_launch(void* const* d_in, const int* in_sizes, int n_in,
                              void* d_out, int out_size){
    const float* feat  =(const float*)d_in[0];
    const int*   i1    =(const int*)  d_in[1];
    const float* v1    =(const float*)d_in[2];
    const int*   i2    =(const int*)  d_in[3];
    const float* v2    =(const float*)d_in[4];
    const int*   bidx  =(const int*)  d_in[5];
    const float* Wgen1 =(const float*)d_in[6];
    const float* Wm1   =(const float*)d_in[7];
    const float* bm1   =(const float*)d_in[8];
    const float* Wgen2 =(const float*)d_in[9];
    const float* Wm2   =(const float*)d_in[10];
    const float* bm2   =(const float*)d_in[11];
    const float* W1v1  =(const float*)d_in[12];
    const float* W2v1  =(const float*)d_in[13];
    const float* W1v2  =(const float*)d_in[14];
    const float* W2v2  =(const float*)d_in[15];
    const float* W1v   =(const float*)d_in[16];
    const float* W2v   =(const float*)d_in[17];
    const float* Wg    =(const float*)d_in[18];
    const float* Wg1   =(const float*)d_in[19];
    const float* Wg2   =(const float*)d_in[20];
    const float* Wp1   =(const float*)d_in[21];
    const float* bp1   =(const float*)d_in[22];
    const float* Wp2   =(const float*)d_in[23];
    const float* bp2   =(const float*)d_in[24];
    float* out=(float*)d_out;

    float* Wp=(float*)GSA(g_Wp);
    float* X64a=(float*)GSA(g_X64a); float* X64b=(float*)GSA(g_X64b);
    float* XC1=(float*)GSA(g_XC1); float* XC2=(float*)GSA(g_XC2); float* XCf=(float*)GSA(g_XCf);
    float* XG=(float*)GSA(g_XG); float* XG1=(float*)GSA(g_XG1); float* XG2=(float*)GSA(g_XG2);
    float* Ha=(float*)GSA(g_Ha); float* Hb=(float*)GSA(g_Hb);
    float* emba=(float*)GSA(g_emba); float* embb=(float*)GSA(g_embb);
    float* S16a=(float*)GSA(g_S16a); float* S16b=(float*)GSA(g_S16b);
    float* C16a=(float*)GSA(g_C16a); float* C16b=(float*)GSA(g_C16b);
    float* dra=(float*)GSA(g_dra), *dca=(float*)GSA(g_dca);
    float* drb=(float*)GSA(g_drb), *dcb=(float*)GSA(g_dcb);
    float* w1=(float*)GSA(g_w1), *w2=(float*)GSA(g_w2);
    float* b1=(float*)GSA(g_b1), *b2=(float*)GSA(g_b2);
    int* cnt1=(int*)GSA(g_cnt1), *cnt1b=(int*)GSA(g_cnt1b);
    int* cnt2=(int*)GSA(g_cnt2), *cnt2b=(int*)GSA(g_cnt2b);
    int* cur1d=(int*)GSA(g_cur1d), *cur2d=(int*)GSA(g_cur2d);
    int* cur1s=(int*)GSA(g_cur1s), *cur2s=(int*)GSA(g_cur2s);
    int* rp1d=(int*)GSA(g_rp1d), *rp2d=(int*)GSA(g_rp2d);
    int* rp1s=(int*)GSA(g_rp1s), *rp2s=(int*)GSA(g_rp2s);
    int* col1d=(int*)GSA(g_col1d);   float* val1d=(float*)GSA(g_val1d);
    int* col2d=(int*)GSA(g_col2d);   float* val2d=(float*)GSA(g_val2d);
    int* col1s=(int*)GSA(g_col1s);   float* val1s=(float*)GSA(g_val1s);
    int* col2s=(int*)GSA(g_col2s);   float* val2s=(float*)GSA(g_val2s);
    float* Z=(float*)GSA(g_Z), *T=(float*)GSA(g_T), *E=(float*)GSA(g_E);
    float* RS=(float*)GSA(g_RS), *CS=(float*)GSA(g_CS), *DG=(float*)GSA(g_DG);

    float* E0=E;                    // EV
    float* E1=E+(long)Bb*128;       // view1
    float* E2=E+(long)2*Bb*128;     // view2

    const int TB=256;
    int gN  =(Nn+TB-1)/TB;
    int gE  =(Ee+TB-1)/TB;
    int gW  =(Nn*32+TB-1)/TB;
    int gWB =(Bb*32+TB-1)/TB;
    dim3 b16(16,16); int g16=(Nn+15)/16;
    dim3 cg(32,32);

    static cudaStream_t s1=0, s2=0, s3=0;
    static cudaEvent_t eRoot=0,eScan=0,eA=0,eB=0,eC=0,eW1=0,eW2=0,eZ1=0,eZ2=0,
                       eFg=0,eEV=0,eE12=0,eCa=0,eCb=0;
    if(!s1){
        cudaStreamCreateWithFlags(&s1, cudaStreamNonBlocking);
        cudaStreamCreateWithFlags(&s2, cudaStreamNonBlocking);
        cudaStreamCreateWithFlags(&s3, cudaStreamNonBlocking);
        cudaEventCreateWithFlags(&eRoot,cudaEventDisableTiming);
        cudaEventCreateWithFlags(&eScan,cudaEventDisableTiming);
        cudaEventCreateWithFlags(&eA, cudaEventDisableTiming);
        cudaEventCreateWithFlags(&eB, cudaEventDisableTiming);
        cudaEventCreateWithFlags(&eC, cudaEventDisableTiming);
        cudaEventCreateWithFlags(&eW1,cudaEventDisableTiming);
        cudaEventCreateWithFlags(&eW2,cudaEventDisableTiming);
        cudaEventCreateWithFlags(&eZ1,cudaEventDisableTiming);
        cudaEventCreateWithFlags(&eZ2,cudaEventDisableTiming);
        cudaEventCreateWithFlags(&eFg,cudaEventDisableTiming);
        cudaEventCreateWithFlags(&eEV,cudaEventDisableTiming);
        cudaEventCreateWithFlags(&eE12,cudaEventDisableTiming);
        cudaEventCreateWithFlags(&eCa,cudaEventDisableTiming);
        cudaEventCreateWithFlags(&eCb,cudaEventDisableTiming);
    }

    cudaEventRecord(eRoot, 0);
    cudaStreamWaitEvent(s1, eRoot, 0);
    cudaStreamWaitEvent(s2, eRoot, 0);
    cudaStreamWaitEvent(s3, eRoot, 0);

    int gyP=(Nn+127)/128;
    // ---- stream 0: pack + sliced big GEMM (ordered by consumer need) ----
    k_pack<<<(256*896+TB-1)/TB,TB>>>(Wgen1,Wgen2,W1v1,W1v2,W1v,Wg,Wg1,Wg2,Wp);
    k_zero_f2<<<(3*Bb+TB-1)/TB,TB>>>(RS,CS,3*Bb);
    k_gemmP<<<dim3(1,gyP),256>>>(feat,Wp,0,X64a,X64b,XC1,XC2,XCf,XG,XG1,XG2);
    cudaEventRecord(eA, 0);   // X64a, X64b ready
    k_gemmP<<<dim3(2,gyP),256>>>(feat,Wp,1,X64a,X64b,XC1,XC2,XCf,XG,XG1,XG2);
    cudaEventRecord(eB, 0);   // XC1, XC2 ready
    k_gemmP<<<dim3(2,gyP),256>>>(feat,Wp,5,X64a,X64b,XC1,XC2,XCf,XG,XG1,XG2);
    cudaEventRecord(eC, 0);   // XG1, XG2 ready
    k_gemmP<<<dim3(2,gyP),256>>>(feat,Wp,3,X64a,X64b,XC1,XC2,XCf,XG,XG1,XG2);
    // XCf, XG ready (stream 0 in-order for later stream-0 consumers)

    // ---- s1: CSR build + view1 pipeline ----
    k_zero4<<<gN,TB,0,s1>>>(cnt1,cnt1b,cnt2,cnt2b,Nn);
    k_count2<<<gE,TB,0,s1>>>(i1,i2,cnt1,cnt1b,cnt2,cnt2b);
    k_scan4<<<4,1024,0,s1>>>(cnt1,rp1d,cur1d,cnt1b,rp1s,cur1s,cnt2,rp2d,cur2d,cnt2b,rp2s,cur2s);
    cudaEventRecord(eScan, s1);
    k_scatter_dir<<<gE,TB,0,s1>>>(i1,v1,cur1d,col1d,val1d);
    cudaStreamWaitEvent(s1, eA, 0);
    k_spmm64<<<gW,TB,0,s1>>>(rp1d,col1d,val1d,X64a,emba);
    k_nodedot<<<gW,TB,0,s1>>>(emba,Wm1,dra,dca);
    k_gensoftmax<<<gW,TB,0,s1>>>(rp1d,col1d,val1d,dra,dca,bm1,0.5f);
    k_scatter_sym<<<gN,TB,0,s1>>>(rp1d,col1d,val1d,cur1s,col1s,val1s);
    cudaStreamWaitEvent(s1, eB, 0);
    k_spmm128<<<gW,TB,0,s1>>>(rp1s,col1s,val1s,XC1,Ha);
    k_gemm16<<<g16,b16,0,s1>>>(Ha,W2v1,S16a,Nn);
    k_spmm16<<<g16,b16,0,s1>>>(rp1s,col1s,val1s,S16a,C16a);
    k_softmax_w<<<gN,TB,0,s1>>>(C16a,out+(long)16*Nn,w1);
    cudaEventRecord(eW1, s1);
    cudaStreamWaitEvent(s1, eC, 0);
    k_spmm128g<<<gWB,TB,0,s1>>>(bidx,rp1s,col1s,val1s,XG1,E1 /*temp via Z1 slot*/);
    cudaEventRecord(eZ1, s1);

    // ---- s2: view2 pipeline ----
    cudaStreamWaitEvent(s2, eScan, 0);
    k_scatter_dir<<<gE,TB,0,s2>>>(i2,v2,cur2d,col2d,val2d);
    cudaStreamWaitEvent(s2, eA, 0);
    k_spmm64<<<gW,TB,0,s2>>>(rp2d,col2d,val2d,X64b,embb);
    k_nodedot<<<gW,TB,0,s2>>>(embb,Wm2,drb,dcb);
    k_gensoftmax<<<gW,TB,0,s2>>>(rp2d,col2d,val2d,drb,dcb,bm2,0.5f);
    k_scatter_sym<<<gN,TB,0,s2>>>(rp2d,col2d,val2d,cur2s,col2s,val2s);
    cudaStreamWaitEvent(s2, eB, 0);
    k_spmm128<<<gW,TB,0,s2>>>(rp2s,col2s,val2s,XC2,Hb);
    k_gemm16<<<g16,b16,0,s2>>>(Hb,W2v2,S16b,Nn);
    k_spmm16<<<g16,b16,0,s2>>>(rp2s,col2s,val2s,S16b,C16b);
    k_softmax_w<<<gN,TB,0,s2>>>(C16b,out+(long)32*Nn,w2);
    cudaEventRecord(eW2, s2);
    cudaStreamWaitEvent(s2, eC, 0);
    k_spmm128g<<<gWB,TB,0,s2>>>(bidx,rp2s,col2s,val2s,XG2,E2 /*temp via Z2 slot*/);
    cudaEventRecord(eZ2, s2);

    // NOTE: the spmm128g outputs above were written into Z slices via E1/E2
    // aliases — fix: they must go to Z. Use Z slices:
    // (we actually wrote to E1/E2 pointers — correct them by projecting from there)
    // To keep dataflow simple, treat Z1=Z+Bb*128 and Z2=Z+2Bb*128 as the gather
    // outputs: re-issue is not possible, so we use E1/E2 as gather buffers and
    // project E->T->Z? No: instead, project from gather buffers (E1,E2) into
    // T then overwrite E1,E2. This is safe: gemm128 reads A fully before C is
    // written only when A!=C — here A=E1, C=T (disjoint), then A=T, C=E1. OK.

    // ---- s3: E1/E2 projection + contrast(E1,E2) ----
    cudaStreamWaitEvent(s3, eZ1, 0);
    cudaStreamWaitEvent(s3, eZ2, 0);
    k_gemm128<<<dim3(1,(2*Bb+127)/128),256,0,s3>>>(E1,Wp1,bp1,T+(long)Bb*128,2*Bb,128,1);
    k_gemm128<<<dim3(1,(2*Bb+127)/128),256,0,s3>>>(T+(long)Bb*128,Wp2,bp2,E1,2*Bb,128,0);
    k_normrows<<<(2*Bb*32+TB-1)/TB,TB,0,s3>>>(E1,2*Bb);
    cudaEventRecord(eE12, s3);
    k_contrast<<<cg,256,0,s3>>>(E1,E2,RS+2*Bb,CS+2*Bb,DG+2*Bb);   // pair v1v2

    // ---- stream 0: bal + EV gather/proj fork, fused classifier chain ----
    cudaStreamWaitEvent(0, eW1, 0);
    cudaStreamWaitEvent(0, eW2, 0);
    k_bal<<<gN,TB>>>(w1,w2,b1,b2);
    k_spmm128fg<<<gWB,TB>>>(bidx,rp1s,col1s,val1s,rp2s,col2s,val2s,b1,b2,XG,Z);
    cudaEventRecord(eFg, 0);
    // fused classifier (L2-bound; overlaps FMA-bound contrasts)
    k_spmm128f<<<gW,TB>>>(rp1s,col1s,val1s,rp2s,col2s,val2s,b1,b2,XCf,Ha);
    k_gemm16<<<g16,b16>>>(Ha,W2v,S16a,Nn);
    k_spmm16f<<<g16,b16>>>(rp1s,col1s,val1s,rp2s,col2s,val2s,b1,b2,S16a,C16a);
    k_softmax_w<<<gN,TB>>>(C16a,out,nullptr);

    // ---- s1: EV projection + contrast(EV,E1) ----
    cudaStreamWaitEvent(s1, eFg, 0);
    k_gemm128<<<dim3(1,(Bb+127)/128),256,0,s1>>>(Z,Wp1,bp1,T,Bb,128,1);
    k_gemm128<<<dim3(1,(Bb+127)/128),256,0,s1>>>(T,Wp2,bp2,E0,Bb,128,0);
    k_normrows<<<(Bb*32+TB-1)/TB,TB,0,s1>>>(E0,Bb);
    cudaEventRecord(eEV, s1);
    cudaStreamWaitEvent(s1, eE12, 0);
    k_contrast<<<cg,256,0,s1>>>(E0,E1,RS,CS,DG);                   // pair vv1
    cudaEventRecord(eCa, s1);

    // ---- s3: contrast(EV,E2) after its own pair ----
    cudaStreamWaitEvent(s3, eEV, 0);
    k_contrast<<<cg,256,0,s3>>>(E0,E2,RS+Bb,CS+Bb,DG+Bb);          // pair vv2
    cudaEventRecord(eCb, s3);

    // ---- stream 0: final reduce ----
    cudaStreamWaitEvent(0, eCa, 0);
    cudaStreamWaitEvent(0, eCb, 0);
    k_creduce3<<<3,1024>>>(RS,CS,DG,out+(long)48*Nn);
}